// round 1
// baseline (speedup 1.0000x reference)
#include <cuda_runtime.h>
#include <math.h>

#define Nn 65536
#define Ee 1048576
#define Bb 64
#define Hh 128

// ------------------- scratch (static device globals; no allocation) -------------------
__device__ float g_csum[Bb * 4];          // per-graph pos sums + count
__device__ float g_center[Bb * 3];
__device__ float g_posrel[Nn * 3];
__device__ float g_x0[Nn * Hh];
__device__ float g_x1[Nn * Hh];
__device__ float g_xa[Nn * Hh];           // x @ W1a + b1  (gathered at col)
__device__ float g_xb[Nn * Hh];           // x @ W1b       (gathered at row)
__device__ float g_msum[Nn * Hh];         // scatter-add of m_ij at row
__device__ float g_dist[Ee];
__device__ int   g_deg[Nn];
__device__ float g_invdeg[Nn];
__device__ float g_gsum[Bb * Hh];
__device__ float g_ligcnt[Bb];

// ------------------- small kernels -------------------
__global__ void k_center_sum(const float* __restrict__ pos, const int* __restrict__ batch) {
    __shared__ float sb[Bb * 4];
    for (int i = threadIdx.x; i < Bb * 4; i += blockDim.x) sb[i] = 0.f;
    __syncthreads();
    for (int n = blockIdx.x * blockDim.x + threadIdx.x; n < Nn; n += gridDim.x * blockDim.x) {
        int b = batch[n];
        atomicAdd(&sb[b * 4 + 0], pos[n * 3 + 0]);
        atomicAdd(&sb[b * 4 + 1], pos[n * 3 + 1]);
        atomicAdd(&sb[b * 4 + 2], pos[n * 3 + 2]);
        atomicAdd(&sb[b * 4 + 3], 1.f);
    }
    __syncthreads();
    for (int i = threadIdx.x; i < Bb * 4; i += blockDim.x)
        if (sb[i] != 0.f) atomicAdd(&g_csum[i], sb[i]);
}

__global__ void k_center_fin() {
    int b = threadIdx.x;
    if (b < Bb) {
        float c = fmaxf(g_csum[b * 4 + 3], 1.f);
        g_center[b * 3 + 0] = g_csum[b * 4 + 0] / c;
        g_center[b * 3 + 1] = g_csum[b * 4 + 1] / c;
        g_center[b * 3 + 2] = g_csum[b * 4 + 2] / c;
    }
}

__global__ void k_dist(const int* __restrict__ eidx) {
    int e = blockIdx.x * blockDim.x + threadIdx.x;
    if (e >= Ee) return;
    int r = eidx[e], c = eidx[Ee + e];
    float dx = g_posrel[c * 3 + 0] - g_posrel[r * 3 + 0];
    float dy = g_posrel[c * 3 + 1] - g_posrel[r * 3 + 1];
    float dz = g_posrel[c * 3 + 2] - g_posrel[r * 3 + 2];
    g_dist[e] = sqrtf(dx * dx + dy * dy + dz * dz);
}

__global__ void k_deg(const int* __restrict__ row) {
    int e = blockIdx.x * blockDim.x + threadIdx.x;
    if (e < Ee) atomicAdd(&g_deg[row[e]], 1);
}

__global__ void k_invdeg() {
    int n = blockIdx.x * blockDim.x + threadIdx.x;
    if (n < Nn) g_invdeg[n] = 1.f / fmaxf((float)g_deg[n], 1.f);
}

// ------------------- input embedding + lin_in : x0 = [emb[z], pos_rel] @ W + b ----------
__global__ void __launch_bounds__(128)
k_input(const float* __restrict__ pos, const int* __restrict__ z,
        const int* __restrict__ batch, const float* __restrict__ emb,
        const float* __restrict__ W, const float* __restrict__ bias) {
    __shared__ __align__(16) float fs[8 * 128];
    __shared__ float prs[8][3];
    int n0 = blockIdx.x * 8;
    int tid = threadIdx.x;
    if (tid < 8) {
        int n = n0 + tid;
        int b = batch[n];
        #pragma unroll
        for (int d = 0; d < 3; d++) {
            float v = pos[n * 3 + d] - g_center[b * 3 + d];
            prs[tid][d] = v;
            g_posrel[n * 3 + d] = v;
        }
    }
    #pragma unroll
    for (int e = 0; e < 8; e++)
        fs[e * 128 + tid] = emb[z[n0 + e] * 128 + tid];
    __syncthreads();

    int j = tid;
    const float* Wj = W + j;
    const float4* fs4 = (const float4*)fs;
    float acc[8];
    #pragma unroll
    for (int e = 0; e < 8; e++) acc[e] = 0.f;

    for (int kk = 0; kk < 32; kk++) {
        float w0 = Wj[(kk * 4 + 0) * 128];
        float w1 = Wj[(kk * 4 + 1) * 128];
        float w2 = Wj[(kk * 4 + 2) * 128];
        float w3 = Wj[(kk * 4 + 3) * 128];
        #pragma unroll
        for (int e = 0; e < 8; e++) {
            float4 xv = fs4[e * 32 + kk];
            acc[e] += xv.x * w0 + xv.y * w1 + xv.z * w2 + xv.w * w3;
        }
    }
    #pragma unroll
    for (int d = 0; d < 3; d++) {
        float w = Wj[(128 + d) * 128];
        #pragma unroll
        for (int e = 0; e < 8; e++) acc[e] += prs[e][d] * w;
    }
    float bj = bias[j];
    #pragma unroll
    for (int e = 0; e < 8; e++) g_x0[(n0 + e) * 128 + j] = acc[e] + bj;
}

// ------------------- per-layer node pre-GEMM: xa = x@W1a + b1, xb = x@W1b ---------------
__global__ void __launch_bounds__(128)
k_xab(const float* __restrict__ x, const float* __restrict__ W1, const float* __restrict__ b1) {
    __shared__ __align__(16) float xs[8 * 128];
    int n0 = blockIdx.x * 8;
    int tid = threadIdx.x;
    #pragma unroll
    for (int e = 0; e < 8; e++) xs[e * 128 + tid] = x[(n0 + e) * 128 + tid];
    __syncthreads();

    int j = tid;
    const float* WA = W1 + j;                 // rows 0..127 (x[col] part)
    const float* WB = W1 + 128 * 128 + j;     // rows 128..255 (x[row] part)
    const float4* xs4 = (const float4*)xs;
    float accA[8], accB[8];
    #pragma unroll
    for (int e = 0; e < 8; e++) { accA[e] = 0.f; accB[e] = 0.f; }

    for (int kk = 0; kk < 32; kk++) {
        float wa0 = WA[(kk * 4 + 0) * 128], wa1 = WA[(kk * 4 + 1) * 128];
        float wa2 = WA[(kk * 4 + 2) * 128], wa3 = WA[(kk * 4 + 3) * 128];
        float wb0 = WB[(kk * 4 + 0) * 128], wb1 = WB[(kk * 4 + 1) * 128];
        float wb2 = WB[(kk * 4 + 2) * 128], wb3 = WB[(kk * 4 + 3) * 128];
        #pragma unroll
        for (int e = 0; e < 8; e++) {
            float4 xv = xs4[e * 32 + kk];
            accA[e] += xv.x * wa0 + xv.y * wa1 + xv.z * wa2 + xv.w * wa3;
            accB[e] += xv.x * wb0 + xv.y * wb1 + xv.z * wb2 + xv.w * wb3;
        }
    }
    float b1j = b1[j];
    #pragma unroll
    for (int e = 0; e < 8; e++) {
        g_xa[(n0 + e) * 128 + j] = accA[e] + b1j;
        g_xb[(n0 + e) * 128 + j] = accB[e];
    }
}

// ------------------- edge kernel: h = relu(xa[col]+xb[row]+dist*w1c); m = relu(h@W2+b2);
//                     red-add m into msum[row] -------------------
__global__ void __launch_bounds__(256)
k_edge(const int* __restrict__ row, const int* __restrict__ col,
       const float* __restrict__ w1c, const float* __restrict__ W2,
       const float* __restrict__ b2) {
    __shared__ __align__(16) float hs[64 * 128];
    __shared__ int rows[64];
    __shared__ int cols[64];
    __shared__ float ds[64];
    int e0 = blockIdx.x * 64;
    int tid = threadIdx.x;
    if (tid < 64) {
        rows[tid] = row[e0 + tid];
        cols[tid] = col[e0 + tid];
        ds[tid] = g_dist[e0 + tid];
    }
    __syncthreads();

    for (int i = tid; i < 64 * 128; i += 256) {
        int e = i >> 7;
        int j = i & 127;
        float v = g_xa[cols[e] * 128 + j] + g_xb[rows[e] * 128 + j] + ds[e] * w1c[j];
        hs[i] = fmaxf(v, 0.f);
    }
    __syncthreads();

    int fg = tid & 31;      // 32 feature groups of 4
    int eg = tid >> 5;      // 8 edge groups of 8
    int f0 = fg * 4;
    float acc[8][4];
    #pragma unroll
    for (int e = 0; e < 8; e++)
        #pragma unroll
        for (int c = 0; c < 4; c++) acc[e][c] = 0.f;

    const float4* W2v = (const float4*)W2;
    const float4* hs4 = (const float4*)hs;

    for (int kk = 0; kk < 32; kk++) {
        float4 w0 = W2v[(kk * 4 + 0) * 32 + fg];
        float4 w1 = W2v[(kk * 4 + 1) * 32 + fg];
        float4 w2 = W2v[(kk * 4 + 2) * 32 + fg];
        float4 w3 = W2v[(kk * 4 + 3) * 32 + fg];
        #pragma unroll
        for (int e = 0; e < 8; e++) {
            float4 hv = hs4[(eg * 8 + e) * 32 + kk];
            acc[e][0] += hv.x * w0.x + hv.y * w1.x + hv.z * w2.x + hv.w * w3.x;
            acc[e][1] += hv.x * w0.y + hv.y * w1.y + hv.z * w2.y + hv.w * w3.y;
            acc[e][2] += hv.x * w0.z + hv.y * w1.z + hv.z * w2.z + hv.w * w3.z;
            acc[e][3] += hv.x * w0.w + hv.y * w1.w + hv.z * w2.w + hv.w * w3.w;
        }
    }

    float4 bb = *(const float4*)(b2 + f0);
    #pragma unroll
    for (int e = 0; e < 8; e++) {
        int ee = eg * 8 + e;
        int r = rows[ee];
        float m0 = fmaxf(acc[e][0] + bb.x, 0.f);
        float m1 = fmaxf(acc[e][1] + bb.y, 0.f);
        float m2 = fmaxf(acc[e][2] + bb.z, 0.f);
        float m3 = fmaxf(acc[e][3] + bb.w, 0.f);
        float* p = &g_msum[r * 128 + f0];
        asm volatile("red.global.add.v4.f32 [%0], {%1,%2,%3,%4};"
                     :: "l"(p), "f"(m0), "f"(m1), "f"(m2), "f"(m3) : "memory");
    }
}

// ------------------- update: x' = relu([x, msum*invdeg] @ U + b) -------------------
__global__ void __launch_bounds__(128)
k_update(const float* __restrict__ x, const float* __restrict__ W,
         const float* __restrict__ bias, float* __restrict__ xout) {
    __shared__ __align__(16) float xs[8 * 128];
    __shared__ __align__(16) float ms[8 * 128];
    __shared__ float idg[8];
    int n0 = blockIdx.x * 8;
    int tid = threadIdx.x;
    if (tid < 8) idg[tid] = g_invdeg[n0 + tid];
    #pragma unroll
    for (int e = 0; e < 8; e++) xs[e * 128 + tid] = x[(n0 + e) * 128 + tid];
    __syncthreads();
    #pragma unroll
    for (int e = 0; e < 8; e++) ms[e * 128 + tid] = g_msum[(n0 + e) * 128 + tid] * idg[e];
    __syncthreads();

    int j = tid;
    const float* WA = W + j;                 // rows 0..127 (x part)
    const float* WB = W + 128 * 128 + j;     // rows 128..255 (m_i part)
    const float4* xs4 = (const float4*)xs;
    const float4* ms4 = (const float4*)ms;
    float acc[8];
    #pragma unroll
    for (int e = 0; e < 8; e++) acc[e] = 0.f;

    for (int kk = 0; kk < 32; kk++) {
        float wa0 = WA[(kk * 4 + 0) * 128], wa1 = WA[(kk * 4 + 1) * 128];
        float wa2 = WA[(kk * 4 + 2) * 128], wa3 = WA[(kk * 4 + 3) * 128];
        float wb0 = WB[(kk * 4 + 0) * 128], wb1 = WB[(kk * 4 + 1) * 128];
        float wb2 = WB[(kk * 4 + 2) * 128], wb3 = WB[(kk * 4 + 3) * 128];
        #pragma unroll
        for (int e = 0; e < 8; e++) {
            float4 xv = xs4[e * 32 + kk];
            float4 mv = ms4[e * 32 + kk];
            acc[e] += xv.x * wa0 + xv.y * wa1 + xv.z * wa2 + xv.w * wa3
                    + mv.x * wb0 + mv.y * wb1 + mv.z * wb2 + mv.w * wb3;
        }
    }
    float bj = bias[j];
    #pragma unroll
    for (int e = 0; e < 8; e++)
        xout[(n0 + e) * 128 + j] = fmaxf(acc[e] + bj, 0.f);
}

// ------------------- readout pooling -------------------
__global__ void k_pool(const float* __restrict__ x, const int* __restrict__ batch,
                       const int* __restrict__ ntype) {
    int idx = blockIdx.x * blockDim.x + threadIdx.x;   // over Nn*32
    int n = idx >> 5;
    int q = idx & 31;
    if (n >= Nn) return;
    if (ntype[n] == 1) {
        float4 v = ((const float4*)x)[n * 32 + q];
        float* p = &g_gsum[batch[n] * 128 + q * 4];
        asm volatile("red.global.add.v4.f32 [%0], {%1,%2,%3,%4};"
                     :: "l"(p), "f"(v.x), "f"(v.y), "f"(v.z), "f"(v.w) : "memory");
    }
}

__global__ void k_ligcnt(const int* __restrict__ batch, const int* __restrict__ ntype) {
    int n = blockIdx.x * blockDim.x + threadIdx.x;
    if (n < Nn && ntype[n] == 1) atomicAdd(&g_ligcnt[batch[n]], 1.f);
}

__global__ void __launch_bounds__(128)
k_readout(const float* __restrict__ rw1, const float* __restrict__ rb1,
          const float* __restrict__ rw2, const float* __restrict__ rb2,
          float* __restrict__ out) {
    __shared__ __align__(16) float gs[128];
    __shared__ float red_s[128];
    int b = blockIdx.x;
    int tid = threadIdx.x;
    float cnt = fmaxf(g_ligcnt[b], 1.f);
    gs[tid] = g_gsum[b * 128 + tid] / cnt;
    __syncthreads();

    int j = tid;
    const float* Wj = rw1 + j;
    const float4* gs4 = (const float4*)gs;
    float acc = rb1[j];
    for (int kk = 0; kk < 32; kk++) {
        float w0 = Wj[(kk * 4 + 0) * 128];
        float w1 = Wj[(kk * 4 + 1) * 128];
        float w2 = Wj[(kk * 4 + 2) * 128];
        float w3 = Wj[(kk * 4 + 3) * 128];
        float4 gv = gs4[kk];
        acc += gv.x * w0 + gv.y * w1 + gv.z * w2 + gv.w * w3;
    }
    float hg = fmaxf(acc, 0.f);
    red_s[tid] = hg * rw2[j];
    __syncthreads();
    for (int s = 64; s > 0; s >>= 1) {
        if (tid < s) red_s[tid] += red_s[tid + s];
        __syncthreads();
    }
    if (tid == 0) out[b] = red_s[0] + rb2[0];
}

// ------------------- launch -------------------
extern "C" void kernel_launch(void* const* d_in, const int* in_sizes, int n_in,
                              void* d_out, int out_size) {
    const float* pos   = (const float*)d_in[0];
    const int*   z     = (const int*)d_in[1];
    const int*   batch = (const int*)d_in[2];
    const int*   eidx  = (const int*)d_in[3];
    const int*   ntype = (const int*)d_in[4];
    const float* emb   = (const float*)d_in[5];
    const float* lin_w = (const float*)d_in[6];
    const float* lin_b = (const float*)d_in[7];
    const float* mw1   = (const float*)d_in[8];
    const float* mb1   = (const float*)d_in[9];
    const float* mw2   = (const float*)d_in[10];
    const float* mb2   = (const float*)d_in[11];
    const float* uw    = (const float*)d_in[12];
    const float* ub    = (const float*)d_in[13];
    const float* rw1   = (const float*)d_in[14];
    const float* rb1   = (const float*)d_in[15];
    const float* rw2   = (const float*)d_in[16];
    const float* rb2   = (const float*)d_in[17];
    float* out = (float*)d_out;
    const int* row = eidx;
    const int* col = eidx + Ee;

    void *p_csum, *p_deg, *p_msum, *p_gsum, *p_lig, *p_x0, *p_x1;
    cudaGetSymbolAddress(&p_csum, g_csum);
    cudaGetSymbolAddress(&p_deg, g_deg);
    cudaGetSymbolAddress(&p_msum, g_msum);
    cudaGetSymbolAddress(&p_gsum, g_gsum);
    cudaGetSymbolAddress(&p_lig, g_ligcnt);
    cudaGetSymbolAddress(&p_x0, g_x0);
    cudaGetSymbolAddress(&p_x1, g_x1);
    float* xbuf[2] = {(float*)p_x0, (float*)p_x1};

    cudaMemsetAsync(p_csum, 0, Bb * 4 * sizeof(float));
    cudaMemsetAsync(p_deg, 0, Nn * sizeof(int));
    cudaMemsetAsync(p_gsum, 0, Bb * Hh * sizeof(float));
    cudaMemsetAsync(p_lig, 0, Bb * sizeof(float));

    k_center_sum<<<128, 256>>>(pos, batch);
    k_center_fin<<<1, 64>>>();
    k_input<<<Nn / 8, 128>>>(pos, z, batch, emb, lin_w, lin_b);
    k_dist<<<Ee / 256, 256>>>(eidx);
    k_deg<<<Ee / 256, 256>>>(row);
    k_invdeg<<<Nn / 256, 256>>>();

    for (int l = 0; l < 3; l++) {
        const float* W1 = mw1 + l * 257 * 128;
        k_xab<<<Nn / 8, 128>>>(xbuf[l & 1], W1, mb1 + l * 128);
        cudaMemsetAsync(p_msum, 0, (size_t)Nn * Hh * sizeof(float));
        k_edge<<<Ee / 64, 256>>>(row, col, W1 + 256 * 128, mw2 + l * 128 * 128, mb2 + l * 128);
        k_update<<<Nn / 8, 128>>>(xbuf[l & 1], uw + l * 256 * 128, ub + l * 128, xbuf[(l + 1) & 1]);
    }

    k_pool<<<Nn * 32 / 256, 256>>>(xbuf[1], batch, ntype);
    k_ligcnt<<<Nn / 256, 256>>>(batch, ntype);
    k_readout<<<Bb, 128>>>(rw1, rb1, rw2, rb2, out);
}

// round 3
// speedup vs baseline: 1.5548x; 1.5548x over previous
#include <cuda_runtime.h>
#include <cuda_bf16.h>
#include <math.h>
#include <stdint.h>

#define Nn 65536
#define Ee 1048576
#define Bb 64
#define Hh 128

// ------------------- scratch (static device globals; no allocation) -------------------
__device__ float g_csum[Bb * 4];
__device__ float g_center[Bb * 3];
__device__ float g_posrel[Nn * 3];
__device__ float g_x0[Nn * Hh];
__device__ float g_x1[Nn * Hh];
__device__ float g_xa[Nn * Hh];           // x @ W1a + b1  (gathered at col)
__device__ float g_xb[Nn * Hh];           // x @ W1b       (gathered at row)
__device__ float g_msum[Nn * Hh];         // scatter-add of m_ij at row
__device__ float g_dist[Ee];
__device__ int   g_deg[Nn];
__device__ float g_invdeg[Nn];
__device__ float g_gsum[Bb * Hh];
__device__ float g_ligcnt[Bb];
// W2^T as bf16 hi/lo, plain [n][k] row-major (256B rows)
__device__ uint16_t g_w2t_hi[128 * 128];
__device__ uint16_t g_w2t_lo[128 * 128];

// ------------------- mma helpers (plain sm_103 features only) -------------------
__device__ __forceinline__ uint32_t smem_u32(const void* p) {
    uint32_t a;
    asm("{ .reg .u64 t; cvta.to.shared.u64 t, %1; cvt.u32.u64 %0, t; }" : "=r"(a) : "l"(p));
    return a;
}

__device__ __forceinline__ void ldsm_x4(uint32_t* r, uint32_t addr) {
    asm volatile("ldmatrix.sync.aligned.m8n8.x4.shared.b16 {%0,%1,%2,%3}, [%4];"
                 : "=r"(r[0]), "=r"(r[1]), "=r"(r[2]), "=r"(r[3]) : "r"(addr));
}
__device__ __forceinline__ void ldsm_x2(uint32_t* r, uint32_t addr) {
    asm volatile("ldmatrix.sync.aligned.m8n8.x2.shared.b16 {%0,%1}, [%2];"
                 : "=r"(r[0]), "=r"(r[1]) : "r"(addr));
}
__device__ __forceinline__ void mma_bf16(float* d, const uint32_t* a, const uint32_t* b) {
    asm volatile("mma.sync.aligned.m16n8k16.row.col.f32.bf16.bf16.f32 "
                 "{%0,%1,%2,%3}, {%4,%5,%6,%7}, {%8,%9}, {%0,%1,%2,%3};"
                 : "+f"(d[0]), "+f"(d[1]), "+f"(d[2]), "+f"(d[3])
                 : "r"(a[0]), "r"(a[1]), "r"(a[2]), "r"(a[3]), "r"(b[0]), "r"(b[1]));
}

// ------------------- small kernels -------------------
__global__ void k_center_sum(const float* __restrict__ pos, const int* __restrict__ batch) {
    __shared__ float sb[Bb * 4];
    for (int i = threadIdx.x; i < Bb * 4; i += blockDim.x) sb[i] = 0.f;
    __syncthreads();
    for (int n = blockIdx.x * blockDim.x + threadIdx.x; n < Nn; n += gridDim.x * blockDim.x) {
        int b = batch[n];
        atomicAdd(&sb[b * 4 + 0], pos[n * 3 + 0]);
        atomicAdd(&sb[b * 4 + 1], pos[n * 3 + 1]);
        atomicAdd(&sb[b * 4 + 2], pos[n * 3 + 2]);
        atomicAdd(&sb[b * 4 + 3], 1.f);
    }
    __syncthreads();
    for (int i = threadIdx.x; i < Bb * 4; i += blockDim.x)
        if (sb[i] != 0.f) atomicAdd(&g_csum[i], sb[i]);
}

__global__ void k_center_fin() {
    int b = threadIdx.x;
    if (b < Bb) {
        float c = fmaxf(g_csum[b * 4 + 3], 1.f);
        g_center[b * 3 + 0] = g_csum[b * 4 + 0] / c;
        g_center[b * 3 + 1] = g_csum[b * 4 + 1] / c;
        g_center[b * 3 + 2] = g_csum[b * 4 + 2] / c;
    }
}

__global__ void k_dist(const int* __restrict__ eidx) {
    int e = blockIdx.x * blockDim.x + threadIdx.x;
    if (e >= Ee) return;
    int r = eidx[e], c = eidx[Ee + e];
    float dx = g_posrel[c * 3 + 0] - g_posrel[r * 3 + 0];
    float dy = g_posrel[c * 3 + 1] - g_posrel[r * 3 + 1];
    float dz = g_posrel[c * 3 + 2] - g_posrel[r * 3 + 2];
    g_dist[e] = sqrtf(dx * dx + dy * dy + dz * dz);
}

__global__ void k_deg(const int* __restrict__ row) {
    int e = blockIdx.x * blockDim.x + threadIdx.x;
    if (e < Ee) atomicAdd(&g_deg[row[e]], 1);
}

__global__ void k_invdeg() {
    int n = blockIdx.x * blockDim.x + threadIdx.x;
    if (n < Nn) g_invdeg[n] = 1.f / fmaxf((float)g_deg[n], 1.f);
}

// W2^T -> bf16 hi/lo, plain [n][k]
__global__ void k_w2prep(const float* __restrict__ W2) {
    int idx = blockIdx.x * blockDim.x + threadIdx.x;   // 16384
    if (idx >= 128 * 128) return;
    int n = idx >> 7, k = idx & 127;
    float v = W2[k * 128 + n];
    __nv_bfloat16 h = __float2bfloat16_rn(v);
    __nv_bfloat16 l = __float2bfloat16_rn(v - __bfloat162float(h));
    g_w2t_hi[n * 128 + k] = *(uint16_t*)&h;
    g_w2t_lo[n * 128 + k] = *(uint16_t*)&l;
}

// ------------------- input embedding + lin_in -------------------
__global__ void __launch_bounds__(128)
k_input(const float* __restrict__ pos, const int* __restrict__ z,
        const int* __restrict__ batch, const float* __restrict__ emb,
        const float* __restrict__ W, const float* __restrict__ bias) {
    __shared__ __align__(16) float fs[8 * 128];
    __shared__ float prs[8][3];
    int n0 = blockIdx.x * 8;
    int tid = threadIdx.x;
    if (tid < 8) {
        int n = n0 + tid;
        int b = batch[n];
        #pragma unroll
        for (int d = 0; d < 3; d++) {
            float v = pos[n * 3 + d] - g_center[b * 3 + d];
            prs[tid][d] = v;
            g_posrel[n * 3 + d] = v;
        }
    }
    #pragma unroll
    for (int e = 0; e < 8; e++)
        fs[e * 128 + tid] = emb[z[n0 + e] * 128 + tid];
    __syncthreads();

    int j = tid;
    const float* Wj = W + j;
    const float4* fs4 = (const float4*)fs;
    float acc[8];
    #pragma unroll
    for (int e = 0; e < 8; e++) acc[e] = 0.f;

    for (int kk = 0; kk < 32; kk++) {
        float w0 = Wj[(kk * 4 + 0) * 128];
        float w1 = Wj[(kk * 4 + 1) * 128];
        float w2 = Wj[(kk * 4 + 2) * 128];
        float w3 = Wj[(kk * 4 + 3) * 128];
        #pragma unroll
        for (int e = 0; e < 8; e++) {
            float4 xv = fs4[e * 32 + kk];
            acc[e] += xv.x * w0 + xv.y * w1 + xv.z * w2 + xv.w * w3;
        }
    }
    #pragma unroll
    for (int d = 0; d < 3; d++) {
        float w = Wj[(128 + d) * 128];
        #pragma unroll
        for (int e = 0; e < 8; e++) acc[e] += prs[e][d] * w;
    }
    float bj = bias[j];
    #pragma unroll
    for (int e = 0; e < 8; e++) g_x0[(n0 + e) * 128 + j] = acc[e] + bj;
}

// ------------------- per-layer node pre-GEMM -------------------
__global__ void __launch_bounds__(128)
k_xab(const float* __restrict__ x, const float* __restrict__ W1, const float* __restrict__ b1) {
    __shared__ __align__(16) float xs[8 * 128];
    int n0 = blockIdx.x * 8;
    int tid = threadIdx.x;
    #pragma unroll
    for (int e = 0; e < 8; e++) xs[e * 128 + tid] = x[(n0 + e) * 128 + tid];
    __syncthreads();

    int j = tid;
    const float* WA = W1 + j;
    const float* WB = W1 + 128 * 128 + j;
    const float4* xs4 = (const float4*)xs;
    float accA[8], accB[8];
    #pragma unroll
    for (int e = 0; e < 8; e++) { accA[e] = 0.f; accB[e] = 0.f; }

    for (int kk = 0; kk < 32; kk++) {
        float wa0 = WA[(kk * 4 + 0) * 128], wa1 = WA[(kk * 4 + 1) * 128];
        float wa2 = WA[(kk * 4 + 2) * 128], wa3 = WA[(kk * 4 + 3) * 128];
        float wb0 = WB[(kk * 4 + 0) * 128], wb1 = WB[(kk * 4 + 1) * 128];
        float wb2 = WB[(kk * 4 + 2) * 128], wb3 = WB[(kk * 4 + 3) * 128];
        #pragma unroll
        for (int e = 0; e < 8; e++) {
            float4 xv = xs4[e * 32 + kk];
            accA[e] += xv.x * wa0 + xv.y * wa1 + xv.z * wa2 + xv.w * wa3;
            accB[e] += xv.x * wb0 + xv.y * wb1 + xv.z * wb2 + xv.w * wb3;
        }
    }
    float b1j = b1[j];
    #pragma unroll
    for (int e = 0; e < 8; e++) {
        g_xa[(n0 + e) * 128 + j] = accA[e] + b1j;
        g_xb[(n0 + e) * 128 + j] = accB[e];
    }
}

// ------------------- HMMA edge kernel -------------------
// per CTA: 128 edges. h = relu(xa[col]+xb[row]+dist*w1c)  -> bf16 hi/lo split in smem
// D(128x128 fp32) = Ahi*Bhi + Alo*Bhi + Ahi*Blo  via mma.sync m16n8k16 (B = W2^T)
// m = relu(D + b2) -> red.global.add.v2 into g_msum[row] directly from fragments
#define EOFF_ROWS 0
#define EOFF_COLS 512
#define EOFF_DIST 1024
#define EOFF_BIAS 1536
#define EOFF_W1C  2048
#define EOFF_AHI  2560
#define E_ASZ     34816            // 128 rows * 272B
#define EOFF_ALO  (EOFF_AHI + E_ASZ)
#define EOFF_BHI  (EOFF_ALO + E_ASZ)
#define EOFF_BLO  (EOFF_BHI + E_ASZ)
#define E_SMEM    (EOFF_BLO + E_ASZ)   // 141824 bytes

__global__ void __launch_bounds__(256, 1)
k_edge_mma(const int* __restrict__ row, const int* __restrict__ col,
           const float* __restrict__ w1c, const float* __restrict__ b2) {
    extern __shared__ __align__(16) char sm[];
    uint32_t sbase = smem_u32(sm);
    int tid = threadIdx.x;
    int lane = tid & 31;
    int wid = tid >> 5;
    int e0 = blockIdx.x * 128;

    int*   rows = (int*)(sm + EOFF_ROWS);
    int*   cols = (int*)(sm + EOFF_COLS);
    float* ds   = (float*)(sm + EOFF_DIST);
    float* bs   = (float*)(sm + EOFF_BIAS);
    float* ws   = (float*)(sm + EOFF_W1C);

    if (tid < 128) {
        rows[tid] = row[e0 + tid];
        cols[tid] = col[e0 + tid];
        ds[tid]   = g_dist[e0 + tid];
        bs[tid]   = b2[tid];
        ws[tid]   = w1c[tid];
    }

    // copy B (W2^T) hi/lo into padded smem: 128 rows x 256B data, stride 272B
    {
        const uint4* bh = (const uint4*)g_w2t_hi;
        const uint4* bl = (const uint4*)g_w2t_lo;
        #pragma unroll
        for (int it = 0; it < 8; it++) {
            int i = tid + it * 256;           // 0..2047
            int r = i >> 4, c = i & 15;
            *(uint4*)(sm + EOFF_BHI + r * 272 + c * 16) = bh[i];
            *(uint4*)(sm + EOFF_BLO + r * 272 + c * 16) = bl[i];
        }
    }
    __syncthreads();

    // build A (h) tiles: 2048 chunks of 8 K-values; 8 chunks per thread
    #pragma unroll
    for (int it = 0; it < 8; it++) {
        int cid = tid + it * 256;
        int e = cid >> 4;
        int kc = cid & 15;
        const float4* pa = (const float4*)(g_xa + (size_t)cols[e] * 128) + kc * 2;
        const float4* pb = (const float4*)(g_xb + (size_t)rows[e] * 128) + kc * 2;
        float d = ds[e];
        float4 a0 = pa[0], a1 = pa[1];
        float4 b0 = pb[0], b1 = pb[1];
        int k0 = kc * 8;
        float v[8];
        v[0] = fmaxf(a0.x + b0.x + d * ws[k0 + 0], 0.f);
        v[1] = fmaxf(a0.y + b0.y + d * ws[k0 + 1], 0.f);
        v[2] = fmaxf(a0.z + b0.z + d * ws[k0 + 2], 0.f);
        v[3] = fmaxf(a0.w + b0.w + d * ws[k0 + 3], 0.f);
        v[4] = fmaxf(a1.x + b1.x + d * ws[k0 + 4], 0.f);
        v[5] = fmaxf(a1.y + b1.y + d * ws[k0 + 5], 0.f);
        v[6] = fmaxf(a1.z + b1.z + d * ws[k0 + 6], 0.f);
        v[7] = fmaxf(a1.w + b1.w + d * ws[k0 + 7], 0.f);
        uint32_t hw[4], lw[4];
        #pragma unroll
        for (int p = 0; p < 4; p++) {
            __nv_bfloat162 h2;
            h2.x = __float2bfloat16_rn(v[2 * p]);
            h2.y = __float2bfloat16_rn(v[2 * p + 1]);
            float r0 = v[2 * p]     - __bfloat162float(h2.x);
            float r1 = v[2 * p + 1] - __bfloat162float(h2.y);
            __nv_bfloat162 l2;
            l2.x = __float2bfloat16_rn(r0);
            l2.y = __float2bfloat16_rn(r1);
            hw[p] = *(uint32_t*)&h2;
            lw[p] = *(uint32_t*)&l2;
        }
        *(uint4*)(sm + EOFF_AHI + e * 272 + kc * 16) = make_uint4(hw[0], hw[1], hw[2], hw[3]);
        *(uint4*)(sm + EOFF_ALO + e * 272 + kc * 16) = make_uint4(lw[0], lw[1], lw[2], lw[3]);
    }
    __syncthreads();

    // warp tile: m32 x n64.  8 warps: warp_m = wid & 3, warp_n = wid >> 2
    int warp_m = wid & 3;
    int warp_n = wid >> 2;

    float acc[2][8][4];
    #pragma unroll
    for (int mt = 0; mt < 2; mt++)
        #pragma unroll
        for (int nt = 0; nt < 8; nt++)
            #pragma unroll
            for (int q = 0; q < 4; q++) acc[mt][nt][q] = 0.f;

    uint32_t a_row_off = (uint32_t)(warp_m * 32 + (lane & 15)) * 272 + (uint32_t)(lane >> 4) * 16;
    uint32_t b_row_off = (uint32_t)(warp_n * 64 + (lane & 7)) * 272 + (uint32_t)((lane >> 3) & 1) * 16;

    for (int ks = 0; ks < 8; ks++) {
        uint32_t kb = (uint32_t)ks * 32;
        uint32_t a_hi[2][4], a_lo[2][4];
        #pragma unroll
        for (int mt = 0; mt < 2; mt++) {
            uint32_t ad = sbase + EOFF_AHI + a_row_off + (uint32_t)(mt * 16) * 272 + kb;
            ldsm_x4(a_hi[mt], ad);
            ldsm_x4(a_lo[mt], ad + (EOFF_ALO - EOFF_AHI));
        }
        uint32_t b_hi[8][2], b_lo[8][2];
        #pragma unroll
        for (int nt = 0; nt < 8; nt++) {
            uint32_t bd = sbase + EOFF_BHI + b_row_off + (uint32_t)(nt * 8) * 272 + kb;
            ldsm_x2(b_hi[nt], bd);
            ldsm_x2(b_lo[nt], bd + (EOFF_BLO - EOFF_BHI));
        }
        #pragma unroll
        for (int mt = 0; mt < 2; mt++)
            #pragma unroll
            for (int nt = 0; nt < 8; nt++)
                mma_bf16(acc[mt][nt], a_hi[mt], b_hi[nt]);
        #pragma unroll
        for (int mt = 0; mt < 2; mt++)
            #pragma unroll
            for (int nt = 0; nt < 8; nt++)
                mma_bf16(acc[mt][nt], a_lo[mt], b_hi[nt]);
        #pragma unroll
        for (int mt = 0; mt < 2; mt++)
            #pragma unroll
            for (int nt = 0; nt < 8; nt++)
                mma_bf16(acc[mt][nt], a_hi[mt], b_lo[nt]);
    }

    // epilogue: bias + relu + scatter red.v2 per fragment row
    #pragma unroll
    for (int mt = 0; mt < 2; mt++) {
        int er = warp_m * 32 + mt * 16 + (lane >> 2);
        int r0 = rows[er];
        int r1 = rows[er + 8];
        float* m0p = g_msum + (size_t)r0 * 128;
        float* m1p = g_msum + (size_t)r1 * 128;
        #pragma unroll
        for (int nt = 0; nt < 8; nt++) {
            int cb = warp_n * 64 + nt * 8 + (lane & 3) * 2;
            float bb0 = bs[cb], bb1 = bs[cb + 1];
            float v0 = fmaxf(acc[mt][nt][0] + bb0, 0.f);
            float v1 = fmaxf(acc[mt][nt][1] + bb1, 0.f);
            float v2 = fmaxf(acc[mt][nt][2] + bb0, 0.f);
            float v3 = fmaxf(acc[mt][nt][3] + bb1, 0.f);
            asm volatile("red.global.add.v2.f32 [%0], {%1,%2};"
                         :: "l"(m0p + cb), "f"(v0), "f"(v1) : "memory");
            asm volatile("red.global.add.v2.f32 [%0], {%1,%2};"
                         :: "l"(m1p + cb), "f"(v2), "f"(v3) : "memory");
        }
    }
}

// ------------------- update -------------------
__global__ void __launch_bounds__(128)
k_update(const float* __restrict__ x, const float* __restrict__ W,
         const float* __restrict__ bias, float* __restrict__ xout) {
    __shared__ __align__(16) float xs[8 * 128];
    __shared__ __align__(16) float ms[8 * 128];
    __shared__ float idg[8];
    int n0 = blockIdx.x * 8;
    int tid = threadIdx.x;
    if (tid < 8) idg[tid] = g_invdeg[n0 + tid];
    #pragma unroll
    for (int e = 0; e < 8; e++) xs[e * 128 + tid] = x[(n0 + e) * 128 + tid];
    __syncthreads();
    #pragma unroll
    for (int e = 0; e < 8; e++) ms[e * 128 + tid] = g_msum[(n0 + e) * 128 + tid] * idg[e];
    __syncthreads();

    int j = tid;
    const float* WA = W + j;
    const float* WB = W + 128 * 128 + j;
    const float4* xs4 = (const float4*)xs;
    const float4* ms4 = (const float4*)ms;
    float acc[8];
    #pragma unroll
    for (int e = 0; e < 8; e++) acc[e] = 0.f;

    for (int kk = 0; kk < 32; kk++) {
        float wa0 = WA[(kk * 4 + 0) * 128], wa1 = WA[(kk * 4 + 1) * 128];
        float wa2 = WA[(kk * 4 + 2) * 128], wa3 = WA[(kk * 4 + 3) * 128];
        float wb0 = WB[(kk * 4 + 0) * 128], wb1 = WB[(kk * 4 + 1) * 128];
        float wb2 = WB[(kk * 4 + 2) * 128], wb3 = WB[(kk * 4 + 3) * 128];
        #pragma unroll
        for (int e = 0; e < 8; e++) {
            float4 xv = xs4[e * 32 + kk];
            float4 mv = ms4[e * 32 + kk];
            acc[e] += xv.x * wa0 + xv.y * wa1 + xv.z * wa2 + xv.w * wa3
                    + mv.x * wb0 + mv.y * wb1 + mv.z * wb2 + mv.w * wb3;
        }
    }
    float bj = bias[j];
    #pragma unroll
    for (int e = 0; e < 8; e++)
        xout[(n0 + e) * 128 + j] = fmaxf(acc[e] + bj, 0.f);
}

// ------------------- readout pooling -------------------
__global__ void k_pool(const float* __restrict__ x, const int* __restrict__ batch,
                       const int* __restrict__ ntype) {
    int idx = blockIdx.x * blockDim.x + threadIdx.x;
    int n = idx >> 5;
    int q = idx & 31;
    if (n >= Nn) return;
    if (ntype[n] == 1) {
        float4 v = ((const float4*)x)[n * 32 + q];
        float* p = &g_gsum[batch[n] * 128 + q * 4];
        asm volatile("red.global.add.v4.f32 [%0], {%1,%2,%3,%4};"
                     :: "l"(p), "f"(v.x), "f"(v.y), "f"(v.z), "f"(v.w) : "memory");
    }
}

__global__ void k_ligcnt(const int* __restrict__ batch, const int* __restrict__ ntype) {
    int n = blockIdx.x * blockDim.x + threadIdx.x;
    if (n < Nn && ntype[n] == 1) atomicAdd(&g_ligcnt[batch[n]], 1.f);
}

__global__ void __launch_bounds__(128)
k_readout(const float* __restrict__ rw1, const float* __restrict__ rb1,
          const float* __restrict__ rw2, const float* __restrict__ rb2,
          float* __restrict__ out) {
    __shared__ __align__(16) float gs[128];
    __shared__ float red_s[128];
    int b = blockIdx.x;
    int tid = threadIdx.x;
    float cnt = fmaxf(g_ligcnt[b], 1.f);
    gs[tid] = g_gsum[b * 128 + tid] / cnt;
    __syncthreads();

    int j = tid;
    const float* Wj = rw1 + j;
    const float4* gs4 = (const float4*)gs;
    float acc = rb1[j];
    for (int kk = 0; kk < 32; kk++) {
        float w0 = Wj[(kk * 4 + 0) * 128];
        float w1 = Wj[(kk * 4 + 1) * 128];
        float w2 = Wj[(kk * 4 + 2) * 128];
        float w3 = Wj[(kk * 4 + 3) * 128];
        float4 gv = gs4[kk];
        acc += gv.x * w0 + gv.y * w1 + gv.z * w2 + gv.w * w3;
    }
    float hg = fmaxf(acc, 0.f);
    red_s[tid] = hg * rw2[j];
    __syncthreads();
    for (int s = 64; s > 0; s >>= 1) {
        if (tid < s) red_s[tid] += red_s[tid + s];
        __syncthreads();
    }
    if (tid == 0) out[b] = red_s[0] + rb2[0];
}

// ------------------- launch -------------------
extern "C" void kernel_launch(void* const* d_in, const int* in_sizes, int n_in,
                              void* d_out, int out_size) {
    const float* pos   = (const float*)d_in[0];
    const int*   z     = (const int*)d_in[1];
    const int*   batch = (const int*)d_in[2];
    const int*   eidx  = (const int*)d_in[3];
    const int*   ntype = (const int*)d_in[4];
    const float* emb   = (const float*)d_in[5];
    const float* lin_w = (const float*)d_in[6];
    const float* lin_b = (const float*)d_in[7];
    const float* mw1   = (const float*)d_in[8];
    const float* mb1   = (const float*)d_in[9];
    const float* mw2   = (const float*)d_in[10];
    const float* mb2   = (const float*)d_in[11];
    const float* uw    = (const float*)d_in[12];
    const float* ub    = (const float*)d_in[13];
    const float* rw1   = (const float*)d_in[14];
    const float* rb1   = (const float*)d_in[15];
    const float* rw2   = (const float*)d_in[16];
    const float* rb2   = (const float*)d_in[17];
    float* out = (float*)d_out;
    const int* row = eidx;
    const int* col = eidx + Ee;

    cudaFuncSetAttribute(k_edge_mma, cudaFuncAttributeMaxDynamicSharedMemorySize, E_SMEM);

    void *p_csum, *p_deg, *p_msum, *p_gsum, *p_lig, *p_x0, *p_x1;
    cudaGetSymbolAddress(&p_csum, g_csum);
    cudaGetSymbolAddress(&p_deg, g_deg);
    cudaGetSymbolAddress(&p_msum, g_msum);
    cudaGetSymbolAddress(&p_gsum, g_gsum);
    cudaGetSymbolAddress(&p_lig, g_ligcnt);
    cudaGetSymbolAddress(&p_x0, g_x0);
    cudaGetSymbolAddress(&p_x1, g_x1);
    float* xbuf[2] = {(float*)p_x0, (float*)p_x1};

    cudaMemsetAsync(p_csum, 0, Bb * 4 * sizeof(float));
    cudaMemsetAsync(p_deg, 0, Nn * sizeof(int));
    cudaMemsetAsync(p_gsum, 0, Bb * Hh * sizeof(float));
    cudaMemsetAsync(p_lig, 0, Bb * sizeof(float));

    k_center_sum<<<128, 256>>>(pos, batch);
    k_center_fin<<<1, 64>>>();
    k_input<<<Nn / 8, 128>>>(pos, z, batch, emb, lin_w, lin_b);
    k_dist<<<Ee / 256, 256>>>(eidx);
    k_deg<<<Ee / 256, 256>>>(row);
    k_invdeg<<<Nn / 256, 256>>>();

    for (int l = 0; l < 3; l++) {
        const float* W1 = mw1 + l * 257 * 128;
        k_xab<<<Nn / 8, 128>>>(xbuf[l & 1], W1, mb1 + l * 128);
        k_w2prep<<<64, 256>>>(mw2 + l * 128 * 128);
        cudaMemsetAsync(p_msum, 0, (size_t)Nn * Hh * sizeof(float));
        k_edge_mma<<<Ee / 128, 256, E_SMEM>>>(row, col, W1 + 256 * 128, mb2 + l * 128);
        k_update<<<Nn / 8, 128>>>(xbuf[l & 1], uw + l * 256 * 128, ub + l * 128, xbuf[(l + 1) & 1]);
    }

    k_pool<<<Nn * 32 / 256, 256>>>(xbuf[1], batch, ntype);
    k_ligcnt<<<Nn / 256, 256>>>(batch, ntype);
    k_readout<<<Bb, 128>>>(rw1, rb1, rw2, rb2, out);
}

// round 6
// speedup vs baseline: 1.9286x; 1.2404x over previous
#include <cuda_runtime.h>
#include <cuda_bf16.h>
#include <math.h>
#include <stdint.h>

#define Nn 65536
#define Ee 1048576
#define Bb 64
#define Hh 128

// ------------------- scratch (static device globals; no allocation) -------------------
__device__ float g_csum[Bb * 4];
__device__ float g_center[Bb * 3];
__device__ float g_posrel[Nn * 3];
__device__ float g_x0[Nn * Hh];           // fp32 node features (in-place across layers)
__device__ uint32_t g_xhi[Nn * 64];       // bf16x2-packed hi split of x
__device__ uint32_t g_xlo[Nn * 64];       // bf16x2-packed lo split of x
__device__ float g_xa[Nn * Hh];           // x @ W1a + b1  (gathered at col)
__device__ float g_xb[Nn * Hh];           // x @ W1b       (gathered at row)
__device__ float g_msum[Nn * Hh];         // scatter-add of m_ij at row
__device__ float g_dist[Ee];
__device__ int   g_deg[Nn];
__device__ float g_invdeg[Nn];
__device__ float g_gsum[Bb * Hh];
__device__ float g_ligcnt[Bb];
// prepped transposed weights, bf16 hi/lo, [out][k] row-major
__device__ uint16_t g_w1t_hi[3 * 256 * 128], g_w1t_lo[3 * 256 * 128];
__device__ uint16_t g_w2t_hi[3 * 128 * 128], g_w2t_lo[3 * 128 * 128];
__device__ uint16_t g_ut_hi[3 * 128 * 256], g_ut_lo[3 * 128 * 256];

// ------------------- helpers -------------------
__device__ __forceinline__ uint32_t smem_u32(const void* p) {
    uint32_t a;
    asm("{ .reg .u64 t; cvta.to.shared.u64 t, %1; cvt.u32.u64 %0, t; }" : "=r"(a) : "l"(p));
    return a;
}
__device__ __forceinline__ void ldsm_x4(uint32_t* r, uint32_t addr) {
    asm volatile("ldmatrix.sync.aligned.m8n8.x4.shared.b16 {%0,%1,%2,%3}, [%4];"
                 : "=r"(r[0]), "=r"(r[1]), "=r"(r[2]), "=r"(r[3]) : "r"(addr));
}
__device__ __forceinline__ void ldsm_x2(uint32_t* r, uint32_t addr) {
    asm volatile("ldmatrix.sync.aligned.m8n8.x2.shared.b16 {%0,%1}, [%2];"
                 : "=r"(r[0]), "=r"(r[1]) : "r"(addr));
}
__device__ __forceinline__ void mma_bf16(float* d, const uint32_t* a, const uint32_t* b) {
    asm volatile("mma.sync.aligned.m16n8k16.row.col.f32.bf16.bf16.f32 "
                 "{%0,%1,%2,%3}, {%4,%5,%6,%7}, {%8,%9}, {%0,%1,%2,%3};"
                 : "+f"(d[0]), "+f"(d[1]), "+f"(d[2]), "+f"(d[3])
                 : "r"(a[0]), "r"(a[1]), "r"(a[2]), "r"(a[3]), "r"(b[0]), "r"(b[1]));
}
// split two fp32 into bf16x2 hi + bf16x2 lo (residual)
__device__ __forceinline__ void split2(float v0, float v1, uint32_t& hi, uint32_t& lo) {
    __nv_bfloat162 h = __floats2bfloat162_rn(v0, v1);
    uint32_t hu = *(uint32_t*)&h;
    float h0 = __uint_as_float(hu << 16);
    float h1 = __uint_as_float(hu & 0xFFFF0000u);
    __nv_bfloat162 l = __floats2bfloat162_rn(v0 - h0, v1 - h1);
    hi = hu; lo = *(uint32_t*)&l;
}

// shared 3-term MMA core: D(128x128) += Ahi*Bhi + Alo*Bhi + Ahi*Blo
// A,B tiles in smem, 128 rows x 256B data, 272B stride. 8 warps, warp tile m32 x n64.
__device__ __forceinline__ void mma3_128(uint32_t sbase, uint32_t oAhi, uint32_t oAlo,
                                         uint32_t oBhi, uint32_t oBlo,
                                         int lane, int warp_m, int warp_n,
                                         float (&acc)[2][8][4]) {
    uint32_t a_base = sbase + oAhi + (uint32_t)(warp_m * 32 + (lane & 15)) * 272 + (uint32_t)(lane >> 4) * 16;
    uint32_t b_base = sbase + oBhi + (uint32_t)(warp_n * 64 + (lane & 7)) * 272 + (uint32_t)((lane >> 3) & 1) * 16;
    uint32_t dA = oAlo - oAhi, dB = oBlo - oBhi;
    for (int ks = 0; ks < 8; ks++) {
        uint32_t kb = (uint32_t)ks * 32;
        uint32_t a_hi[2][4], a_lo[2][4];
        #pragma unroll
        for (int mt = 0; mt < 2; mt++) {
            uint32_t ad = a_base + (uint32_t)(mt * 16) * 272 + kb;
            ldsm_x4(a_hi[mt], ad);
            ldsm_x4(a_lo[mt], ad + dA);
        }
        uint32_t b_hi[8][2], b_lo[8][2];
        #pragma unroll
        for (int nt = 0; nt < 8; nt++) {
            uint32_t bd = b_base + (uint32_t)(nt * 8) * 272 + kb;
            ldsm_x2(b_hi[nt], bd);
            ldsm_x2(b_lo[nt], bd + dB);
        }
        #pragma unroll
        for (int mt = 0; mt < 2; mt++)
            #pragma unroll
            for (int nt = 0; nt < 8; nt++)
                mma_bf16(acc[mt][nt], a_hi[mt], b_hi[nt]);
        #pragma unroll
        for (int mt = 0; mt < 2; mt++)
            #pragma unroll
            for (int nt = 0; nt < 8; nt++)
                mma_bf16(acc[mt][nt], a_lo[mt], b_hi[nt]);
        #pragma unroll
        for (int mt = 0; mt < 2; mt++)
            #pragma unroll
            for (int nt = 0; nt < 8; nt++)
                mma_bf16(acc[mt][nt], a_hi[mt], b_lo[nt]);
    }
}

// stage fragments into smem m-buffer (stride 528B) for coalesced epilogue
__device__ __forceinline__ void stage_acc(char* sm, uint32_t oM, int lane, int warp_m, int warp_n,
                                          float (&acc)[2][8][4]) {
    #pragma unroll
    for (int mt = 0; mt < 2; mt++) {
        int er = warp_m * 32 + mt * 16 + (lane >> 2);
        #pragma unroll
        for (int nt = 0; nt < 8; nt++) {
            int cb = warp_n * 64 + nt * 8 + (lane & 3) * 2;
            *(float2*)(sm + oM + (uint32_t)er * 528 + cb * 4) = make_float2(acc[mt][nt][0], acc[mt][nt][1]);
            *(float2*)(sm + oM + (uint32_t)(er + 8) * 528 + cb * 4) = make_float2(acc[mt][nt][2], acc[mt][nt][3]);
        }
    }
}

// ------------------- small kernels -------------------
__global__ void k_center_sum(const float* __restrict__ pos, const int* __restrict__ batch) {
    __shared__ float sb[Bb * 4];
    for (int i = threadIdx.x; i < Bb * 4; i += blockDim.x) sb[i] = 0.f;
    __syncthreads();
    for (int n = blockIdx.x * blockDim.x + threadIdx.x; n < Nn; n += gridDim.x * blockDim.x) {
        int b = batch[n];
        atomicAdd(&sb[b * 4 + 0], pos[n * 3 + 0]);
        atomicAdd(&sb[b * 4 + 1], pos[n * 3 + 1]);
        atomicAdd(&sb[b * 4 + 2], pos[n * 3 + 2]);
        atomicAdd(&sb[b * 4 + 3], 1.f);
    }
    __syncthreads();
    for (int i = threadIdx.x; i < Bb * 4; i += blockDim.x)
        if (sb[i] != 0.f) atomicAdd(&g_csum[i], sb[i]);
}

__global__ void k_center_fin() {
    int b = threadIdx.x;
    if (b < Bb) {
        float c = fmaxf(g_csum[b * 4 + 3], 1.f);
        g_center[b * 3 + 0] = g_csum[b * 4 + 0] / c;
        g_center[b * 3 + 1] = g_csum[b * 4 + 1] / c;
        g_center[b * 3 + 2] = g_csum[b * 4 + 2] / c;
    }
}

__global__ void k_dist(const int* __restrict__ eidx) {
    int e = blockIdx.x * blockDim.x + threadIdx.x;
    if (e >= Ee) return;
    int r = eidx[e], c = eidx[Ee + e];
    float dx = g_posrel[c * 3 + 0] - g_posrel[r * 3 + 0];
    float dy = g_posrel[c * 3 + 1] - g_posrel[r * 3 + 1];
    float dz = g_posrel[c * 3 + 2] - g_posrel[r * 3 + 2];
    g_dist[e] = sqrtf(dx * dx + dy * dy + dz * dz);
}

__global__ void k_deg(const int* __restrict__ row) {
    int e = blockIdx.x * blockDim.x + threadIdx.x;
    if (e < Ee) atomicAdd(&g_deg[row[e]], 1);
}

__global__ void k_invdeg() {
    int n = blockIdx.x * blockDim.x + threadIdx.x;
    if (n < Nn) g_invdeg[n] = 1.f / fmaxf((float)g_deg[n], 1.f);
}

// ------------------- weight prep (transposed, bf16 hi/lo) -------------------
__global__ void k_prep_w1(const float* __restrict__ mw1) {   // 3*256*128
    int idx = blockIdx.x * blockDim.x + threadIdx.x;
    if (idx >= 3 * 256 * 128) return;
    int l = idx >> 15, rem = idx & 32767;
    int n = rem >> 7, k = rem & 127;
    int kin = (n < 128) ? k : 128 + k;
    int j = (n < 128) ? n : n - 128;
    float v = mw1[l * 257 * 128 + kin * 128 + j];
    __nv_bfloat16 h = __float2bfloat16_rn(v);
    __nv_bfloat16 lo = __float2bfloat16_rn(v - __bfloat162float(h));
    g_w1t_hi[idx] = *(uint16_t*)&h;
    g_w1t_lo[idx] = *(uint16_t*)&lo;
}
__global__ void k_prep_w2(const float* __restrict__ mw2) {   // 3*128*128
    int idx = blockIdx.x * blockDim.x + threadIdx.x;
    if (idx >= 3 * 128 * 128) return;
    int l = idx >> 14, rem = idx & 16383;
    int n = rem >> 7, k = rem & 127;
    float v = mw2[l * 16384 + k * 128 + n];
    __nv_bfloat16 h = __float2bfloat16_rn(v);
    __nv_bfloat16 lo = __float2bfloat16_rn(v - __bfloat162float(h));
    g_w2t_hi[idx] = *(uint16_t*)&h;
    g_w2t_lo[idx] = *(uint16_t*)&lo;
}
__global__ void k_prep_u(const float* __restrict__ uw) {     // 3*128*256
    int idx = blockIdx.x * blockDim.x + threadIdx.x;
    if (idx >= 3 * 128 * 256) return;
    int l = idx >> 15, rem = idx & 32767;
    int n = rem >> 8, k = rem & 255;
    float v = uw[l * 32768 + k * 128 + n];
    __nv_bfloat16 h = __float2bfloat16_rn(v);
    __nv_bfloat16 lo = __float2bfloat16_rn(v - __bfloat162float(h));
    g_ut_hi[idx] = *(uint16_t*)&h;
    g_ut_lo[idx] = *(uint16_t*)&lo;
}

// split fp32 x -> bf16 hi/lo (after k_input). reads g_x0 internally (device symbol!)
__global__ void k_split_x() {
    int idx = blockIdx.x * blockDim.x + threadIdx.x;    // Nn*32
    if (idx >= Nn * 32) return;
    float4 v = ((const float4*)g_x0)[idx];
    uint32_t h01, l01, h23, l23;
    split2(v.x, v.y, h01, l01);
    split2(v.z, v.w, h23, l23);
    ((uint2*)g_xhi)[idx] = make_uint2(h01, h23);
    ((uint2*)g_xlo)[idx] = make_uint2(l01, l23);
}

// ------------------- input embedding + lin_in (SIMT, runs once) -------------------
__global__ void __launch_bounds__(128)
k_input(const float* __restrict__ pos, const int* __restrict__ z,
        const int* __restrict__ batch, const float* __restrict__ emb,
        const float* __restrict__ W, const float* __restrict__ bias) {
    __shared__ __align__(16) float fs[8 * 128];
    __shared__ float prs[8][3];
    int n0 = blockIdx.x * 8;
    int tid = threadIdx.x;
    if (tid < 8) {
        int n = n0 + tid;
        int b = batch[n];
        #pragma unroll
        for (int d = 0; d < 3; d++) {
            float v = pos[n * 3 + d] - g_center[b * 3 + d];
            prs[tid][d] = v;
            g_posrel[n * 3 + d] = v;
        }
    }
    #pragma unroll
    for (int e = 0; e < 8; e++)
        fs[e * 128 + tid] = emb[z[n0 + e] * 128 + tid];
    __syncthreads();

    int j = tid;
    const float* Wj = W + j;
    const float4* fs4 = (const float4*)fs;
    float acc[8];
    #pragma unroll
    for (int e = 0; e < 8; e++) acc[e] = 0.f;

    for (int kk = 0; kk < 32; kk++) {
        float w0 = Wj[(kk * 4 + 0) * 128];
        float w1 = Wj[(kk * 4 + 1) * 128];
        float w2 = Wj[(kk * 4 + 2) * 128];
        float w3 = Wj[(kk * 4 + 3) * 128];
        #pragma unroll
        for (int e = 0; e < 8; e++) {
            float4 xv = fs4[e * 32 + kk];
            acc[e] += xv.x * w0 + xv.y * w1 + xv.z * w2 + xv.w * w3;
        }
    }
    #pragma unroll
    for (int d = 0; d < 3; d++) {
        float w = Wj[(128 + d) * 128];
        #pragma unroll
        for (int e = 0; e < 8; e++) acc[e] += prs[e][d] * w;
    }
    float bj = bias[j];
    #pragma unroll
    for (int e = 0; e < 8; e++) g_x0[(n0 + e) * 128 + j] = acc[e] + bj;
}

// ------------------- node GEMM smem layout -------------------
#define GOFF_BIAS 0
#define GOFF_IDG  512
#define GOFF_AHI  1024
#define G_ASZ     34816            // 128 rows * 272B
#define GOFF_ALO  (GOFF_AHI + G_ASZ)
#define GOFF_BHI  (GOFF_ALO + G_ASZ)
#define GOFF_BLO  (GOFF_BHI + G_ASZ)
#define G_SMEM    (GOFF_BLO + G_ASZ)   // 140288

// ------------------- k_xab via HMMA: xa = x@W1a + b1 (y=0), xb = x@W1b (y=1) ----------
__global__ void __launch_bounds__(256, 1)
k_xab_mma(const float* __restrict__ b1, int layer) {
    extern __shared__ __align__(16) char sm[];
    uint32_t sbase = smem_u32(sm);
    int tid = threadIdx.x;
    int lane = tid & 31;
    int wid = tid >> 5;
    int n0 = blockIdx.x * 128;
    int half = blockIdx.y;
    float* bs = (float*)(sm + GOFF_BIAS);
    if (tid < 128) bs[tid] = (half == 0) ? b1[tid] : 0.f;

    // A = x hi/lo (copy), B = W1^T rows [half*128, half*128+128)
    const uint4* ah = (const uint4*)g_xhi + (size_t)n0 * 16;
    const uint4* al = (const uint4*)g_xlo + (size_t)n0 * 16;
    const uint4* bh = (const uint4*)(g_w1t_hi + layer * 256 * 128) + (size_t)half * 128 * 16;
    const uint4* bl = (const uint4*)(g_w1t_lo + layer * 256 * 128) + (size_t)half * 128 * 16;
    #pragma unroll
    for (int it = 0; it < 8; it++) {
        int cid = tid + it * 256;
        int r = cid >> 4, c = cid & 15;
        uint32_t o = (uint32_t)r * 272 + c * 16;
        *(uint4*)(sm + GOFF_AHI + o) = ah[r * 16 + c];
        *(uint4*)(sm + GOFF_ALO + o) = al[r * 16 + c];
        *(uint4*)(sm + GOFF_BHI + o) = bh[r * 16 + c];
        *(uint4*)(sm + GOFF_BLO + o) = bl[r * 16 + c];
    }
    __syncthreads();

    float acc[2][8][4];
    #pragma unroll
    for (int mt = 0; mt < 2; mt++)
        #pragma unroll
        for (int nt = 0; nt < 8; nt++)
            #pragma unroll
            for (int q = 0; q < 4; q++) acc[mt][nt][q] = 0.f;

    mma3_128(sbase, GOFF_AHI, GOFF_ALO, GOFF_BHI, GOFF_BLO, lane, wid & 3, wid >> 2, acc);
    __syncthreads();
    stage_acc(sm, GOFF_AHI, lane, wid & 3, wid >> 2, acc);
    __syncthreads();

    float* out = half == 0 ? g_xa : g_xb;
    #pragma unroll
    for (int it = 0; it < 16; it++) {
        int cid = tid + it * 256;
        int r = cid >> 5, c4 = cid & 31;
        float4 v = *(float4*)(sm + GOFF_AHI + (uint32_t)r * 528 + c4 * 16);
        v.x += bs[c4 * 4 + 0]; v.y += bs[c4 * 4 + 1];
        v.z += bs[c4 * 4 + 2]; v.w += bs[c4 * 4 + 3];
        ((float4*)(out + (size_t)(n0 + r) * 128))[c4] = v;
    }
}

// ------------------- k_update via HMMA: x' = relu([x, msum*invdeg] @ U + b) -----------
__global__ void __launch_bounds__(256, 1)
k_update_mma(const float* __restrict__ bias, int layer) {
    extern __shared__ __align__(16) char sm[];
    uint32_t sbase = smem_u32(sm);
    int tid = threadIdx.x;
    int lane = tid & 31;
    int wid = tid >> 5;
    int n0 = blockIdx.x * 128;
    float* bs = (float*)(sm + GOFF_BIAS);
    float* idg = (float*)(sm + GOFF_IDG);
    if (tid < 128) {
        bs[tid] = bias[tid];
        idg[tid] = g_invdeg[n0 + tid];
    }

    const uint16_t* ut_hi = g_ut_hi + layer * 128 * 256;
    const uint16_t* ut_lo = g_ut_lo + layer * 128 * 256;

    float acc[2][8][4];
    #pragma unroll
    for (int mt = 0; mt < 2; mt++)
        #pragma unroll
        for (int nt = 0; nt < 8; nt++)
            #pragma unroll
            for (int q = 0; q < 4; q++) acc[mt][nt][q] = 0.f;

    // ---- pass 0: A = x hi/lo (copy), B = U^T k[0:128)
    {
        const uint4* ah = (const uint4*)g_xhi + (size_t)n0 * 16;
        const uint4* al = (const uint4*)g_xlo + (size_t)n0 * 16;
        const uint4* bh = (const uint4*)ut_hi;
        const uint4* bl = (const uint4*)ut_lo;
        #pragma unroll
        for (int it = 0; it < 8; it++) {
            int cid = tid + it * 256;
            int r = cid >> 4, c = cid & 15;
            uint32_t o = (uint32_t)r * 272 + c * 16;
            *(uint4*)(sm + GOFF_AHI + o) = ah[r * 16 + c];
            *(uint4*)(sm + GOFF_ALO + o) = al[r * 16 + c];
            *(uint4*)(sm + GOFF_BHI + o) = bh[r * 32 + c];
            *(uint4*)(sm + GOFF_BLO + o) = bl[r * 32 + c];
        }
        __syncthreads();
        mma3_128(sbase, GOFF_AHI, GOFF_ALO, GOFF_BHI, GOFF_BLO, lane, wid & 3, wid >> 2, acc);
        __syncthreads();
    }
    // ---- pass 1: A = msum*invdeg (convert+split), B = U^T k[128:256)
    {
        const uint4* bh = (const uint4*)ut_hi;
        const uint4* bl = (const uint4*)ut_lo;
        #pragma unroll
        for (int it = 0; it < 8; it++) {
            int cid = tid + it * 256;
            int r = cid >> 4, c = cid & 15;
            uint32_t o = (uint32_t)r * 272 + c * 16;
            const float4* mp = (const float4*)(g_msum + (size_t)(n0 + r) * 128) + c * 2;
            float s = idg[r];
            float4 m0 = mp[0], m1 = mp[1];
            uint32_t h0, l0, h1, l1, h2, l2, h3, l3;
            split2(m0.x * s, m0.y * s, h0, l0);
            split2(m0.z * s, m0.w * s, h1, l1);
            split2(m1.x * s, m1.y * s, h2, l2);
            split2(m1.z * s, m1.w * s, h3, l3);
            *(uint4*)(sm + GOFF_AHI + o) = make_uint4(h0, h1, h2, h3);
            *(uint4*)(sm + GOFF_ALO + o) = make_uint4(l0, l1, l2, l3);
            *(uint4*)(sm + GOFF_BHI + o) = bh[r * 32 + 16 + c];
            *(uint4*)(sm + GOFF_BLO + o) = bl[r * 32 + 16 + c];
        }
        __syncthreads();
        mma3_128(sbase, GOFF_AHI, GOFF_ALO, GOFF_BHI, GOFF_BLO, lane, wid & 3, wid >> 2, acc);
        __syncthreads();
    }

    stage_acc(sm, GOFF_AHI, lane, wid & 3, wid >> 2, acc);
    __syncthreads();

    #pragma unroll
    for (int it = 0; it < 16; it++) {
        int cid = tid + it * 256;
        int r = cid >> 5, c4 = cid & 31;
        float4 v = *(float4*)(sm + GOFF_AHI + (uint32_t)r * 528 + c4 * 16);
        v.x = fmaxf(v.x + bs[c4 * 4 + 0], 0.f);
        v.y = fmaxf(v.y + bs[c4 * 4 + 1], 0.f);
        v.z = fmaxf(v.z + bs[c4 * 4 + 2], 0.f);
        v.w = fmaxf(v.w + bs[c4 * 4 + 3], 0.f);
        size_t nrow = (size_t)(n0 + r);
        ((float4*)(g_x0 + nrow * 128))[c4] = v;
        uint32_t h01, l01, h23, l23;
        split2(v.x, v.y, h01, l01);
        split2(v.z, v.w, h23, l23);
        ((uint2*)g_xhi)[nrow * 32 + c4] = make_uint2(h01, h23);
        ((uint2*)g_xlo)[nrow * 32 + c4] = make_uint2(l01, l23);
    }
}

// ------------------- HMMA edge kernel -------------------
#define EOFF_ROWS 0
#define EOFF_COLS 512
#define EOFF_DIST 1024
#define EOFF_BIAS 1536
#define EOFF_W1C  2048
#define EOFF_AHI  2560
#define E_ASZ     34816
#define EOFF_ALO  (EOFF_AHI + E_ASZ)
#define EOFF_BHI  (EOFF_ALO + E_ASZ)
#define EOFF_BLO  (EOFF_BHI + E_ASZ)
#define E_SMEM    (EOFF_BLO + E_ASZ)   // 141824

__global__ void __launch_bounds__(256, 1)
k_edge_mma(const int* __restrict__ row, const int* __restrict__ col,
           const float* __restrict__ w1c, const float* __restrict__ b2,
           const uint16_t* __restrict__ w2hi, const uint16_t* __restrict__ w2lo) {
    extern __shared__ __align__(16) char sm[];
    uint32_t sbase = smem_u32(sm);
    int tid = threadIdx.x;
    int lane = tid & 31;
    int wid = tid >> 5;
    int e0 = blockIdx.x * 128;

    int*   rows = (int*)(sm + EOFF_ROWS);
    int*   cols = (int*)(sm + EOFF_COLS);
    float* ds   = (float*)(sm + EOFF_DIST);
    float* bs   = (float*)(sm + EOFF_BIAS);
    float* ws   = (float*)(sm + EOFF_W1C);

    if (tid < 128) {
        rows[tid] = row[e0 + tid];
        cols[tid] = col[e0 + tid];
        ds[tid]   = g_dist[e0 + tid];
        bs[tid]   = b2[tid];
        ws[tid]   = w1c[tid];
    }

    {
        const uint4* bh = (const uint4*)w2hi;
        const uint4* bl = (const uint4*)w2lo;
        #pragma unroll
        for (int it = 0; it < 8; it++) {
            int i = tid + it * 256;
            int r = i >> 4, c = i & 15;
            uint32_t o = (uint32_t)r * 272 + c * 16;
            *(uint4*)(sm + EOFF_BHI + o) = bh[i];
            *(uint4*)(sm + EOFF_BLO + o) = bl[i];
        }
    }
    __syncthreads();

    // build A (h) tiles: h = relu(xa[col] + xb[row] + dist*w1c), split hi/lo
    #pragma unroll
    for (int it = 0; it < 8; it++) {
        int cid = tid + it * 256;
        int e = cid >> 4;
        int kc = cid & 15;
        const float4* pa = (const float4*)(g_xa + (size_t)cols[e] * 128) + kc * 2;
        const float4* pb = (const float4*)(g_xb + (size_t)rows[e] * 128) + kc * 2;
        float d = ds[e];
        float4 a0 = pa[0], a1 = pa[1];
        float4 b0 = pb[0], b1 = pb[1];
        int k0 = kc * 8;
        float v0 = fmaxf(a0.x + b0.x + d * ws[k0 + 0], 0.f);
        float v1 = fmaxf(a0.y + b0.y + d * ws[k0 + 1], 0.f);
        float v2 = fmaxf(a0.z + b0.z + d * ws[k0 + 2], 0.f);
        float v3 = fmaxf(a0.w + b0.w + d * ws[k0 + 3], 0.f);
        float v4 = fmaxf(a1.x + b1.x + d * ws[k0 + 4], 0.f);
        float v5 = fmaxf(a1.y + b1.y + d * ws[k0 + 5], 0.f);
        float v6 = fmaxf(a1.z + b1.z + d * ws[k0 + 6], 0.f);
        float v7 = fmaxf(a1.w + b1.w + d * ws[k0 + 7], 0.f);
        uint32_t h0, l0, h1, l1, h2, l2, h3, l3;
        split2(v0, v1, h0, l0);
        split2(v2, v3, h1, l1);
        split2(v4, v5, h2, l2);
        split2(v6, v7, h3, l3);
        uint32_t o = (uint32_t)e * 272 + kc * 16;
        *(uint4*)(sm + EOFF_AHI + o) = make_uint4(h0, h1, h2, h3);
        *(uint4*)(sm + EOFF_ALO + o) = make_uint4(l0, l1, l2, l3);
    }
    __syncthreads();

    float acc[2][8][4];
    #pragma unroll
    for (int mt = 0; mt < 2; mt++)
        #pragma unroll
        for (int nt = 0; nt < 8; nt++)
            #pragma unroll
            for (int q = 0; q < 4; q++) acc[mt][nt][q] = 0.f;

    mma3_128(sbase, EOFF_AHI, EOFF_ALO, EOFF_BHI, EOFF_BLO, lane, wid & 3, wid >> 2, acc);
    __syncthreads();
    stage_acc(sm, EOFF_AHI, lane, wid & 3, wid >> 2, acc);
    __syncthreads();

    // coalesced epilogue: bias + relu + red.global.add.v4
    #pragma unroll
    for (int it = 0; it < 16; it++) {
        int cid = tid + it * 256;
        int r = cid >> 5, c4 = cid & 31;
        float4 v = *(float4*)(sm + EOFF_AHI + (uint32_t)r * 528 + c4 * 16);
        float4 bb = *(float4*)(bs + c4 * 4);
        float m0 = fmaxf(v.x + bb.x, 0.f);
        float m1 = fmaxf(v.y + bb.y, 0.f);
        float m2 = fmaxf(v.z + bb.z, 0.f);
        float m3 = fmaxf(v.w + bb.w, 0.f);
        float* p = g_msum + (size_t)rows[r] * 128 + c4 * 4;
        asm volatile("red.global.add.v4.f32 [%0], {%1,%2,%3,%4};"
                     :: "l"(p), "f"(m0), "f"(m1), "f"(m2), "f"(m3) : "memory");
    }
}

// ------------------- readout pooling (reads g_x0 internally) -------------------
__global__ void k_pool(const int* __restrict__ batch, const int* __restrict__ ntype) {
    int idx = blockIdx.x * blockDim.x + threadIdx.x;
    int n = idx >> 5;
    int q = idx & 31;
    if (n >= Nn) return;
    if (ntype[n] == 1) {
        float4 v = ((const float4*)g_x0)[n * 32 + q];
        float* p = &g_gsum[batch[n] * 128 + q * 4];
        asm volatile("red.global.add.v4.f32 [%0], {%1,%2,%3,%4};"
                     :: "l"(p), "f"(v.x), "f"(v.y), "f"(v.z), "f"(v.w) : "memory");
    }
}

__global__ void k_ligcnt(const int* __restrict__ batch, const int* __restrict__ ntype) {
    int n = blockIdx.x * blockDim.x + threadIdx.x;
    if (n < Nn && ntype[n] == 1) atomicAdd(&g_ligcnt[batch[n]], 1.f);
}

__global__ void __launch_bounds__(128)
k_readout(const float* __restrict__ rw1, const float* __restrict__ rb1,
          const float* __restrict__ rw2, const float* __restrict__ rb2,
          float* __restrict__ out) {
    __shared__ __align__(16) float gs[128];
    __shared__ float red_s[128];
    int b = blockIdx.x;
    int tid = threadIdx.x;
    float cnt = fmaxf(g_ligcnt[b], 1.f);
    gs[tid] = g_gsum[b * 128 + tid] / cnt;
    __syncthreads();

    int j = tid;
    const float* Wj = rw1 + j;
    const float4* gs4 = (const float4*)gs;
    float acc = rb1[j];
    for (int kk = 0; kk < 32; kk++) {
        float w0 = Wj[(kk * 4 + 0) * 128];
        float w1 = Wj[(kk * 4 + 1) * 128];
        float w2 = Wj[(kk * 4 + 2) * 128];
        float w3 = Wj[(kk * 4 + 3) * 128];
        float4 gv = gs4[kk];
        acc += gv.x * w0 + gv.y * w1 + gv.z * w2 + gv.w * w3;
    }
    float hg = fmaxf(acc, 0.f);
    red_s[tid] = hg * rw2[j];
    __syncthreads();
    for (int s = 64; s > 0; s >>= 1) {
        if (tid < s) red_s[tid] += red_s[tid + s];
        __syncthreads();
    }
    if (tid == 0) out[b] = red_s[0] + rb2[0];
}

// ------------------- launch -------------------
extern "C" void kernel_launch(void* const* d_in, const int* in_sizes, int n_in,
                              void* d_out, int out_size) {
    const float* pos   = (const float*)d_in[0];
    const int*   z     = (const int*)d_in[1];
    const int*   batch = (const int*)d_in[2];
    const int*   eidx  = (const int*)d_in[3];
    const int*   ntype = (const int*)d_in[4];
    const float* emb   = (const float*)d_in[5];
    const float* lin_w = (const float*)d_in[6];
    const float* lin_b = (const float*)d_in[7];
    const float* mw1   = (const float*)d_in[8];
    const float* mb1   = (const float*)d_in[9];
    const float* mw2   = (const float*)d_in[10];
    const float* mb2   = (const float*)d_in[11];
    const float* uw    = (const float*)d_in[12];
    const float* ub    = (const float*)d_in[13];
    const float* rw1   = (const float*)d_in[14];
    const float* rb1   = (const float*)d_in[15];
    const float* rw2   = (const float*)d_in[16];
    const float* rb2   = (const float*)d_in[17];
    float* out = (float*)d_out;
    const int* row = eidx;
    const int* col = eidx + Ee;

    cudaFuncSetAttribute(k_edge_mma, cudaFuncAttributeMaxDynamicSharedMemorySize, E_SMEM);
    cudaFuncSetAttribute(k_xab_mma, cudaFuncAttributeMaxDynamicSharedMemorySize, G_SMEM);
    cudaFuncSetAttribute(k_update_mma, cudaFuncAttributeMaxDynamicSharedMemorySize, G_SMEM);

    void *p_csum, *p_deg, *p_msum, *p_gsum, *p_lig, *p_w2hi, *p_w2lo;
    cudaGetSymbolAddress(&p_csum, g_csum);
    cudaGetSymbolAddress(&p_deg, g_deg);
    cudaGetSymbolAddress(&p_msum, g_msum);
    cudaGetSymbolAddress(&p_gsum, g_gsum);
    cudaGetSymbolAddress(&p_lig, g_ligcnt);
    cudaGetSymbolAddress(&p_w2hi, g_w2t_hi);
    cudaGetSymbolAddress(&p_w2lo, g_w2t_lo);

    cudaMemsetAsync(p_csum, 0, Bb * 4 * sizeof(float));
    cudaMemsetAsync(p_deg, 0, Nn * sizeof(int));
    cudaMemsetAsync(p_gsum, 0, Bb * Hh * sizeof(float));
    cudaMemsetAsync(p_lig, 0, Bb * sizeof(float));

    // weight preps (all layers at once)
    k_prep_w1<<<(3 * 256 * 128) / 256, 256>>>(mw1);
    k_prep_w2<<<(3 * 128 * 128) / 256, 256>>>(mw2);
    k_prep_u<<<(3 * 128 * 256) / 256, 256>>>(uw);

    k_center_sum<<<128, 256>>>(pos, batch);
    k_center_fin<<<1, 64>>>();
    k_input<<<Nn / 8, 128>>>(pos, z, batch, emb, lin_w, lin_b);
    k_split_x<<<Nn * 32 / 256, 256>>>();
    k_dist<<<Ee / 256, 256>>>(eidx);
    k_deg<<<Ee / 256, 256>>>(row);
    k_invdeg<<<Nn / 256, 256>>>();

    for (int l = 0; l < 3; l++) {
        const float* W1 = mw1 + l * 257 * 128;
        k_xab_mma<<<dim3(Nn / 128, 2), 256, G_SMEM>>>(mb1 + l * 128, l);
        cudaMemsetAsync(p_msum, 0, (size_t)Nn * Hh * sizeof(float));
        k_edge_mma<<<Ee / 128, 256, E_SMEM>>>(row, col, W1 + 256 * 128, mb2 + l * 128,
                                              (const uint16_t*)p_w2hi + l * 16384,
                                              (const uint16_t*)p_w2lo + l * 16384);
        k_update_mma<<<Nn / 128, 256, G_SMEM>>>(ub + l * 128, l);
    }

    k_pool<<<Nn * 32 / 256, 256>>>(batch, ntype);
    k_ligcnt<<<Nn / 256, 256>>>(batch, ntype);
    k_readout<<<Bb, 128>>>(rw1, rb1, rw2, rb2, out);
}

// round 7
// speedup vs baseline: 2.2592x; 1.1714x over previous
#include <cuda_runtime.h>
#include <cuda_bf16.h>
#include <math.h>
#include <stdint.h>

#define Nn 65536
#define Ee 1048576
#define Bb 64
#define Hh 128

// ------------------- scratch (static device globals; no allocation) -------------------
__device__ float g_csum[Bb * 4];
__device__ float g_center[Bb * 3];
__device__ float g_posrel[Nn * 3];
__device__ float g_x0[Nn * Hh];           // fp32 node features
__device__ uint32_t g_xhi[Nn * 64];       // bf16x2-packed hi split of x
__device__ uint32_t g_xlo[Nn * 64];       // bf16x2-packed lo split of x
__device__ float g_xa[Nn * Hh];           // x @ W1a + b1  (gathered at col)
__device__ float g_xb[Nn * Hh];           // x @ W1b       (gathered at row)
__device__ float g_msum[Nn * Hh];         // scatter-add of m_ij at row
__device__ float g_dist[Ee];
__device__ int   g_deg[Nn];
__device__ float g_invdeg[Nn];
__device__ float g_gsum[Bb * Hh];
__device__ float g_ligcnt[Bb];
// prepped transposed weights, bf16 hi/lo, [out][k] row-major
__device__ uint16_t g_w1t_hi[3 * 256 * 128], g_w1t_lo[3 * 256 * 128];
__device__ uint16_t g_w2t_hi[3 * 128 * 128], g_w2t_lo[3 * 128 * 128];
__device__ uint16_t g_ut_hi[3 * 128 * 256], g_ut_lo[3 * 128 * 256];
__device__ uint16_t g_lint_hi[128 * 128], g_lint_lo[128 * 128];

// ------------------- helpers -------------------
__device__ __forceinline__ uint32_t smem_u32(const void* p) {
    uint32_t a;
    asm("{ .reg .u64 t; cvta.to.shared.u64 t, %1; cvt.u32.u64 %0, t; }" : "=r"(a) : "l"(p));
    return a;
}
__device__ __forceinline__ void ldsm_x4(uint32_t* r, uint32_t addr) {
    asm volatile("ldmatrix.sync.aligned.m8n8.x4.shared.b16 {%0,%1,%2,%3}, [%4];"
                 : "=r"(r[0]), "=r"(r[1]), "=r"(r[2]), "=r"(r[3]) : "r"(addr));
}
__device__ __forceinline__ void ldsm_x2(uint32_t* r, uint32_t addr) {
    asm volatile("ldmatrix.sync.aligned.m8n8.x2.shared.b16 {%0,%1}, [%2];"
                 : "=r"(r[0]), "=r"(r[1]) : "r"(addr));
}
__device__ __forceinline__ void mma_bf16(float* d, const uint32_t* a, const uint32_t* b) {
    asm volatile("mma.sync.aligned.m16n8k16.row.col.f32.bf16.bf16.f32 "
                 "{%0,%1,%2,%3}, {%4,%5,%6,%7}, {%8,%9}, {%0,%1,%2,%3};"
                 : "+f"(d[0]), "+f"(d[1]), "+f"(d[2]), "+f"(d[3])
                 : "r"(a[0]), "r"(a[1]), "r"(a[2]), "r"(a[3]), "r"(b[0]), "r"(b[1]));
}
__device__ __forceinline__ void split2(float v0, float v1, uint32_t& hi, uint32_t& lo) {
    __nv_bfloat162 h = __floats2bfloat162_rn(v0, v1);
    uint32_t hu = *(uint32_t*)&h;
    float h0 = __uint_as_float(hu << 16);
    float h1 = __uint_as_float(hu & 0xFFFF0000u);
    __nv_bfloat162 l = __floats2bfloat162_rn(v0 - h0, v1 - h1);
    hi = hu; lo = *(uint32_t*)&l;
}

// 3-term MMA core, 16 warps, warp tile m32 x n32: D(128x128) += Ahi*Bhi + Alo*Bhi + Ahi*Blo
// A,B in smem: 128 rows x 256B data, 272B stride.
__device__ __forceinline__ void mma3_128(uint32_t sbase, uint32_t oAhi, uint32_t oAlo,
                                         uint32_t oBhi, uint32_t oBlo,
                                         int lane, int warp_m, int warp_n,
                                         float (&acc)[2][4][4]) {
    uint32_t a_base = sbase + oAhi + (uint32_t)(warp_m * 32 + (lane & 15)) * 272 + (uint32_t)(lane >> 4) * 16;
    uint32_t b_base = sbase + oBhi + (uint32_t)(warp_n * 32 + (lane & 7)) * 272 + (uint32_t)((lane >> 3) & 1) * 16;
    uint32_t dA = oAlo - oAhi, dB = oBlo - oBhi;
    for (int ks = 0; ks < 8; ks++) {
        uint32_t kb = (uint32_t)ks * 32;
        uint32_t a_hi[2][4], a_lo[2][4];
        #pragma unroll
        for (int mt = 0; mt < 2; mt++) {
            uint32_t ad = a_base + (uint32_t)(mt * 16) * 272 + kb;
            ldsm_x4(a_hi[mt], ad);
            ldsm_x4(a_lo[mt], ad + dA);
        }
        uint32_t b_hi[4][2], b_lo[4][2];
        #pragma unroll
        for (int nt = 0; nt < 4; nt++) {
            uint32_t bd = b_base + (uint32_t)(nt * 8) * 272 + kb;
            ldsm_x2(b_hi[nt], bd);
            ldsm_x2(b_lo[nt], bd + dB);
        }
        #pragma unroll
        for (int mt = 0; mt < 2; mt++)
            #pragma unroll
            for (int nt = 0; nt < 4; nt++)
                mma_bf16(acc[mt][nt], a_hi[mt], b_hi[nt]);
        #pragma unroll
        for (int mt = 0; mt < 2; mt++)
            #pragma unroll
            for (int nt = 0; nt < 4; nt++)
                mma_bf16(acc[mt][nt], a_lo[mt], b_hi[nt]);
        #pragma unroll
        for (int mt = 0; mt < 2; mt++)
            #pragma unroll
            for (int nt = 0; nt < 4; nt++)
                mma_bf16(acc[mt][nt], a_hi[mt], b_lo[nt]);
    }
}

// stage fragments into smem m-buffer (stride 528B) for coalesced epilogue
__device__ __forceinline__ void stage_acc(char* sm, uint32_t oM, int lane, int warp_m, int warp_n,
                                          float (&acc)[2][4][4]) {
    #pragma unroll
    for (int mt = 0; mt < 2; mt++) {
        int er = warp_m * 32 + mt * 16 + (lane >> 2);
        #pragma unroll
        for (int nt = 0; nt < 4; nt++) {
            int cb = warp_n * 32 + nt * 8 + (lane & 3) * 2;
            *(float2*)(sm + oM + (uint32_t)er * 528 + cb * 4) = make_float2(acc[mt][nt][0], acc[mt][nt][1]);
            *(float2*)(sm + oM + (uint32_t)(er + 8) * 528 + cb * 4) = make_float2(acc[mt][nt][2], acc[mt][nt][3]);
        }
    }
}

// ------------------- small kernels -------------------
// sorted batch -> contiguous warp segments: segmented shuffle reduce, leaders atomic to global
__global__ void k_center_sum(const float* __restrict__ pos, const int* __restrict__ batch) {
    int n = blockIdx.x * blockDim.x + threadIdx.x;
    if (n >= Nn) return;
    int lane = threadIdx.x & 31;
    int b = batch[n];
    float px = pos[n * 3 + 0], py = pos[n * 3 + 1], pz = pos[n * 3 + 2], pc = 1.f;
    #pragma unroll
    for (int off = 1; off < 32; off <<= 1) {
        int bs = __shfl_down_sync(0xffffffffu, b, off);
        float tx = __shfl_down_sync(0xffffffffu, px, off);
        float ty = __shfl_down_sync(0xffffffffu, py, off);
        float tz = __shfl_down_sync(0xffffffffu, pz, off);
        float tc = __shfl_down_sync(0xffffffffu, pc, off);
        if (lane + off < 32 && bs == b) { px += tx; py += ty; pz += tz; pc += tc; }
    }
    int bprev = __shfl_up_sync(0xffffffffu, b, 1);
    if (lane == 0 || bprev != b) {
        atomicAdd(&g_csum[b * 4 + 0], px);
        atomicAdd(&g_csum[b * 4 + 1], py);
        atomicAdd(&g_csum[b * 4 + 2], pz);
        atomicAdd(&g_csum[b * 4 + 3], pc);
    }
}

__global__ void k_center_fin() {
    int b = threadIdx.x;
    if (b < Bb) {
        float c = fmaxf(g_csum[b * 4 + 3], 1.f);
        g_center[b * 3 + 0] = g_csum[b * 4 + 0] / c;
        g_center[b * 3 + 1] = g_csum[b * 4 + 1] / c;
        g_center[b * 3 + 2] = g_csum[b * 4 + 2] / c;
    }
}

// dist + degree in one pass
__global__ void k_dist_deg(const int* __restrict__ eidx) {
    int e = blockIdx.x * blockDim.x + threadIdx.x;
    if (e >= Ee) return;
    int r = eidx[e], c = eidx[Ee + e];
    float dx = g_posrel[c * 3 + 0] - g_posrel[r * 3 + 0];
    float dy = g_posrel[c * 3 + 1] - g_posrel[r * 3 + 1];
    float dz = g_posrel[c * 3 + 2] - g_posrel[r * 3 + 2];
    g_dist[e] = sqrtf(dx * dx + dy * dy + dz * dz);
    atomicAdd(&g_deg[r], 1);
}

__global__ void k_invdeg() {
    int n = blockIdx.x * blockDim.x + threadIdx.x;
    if (n < Nn) g_invdeg[n] = 1.f / fmaxf((float)g_deg[n], 1.f);
}

// ------------------- weight prep (transposed, bf16 hi/lo) -------------------
__global__ void k_prep_w1(const float* __restrict__ mw1) {   // 3*256*128
    int idx = blockIdx.x * blockDim.x + threadIdx.x;
    if (idx >= 3 * 256 * 128) return;
    int l = idx >> 15, rem = idx & 32767;
    int n = rem >> 7, k = rem & 127;
    int kin = (n < 128) ? k : 128 + k;
    int j = (n < 128) ? n : n - 128;
    float v = mw1[l * 257 * 128 + kin * 128 + j];
    __nv_bfloat16 h = __float2bfloat16_rn(v);
    __nv_bfloat16 lo = __float2bfloat16_rn(v - __bfloat162float(h));
    g_w1t_hi[idx] = *(uint16_t*)&h;
    g_w1t_lo[idx] = *(uint16_t*)&lo;
}
__global__ void k_prep_w2(const float* __restrict__ mw2) {   // 3*128*128
    int idx = blockIdx.x * blockDim.x + threadIdx.x;
    if (idx >= 3 * 128 * 128) return;
    int l = idx >> 14, rem = idx & 16383;
    int n = rem >> 7, k = rem & 127;
    float v = mw2[l * 16384 + k * 128 + n];
    __nv_bfloat16 h = __float2bfloat16_rn(v);
    __nv_bfloat16 lo = __float2bfloat16_rn(v - __bfloat162float(h));
    g_w2t_hi[idx] = *(uint16_t*)&h;
    g_w2t_lo[idx] = *(uint16_t*)&lo;
}
__global__ void k_prep_u(const float* __restrict__ uw) {     // 3*128*256
    int idx = blockIdx.x * blockDim.x + threadIdx.x;
    if (idx >= 3 * 128 * 256) return;
    int l = idx >> 15, rem = idx & 32767;
    int n = rem >> 8, k = rem & 255;
    float v = uw[l * 32768 + k * 128 + n];
    __nv_bfloat16 h = __float2bfloat16_rn(v);
    __nv_bfloat16 lo = __float2bfloat16_rn(v - __bfloat162float(h));
    g_ut_hi[idx] = *(uint16_t*)&h;
    g_ut_lo[idx] = *(uint16_t*)&lo;
}
__global__ void k_prep_lin(const float* __restrict__ lin_w) {  // 128*128 (first 128 k-rows)
    int idx = blockIdx.x * blockDim.x + threadIdx.x;
    if (idx >= 128 * 128) return;
    int n = idx >> 7, k = idx & 127;
    float v = lin_w[k * 128 + n];
    __nv_bfloat16 h = __float2bfloat16_rn(v);
    __nv_bfloat16 lo = __float2bfloat16_rn(v - __bfloat162float(h));
    g_lint_hi[idx] = *(uint16_t*)&h;
    g_lint_lo[idx] = *(uint16_t*)&lo;
}

// ------------------- shared smem layout for 128x128 GEMM kernels -------------------
#define GOFF_BIAS 0        // 512B
#define GOFF_AUX  512      // 1536B  (idg / tail weights)
#define GOFF_IDX  2048     // 2048B  (node/edge indices: up to 512 ints)
#define GOFF_AHI  4096
#define G_ASZ     34816    // 128 rows * 272B
#define GOFF_ALO  (GOFF_AHI + G_ASZ)
#define GOFF_BHI  (GOFF_ALO + G_ASZ)
#define GOFF_BLO  (GOFF_BHI + G_ASZ)
#define G_SMEM    (GOFF_BLO + G_ASZ)   // 143360

// ------------------- k_input via HMMA: x0 = [emb[z], posrel] @ W + b (fuses split) ----
__global__ void __launch_bounds__(512, 1)
k_input_mma(const float* __restrict__ pos, const int* __restrict__ z,
            const int* __restrict__ batch, const float* __restrict__ emb,
            const float* __restrict__ lin_w, const float* __restrict__ bias) {
    extern __shared__ __align__(16) char sm[];
    uint32_t sbase = smem_u32(sm);
    int tid = threadIdx.x;
    int lane = tid & 31;
    int wid = tid >> 5;
    int n0 = blockIdx.x * 128;
    float* bs  = (float*)(sm + GOFF_BIAS);
    float* tl  = (float*)(sm + GOFF_AUX);       // 3 x 128 tail weights
    float* prs = (float*)(sm + GOFF_IDX);       // 128 x 3 posrel  (1536B <= 2048)
    int*   zs  = (int*)(sm + GOFF_IDX + 1536);  // 128 ints (512B) -> fits in IDX region

    if (tid < 128) {
        bs[tid] = bias[tid];
        int n = n0 + tid;
        int b = batch[n];
        #pragma unroll
        for (int d = 0; d < 3; d++) {
            float v = pos[n * 3 + d] - g_center[b * 3 + d];
            prs[tid * 3 + d] = v;
            g_posrel[n * 3 + d] = v;
        }
        zs[tid] = z[n];
    } else if (tid < 512 && tid >= 128 && tid < 128 + 384) {
        int i = tid - 128;   // 0..383 -> tail weights 3*128
        tl[i] = lin_w[(128 + (i >> 7)) * 128 + (i & 127)];
    }

    // B tile copy (prepped lin^T)
    {
        const uint4* bh = (const uint4*)g_lint_hi;
        const uint4* bl = (const uint4*)g_lint_lo;
        #pragma unroll
        for (int it = 0; it < 4; it++) {
            int i = tid + it * 512;
            int r = i >> 4, c = i & 15;
            uint32_t o = (uint32_t)r * 272 + c * 16;
            *(uint4*)(sm + GOFF_BHI + o) = bh[i];
            *(uint4*)(sm + GOFF_BLO + o) = bl[i];
        }
    }
    __syncthreads();

    // A build: gather emb rows, split
    #pragma unroll
    for (int it = 0; it < 4; it++) {
        int cid = tid + it * 512;
        int r = cid >> 4, kc = cid & 15;
        const float4* ep = (const float4*)(emb + (size_t)zs[r] * 128) + kc * 2;
        float4 e0 = ep[0], e1 = ep[1];
        uint32_t h0, l0, h1, l1, h2, l2, h3, l3;
        split2(e0.x, e0.y, h0, l0);
        split2(e0.z, e0.w, h1, l1);
        split2(e1.x, e1.y, h2, l2);
        split2(e1.z, e1.w, h3, l3);
        uint32_t o = (uint32_t)r * 272 + kc * 16;
        *(uint4*)(sm + GOFF_AHI + o) = make_uint4(h0, h1, h2, h3);
        *(uint4*)(sm + GOFF_ALO + o) = make_uint4(l0, l1, l2, l3);
    }
    __syncthreads();

    float acc[2][4][4];
    #pragma unroll
    for (int mt = 0; mt < 2; mt++)
        #pragma unroll
        for (int nt = 0; nt < 4; nt++)
            #pragma unroll
            for (int q = 0; q < 4; q++) acc[mt][nt][q] = 0.f;
    mma3_128(sbase, GOFF_AHI, GOFF_ALO, GOFF_BHI, GOFF_BLO, lane, wid & 3, wid >> 2, acc);
    __syncthreads();
    stage_acc(sm, GOFF_AHI, lane, wid & 3, wid >> 2, acc);
    __syncthreads();

    #pragma unroll
    for (int it = 0; it < 8; it++) {
        int cid = tid + it * 512;
        int r = cid >> 5, c4 = cid & 31;
        float4 v = *(float4*)(sm + GOFF_AHI + (uint32_t)r * 528 + c4 * 16);
        float p0 = prs[r * 3 + 0], p1 = prs[r * 3 + 1], p2 = prs[r * 3 + 2];
        int c = c4 * 4;
        v.x += bs[c + 0] + p0 * tl[c + 0] + p1 * tl[128 + c + 0] + p2 * tl[256 + c + 0];
        v.y += bs[c + 1] + p0 * tl[c + 1] + p1 * tl[128 + c + 1] + p2 * tl[256 + c + 1];
        v.z += bs[c + 2] + p0 * tl[c + 2] + p1 * tl[128 + c + 2] + p2 * tl[256 + c + 2];
        v.w += bs[c + 3] + p0 * tl[c + 3] + p1 * tl[128 + c + 3] + p2 * tl[256 + c + 3];
        size_t nrow = (size_t)(n0 + r);
        ((float4*)(g_x0 + nrow * 128))[c4] = v;
        uint32_t h01, l01, h23, l23;
        split2(v.x, v.y, h01, l01);
        split2(v.z, v.w, h23, l23);
        ((uint2*)g_xhi)[nrow * 32 + c4] = make_uint2(h01, h23);
        ((uint2*)g_xlo)[nrow * 32 + c4] = make_uint2(l01, l23);
    }
}

// ------------------- k_xab via HMMA: xa = x@W1a + b1 (y=0), xb = x@W1b (y=1) ----------
__global__ void __launch_bounds__(512, 1)
k_xab_mma(const float* __restrict__ b1, int layer) {
    extern __shared__ __align__(16) char sm[];
    uint32_t sbase = smem_u32(sm);
    int tid = threadIdx.x;
    int lane = tid & 31;
    int wid = tid >> 5;
    int n0 = blockIdx.x * 128;
    int half = blockIdx.y;
    float* bs = (float*)(sm + GOFF_BIAS);
    if (tid < 128) bs[tid] = (half == 0) ? b1[tid] : 0.f;

    const uint4* ah = (const uint4*)g_xhi + (size_t)n0 * 16;
    const uint4* al = (const uint4*)g_xlo + (size_t)n0 * 16;
    const uint4* bh = (const uint4*)(g_w1t_hi + layer * 256 * 128) + (size_t)half * 128 * 16;
    const uint4* bl = (const uint4*)(g_w1t_lo + layer * 256 * 128) + (size_t)half * 128 * 16;
    #pragma unroll
    for (int it = 0; it < 4; it++) {
        int cid = tid + it * 512;
        int r = cid >> 4, c = cid & 15;
        uint32_t o = (uint32_t)r * 272 + c * 16;
        *(uint4*)(sm + GOFF_AHI + o) = ah[r * 16 + c];
        *(uint4*)(sm + GOFF_ALO + o) = al[r * 16 + c];
        *(uint4*)(sm + GOFF_BHI + o) = bh[r * 16 + c];
        *(uint4*)(sm + GOFF_BLO + o) = bl[r * 16 + c];
    }
    __syncthreads();

    float acc[2][4][4];
    #pragma unroll
    for (int mt = 0; mt < 2; mt++)
        #pragma unroll
        for (int nt = 0; nt < 4; nt++)
            #pragma unroll
            for (int q = 0; q < 4; q++) acc[mt][nt][q] = 0.f;
    mma3_128(sbase, GOFF_AHI, GOFF_ALO, GOFF_BHI, GOFF_BLO, lane, wid & 3, wid >> 2, acc);
    __syncthreads();
    stage_acc(sm, GOFF_AHI, lane, wid & 3, wid >> 2, acc);
    __syncthreads();

    float* out = half == 0 ? g_xa : g_xb;
    #pragma unroll
    for (int it = 0; it < 8; it++) {
        int cid = tid + it * 512;
        int r = cid >> 5, c4 = cid & 31;
        float4 v = *(float4*)(sm + GOFF_AHI + (uint32_t)r * 528 + c4 * 16);
        v.x += bs[c4 * 4 + 0]; v.y += bs[c4 * 4 + 1];
        v.z += bs[c4 * 4 + 2]; v.w += bs[c4 * 4 + 3];
        ((float4*)(out + (size_t)(n0 + r) * 128))[c4] = v;
    }
}

// ------------------- k_update via HMMA: x' = relu([x, msum*invdeg] @ U + b) -----------
__global__ void __launch_bounds__(512, 1)
k_update_mma(const float* __restrict__ bias, int layer) {
    extern __shared__ __align__(16) char sm[];
    uint32_t sbase = smem_u32(sm);
    int tid = threadIdx.x;
    int lane = tid & 31;
    int wid = tid >> 5;
    int n0 = blockIdx.x * 128;
    float* bs = (float*)(sm + GOFF_BIAS);
    float* idg = (float*)(sm + GOFF_AUX);
    if (tid < 128) {
        bs[tid] = bias[tid];
        idg[tid] = g_invdeg[n0 + tid];
    }

    const uint16_t* ut_hi = g_ut_hi + layer * 128 * 256;
    const uint16_t* ut_lo = g_ut_lo + layer * 128 * 256;

    float acc[2][4][4];
    #pragma unroll
    for (int mt = 0; mt < 2; mt++)
        #pragma unroll
        for (int nt = 0; nt < 4; nt++)
            #pragma unroll
            for (int q = 0; q < 4; q++) acc[mt][nt][q] = 0.f;

    // pass 0: A = x hi/lo, B = U^T k[0:128)
    {
        const uint4* ah = (const uint4*)g_xhi + (size_t)n0 * 16;
        const uint4* al = (const uint4*)g_xlo + (size_t)n0 * 16;
        const uint4* bh = (const uint4*)ut_hi;
        const uint4* bl = (const uint4*)ut_lo;
        #pragma unroll
        for (int it = 0; it < 4; it++) {
            int cid = tid + it * 512;
            int r = cid >> 4, c = cid & 15;
            uint32_t o = (uint32_t)r * 272 + c * 16;
            *(uint4*)(sm + GOFF_AHI + o) = ah[r * 16 + c];
            *(uint4*)(sm + GOFF_ALO + o) = al[r * 16 + c];
            *(uint4*)(sm + GOFF_BHI + o) = bh[r * 32 + c];
            *(uint4*)(sm + GOFF_BLO + o) = bl[r * 32 + c];
        }
        __syncthreads();
        mma3_128(sbase, GOFF_AHI, GOFF_ALO, GOFF_BHI, GOFF_BLO, lane, wid & 3, wid >> 2, acc);
        __syncthreads();
    }
    // pass 1: A = msum*invdeg (convert+split), B = U^T k[128:256)
    {
        const uint4* bh = (const uint4*)ut_hi;
        const uint4* bl = (const uint4*)ut_lo;
        #pragma unroll
        for (int it = 0; it < 4; it++) {
            int cid = tid + it * 512;
            int r = cid >> 4, c = cid & 15;
            uint32_t o = (uint32_t)r * 272 + c * 16;
            const float4* mp = (const float4*)(g_msum + (size_t)(n0 + r) * 128) + c * 2;
            float s = idg[r];
            float4 m0 = mp[0], m1 = mp[1];
            uint32_t h0, l0, h1, l1, h2, l2, h3, l3;
            split2(m0.x * s, m0.y * s, h0, l0);
            split2(m0.z * s, m0.w * s, h1, l1);
            split2(m1.x * s, m1.y * s, h2, l2);
            split2(m1.z * s, m1.w * s, h3, l3);
            *(uint4*)(sm + GOFF_AHI + o) = make_uint4(h0, h1, h2, h3);
            *(uint4*)(sm + GOFF_ALO + o) = make_uint4(l0, l1, l2, l3);
            *(uint4*)(sm + GOFF_BHI + o) = bh[r * 32 + 16 + c];
            *(uint4*)(sm + GOFF_BLO + o) = bl[r * 32 + 16 + c];
        }
        __syncthreads();
        mma3_128(sbase, GOFF_AHI, GOFF_ALO, GOFF_BHI, GOFF_BLO, lane, wid & 3, wid >> 2, acc);
        __syncthreads();
    }

    stage_acc(sm, GOFF_AHI, lane, wid & 3, wid >> 2, acc);
    __syncthreads();

    #pragma unroll
    for (int it = 0; it < 8; it++) {
        int cid = tid + it * 512;
        int r = cid >> 5, c4 = cid & 31;
        float4 v = *(float4*)(sm + GOFF_AHI + (uint32_t)r * 528 + c4 * 16);
        v.x = fmaxf(v.x + bs[c4 * 4 + 0], 0.f);
        v.y = fmaxf(v.y + bs[c4 * 4 + 1], 0.f);
        v.z = fmaxf(v.z + bs[c4 * 4 + 2], 0.f);
        v.w = fmaxf(v.w + bs[c4 * 4 + 3], 0.f);
        size_t nrow = (size_t)(n0 + r);
        ((float4*)(g_x0 + nrow * 128))[c4] = v;
        uint32_t h01, l01, h23, l23;
        split2(v.x, v.y, h01, l01);
        split2(v.z, v.w, h23, l23);
        ((uint2*)g_xhi)[nrow * 32 + c4] = make_uint2(h01, h23);
        ((uint2*)g_xlo)[nrow * 32 + c4] = make_uint2(l01, l23);
    }
}

// ------------------- HMMA edge kernel (512 threads, 16 warps) -------------------
#define EOFF_ROWS 0
#define EOFF_COLS 512
#define EOFF_DIST 1024
#define EOFF_BIAS 1536
#define EOFF_W1C  2048
#define EOFF_AHI  2560
#define E_ASZ     34816
#define EOFF_ALO  (EOFF_AHI + E_ASZ)
#define EOFF_BHI  (EOFF_ALO + E_ASZ)
#define EOFF_BLO  (EOFF_BHI + E_ASZ)
#define E_SMEM    (EOFF_BLO + E_ASZ)   // 141824

__global__ void __launch_bounds__(512, 1)
k_edge_mma(const int* __restrict__ row, const int* __restrict__ col,
           const float* __restrict__ w1c, const float* __restrict__ b2,
           const uint16_t* __restrict__ w2hi, const uint16_t* __restrict__ w2lo) {
    extern __shared__ __align__(16) char sm[];
    uint32_t sbase = smem_u32(sm);
    int tid = threadIdx.x;
    int lane = tid & 31;
    int wid = tid >> 5;
    int e0 = blockIdx.x * 128;

    int*   rows = (int*)(sm + EOFF_ROWS);
    int*   cols = (int*)(sm + EOFF_COLS);
    float* ds   = (float*)(sm + EOFF_DIST);
    float* bs   = (float*)(sm + EOFF_BIAS);
    float* ws   = (float*)(sm + EOFF_W1C);

    if (tid < 128) {
        rows[tid] = row[e0 + tid];
        cols[tid] = col[e0 + tid];
        ds[tid]   = g_dist[e0 + tid];
        bs[tid]   = b2[tid];
        ws[tid]   = w1c[tid];
    }

    {
        const uint4* bh = (const uint4*)w2hi;
        const uint4* bl = (const uint4*)w2lo;
        #pragma unroll
        for (int it = 0; it < 4; it++) {
            int i = tid + it * 512;
            int r = i >> 4, c = i & 15;
            uint32_t o = (uint32_t)r * 272 + c * 16;
            *(uint4*)(sm + EOFF_BHI + o) = bh[i];
            *(uint4*)(sm + EOFF_BLO + o) = bl[i];
        }
    }
    __syncthreads();

    // A build: h = relu(xa[col] + xb[row] + dist*w1c), split hi/lo
    #pragma unroll
    for (int it = 0; it < 4; it++) {
        int cid = tid + it * 512;
        int e = cid >> 4;
        int kc = cid & 15;
        const float4* pa = (const float4*)(g_xa + (size_t)cols[e] * 128) + kc * 2;
        const float4* pb = (const float4*)(g_xb + (size_t)rows[e] * 128) + kc * 2;
        float d = ds[e];
        float4 a0 = pa[0], a1 = pa[1];
        float4 b0 = pb[0], b1 = pb[1];
        int k0 = kc * 8;
        float v0 = fmaxf(a0.x + b0.x + d * ws[k0 + 0], 0.f);
        float v1 = fmaxf(a0.y + b0.y + d * ws[k0 + 1], 0.f);
        float v2 = fmaxf(a0.z + b0.z + d * ws[k0 + 2], 0.f);
        float v3 = fmaxf(a0.w + b0.w + d * ws[k0 + 3], 0.f);
        float v4 = fmaxf(a1.x + b1.x + d * ws[k0 + 4], 0.f);
        float v5 = fmaxf(a1.y + b1.y + d * ws[k0 + 5], 0.f);
        float v6 = fmaxf(a1.z + b1.z + d * ws[k0 + 6], 0.f);
        float v7 = fmaxf(a1.w + b1.w + d * ws[k0 + 7], 0.f);
        uint32_t h0, l0, h1, l1, h2, l2, h3, l3;
        split2(v0, v1, h0, l0);
        split2(v2, v3, h1, l1);
        split2(v4, v5, h2, l2);
        split2(v6, v7, h3, l3);
        uint32_t o = (uint32_t)e * 272 + kc * 16;
        *(uint4*)(sm + EOFF_AHI + o) = make_uint4(h0, h1, h2, h3);
        *(uint4*)(sm + EOFF_ALO + o) = make_uint4(l0, l1, l2, l3);
    }
    __syncthreads();

    float acc[2][4][4];
    #pragma unroll
    for (int mt = 0; mt < 2; mt++)
        #pragma unroll
        for (int nt = 0; nt < 4; nt++)
            #pragma unroll
            for (int q = 0; q < 4; q++) acc[mt][nt][q] = 0.f;
    mma3_128(sbase, EOFF_AHI, EOFF_ALO, EOFF_BHI, EOFF_BLO, lane, wid & 3, wid >> 2, acc);
    __syncthreads();
    stage_acc(sm, EOFF_AHI, lane, wid & 3, wid >> 2, acc);
    __syncthreads();

    // coalesced epilogue: bias + relu + red.global.add.v4
    #pragma unroll
    for (int it = 0; it < 8; it++) {
        int cid = tid + it * 512;
        int r = cid >> 5, c4 = cid & 31;
        float4 v = *(float4*)(sm + EOFF_AHI + (uint32_t)r * 528 + c4 * 16);
        float4 bb = *(float4*)(bs + c4 * 4);
        float m0 = fmaxf(v.x + bb.x, 0.f);
        float m1 = fmaxf(v.y + bb.y, 0.f);
        float m2 = fmaxf(v.z + bb.z, 0.f);
        float m3 = fmaxf(v.w + bb.w, 0.f);
        float* p = g_msum + (size_t)rows[r] * 128 + c4 * 4;
        asm volatile("red.global.add.v4.f32 [%0], {%1,%2,%3,%4};"
                     :: "l"(p), "f"(m0), "f"(m1), "f"(m2), "f"(m3) : "memory");
    }
}

// ------------------- readout pooling (reads g_x0 internally) -------------------
__global__ void k_pool(const int* __restrict__ batch, const int* __restrict__ ntype) {
    int idx = blockIdx.x * blockDim.x + threadIdx.x;
    int n = idx >> 5;
    int q = idx & 31;
    if (n >= Nn) return;
    if (ntype[n] == 1) {
        float4 v = ((const float4*)g_x0)[n * 32 + q];
        float* p = &g_gsum[batch[n] * 128 + q * 4];
        asm volatile("red.global.add.v4.f32 [%0], {%1,%2,%3,%4};"
                     :: "l"(p), "f"(v.x), "f"(v.y), "f"(v.z), "f"(v.w) : "memory");
    }
}

__global__ void k_ligcnt(const int* __restrict__ batch, const int* __restrict__ ntype) {
    int n = blockIdx.x * blockDim.x + threadIdx.x;
    if (n < Nn && ntype[n] == 1) atomicAdd(&g_ligcnt[batch[n]], 1.f);
}

__global__ void __launch_bounds__(128)
k_readout(const float* __restrict__ rw1, const float* __restrict__ rb1,
          const float* __restrict__ rw2, const float* __restrict__ rb2,
          float* __restrict__ out) {
    __shared__ __align__(16) float gs[128];
    __shared__ float red_s[128];
    int b = blockIdx.x;
    int tid = threadIdx.x;
    float cnt = fmaxf(g_ligcnt[b], 1.f);
    gs[tid] = g_gsum[b * 128 + tid] / cnt;
    __syncthreads();

    int j = tid;
    const float* Wj = rw1 + j;
    const float4* gs4 = (const float4*)gs;
    float acc = rb1[j];
    for (int kk = 0; kk < 32; kk++) {
        float w0 = Wj[(kk * 4 + 0) * 128];
        float w1 = Wj[(kk * 4 + 1) * 128];
        float w2 = Wj[(kk * 4 + 2) * 128];
        float w3 = Wj[(kk * 4 + 3) * 128];
        float4 gv = gs4[kk];
        acc += gv.x * w0 + gv.y * w1 + gv.z * w2 + gv.w * w3;
    }
    float hg = fmaxf(acc, 0.f);
    red_s[tid] = hg * rw2[j];
    __syncthreads();
    for (int s = 64; s > 0; s >>= 1) {
        if (tid < s) red_s[tid] += red_s[tid + s];
        __syncthreads();
    }
    if (tid == 0) out[b] = red_s[0] + rb2[0];
}

// ------------------- launch -------------------
extern "C" void kernel_launch(void* const* d_in, const int* in_sizes, int n_in,
                              void* d_out, int out_size) {
    const float* pos   = (const float*)d_in[0];
    const int*   z     = (const int*)d_in[1];
    const int*   batch = (const int*)d_in[2];
    const int*   eidx  = (const int*)d_in[3];
    const int*   ntype = (const int*)d_in[4];
    const float* emb   = (const float*)d_in[5];
    const float* lin_w = (const float*)d_in[6];
    const float* lin_b = (const float*)d_in[7];
    const float* mw1   = (const float*)d_in[8];
    const float* mb1   = (const float*)d_in[9];
    const float* mw2   = (const float*)d_in[10];
    const float* mb2   = (const float*)d_in[11];
    const float* uw    = (const float*)d_in[12];
    const float* ub    = (const float*)d_in[13];
    const float* rw1   = (const float*)d_in[14];
    const float* rb1   = (const float*)d_in[15];
    const float* rw2   = (const float*)d_in[16];
    const float* rb2   = (const float*)d_in[17];
    float* out = (float*)d_out;
    const int* row = eidx;
    const int* col = eidx + Ee;

    cudaFuncSetAttribute(k_edge_mma, cudaFuncAttributeMaxDynamicSharedMemorySize, E_SMEM);
    cudaFuncSetAttribute(k_xab_mma, cudaFuncAttributeMaxDynamicSharedMemorySize, G_SMEM);
    cudaFuncSetAttribute(k_update_mma, cudaFuncAttributeMaxDynamicSharedMemorySize, G_SMEM);
    cudaFuncSetAttribute(k_input_mma, cudaFuncAttributeMaxDynamicSharedMemorySize, G_SMEM);

    void *p_csum, *p_deg, *p_msum, *p_gsum, *p_lig, *p_w2hi, *p_w2lo;
    cudaGetSymbolAddress(&p_csum, g_csum);
    cudaGetSymbolAddress(&p_deg, g_deg);
    cudaGetSymbolAddress(&p_msum, g_msum);
    cudaGetSymbolAddress(&p_gsum, g_gsum);
    cudaGetSymbolAddress(&p_lig, g_ligcnt);
    cudaGetSymbolAddress(&p_w2hi, g_w2t_hi);
    cudaGetSymbolAddress(&p_w2lo, g_w2t_lo);

    cudaMemsetAsync(p_csum, 0, Bb * 4 * sizeof(float));
    cudaMemsetAsync(p_deg, 0, Nn * sizeof(int));
    cudaMemsetAsync(p_gsum, 0, Bb * Hh * sizeof(float));
    cudaMemsetAsync(p_lig, 0, Bb * sizeof(float));

    // weight preps (all layers at once)
    k_prep_w1<<<(3 * 256 * 128) / 256, 256>>>(mw1);
    k_prep_w2<<<(3 * 128 * 128) / 256, 256>>>(mw2);
    k_prep_u<<<(3 * 128 * 256) / 256, 256>>>(uw);
    k_prep_lin<<<(128 * 128) / 256, 256>>>(lin_w);

    k_center_sum<<<Nn / 256, 256>>>(pos, batch);
    k_center_fin<<<1, 64>>>();
    k_input_mma<<<Nn / 128, 512, G_SMEM>>>(pos, z, batch, emb, lin_w, lin_b);
    k_dist_deg<<<Ee / 256, 256>>>(eidx);
    k_invdeg<<<Nn / 256, 256>>>();

    for (int l = 0; l < 3; l++) {
        const float* W1 = mw1 + l * 257 * 128;
        k_xab_mma<<<dim3(Nn / 128, 2), 512, G_SMEM>>>(mb1 + l * 128, l);
        cudaMemsetAsync(p_msum, 0, (size_t)Nn * Hh * sizeof(float));
        k_edge_mma<<<Ee / 128, 512, E_SMEM>>>(row, col, W1 + 256 * 128, mb2 + l * 128,
                                              (const uint16_t*)p_w2hi + l * 16384,
                                              (const uint16_t*)p_w2lo + l * 16384);
        k_update_mma<<<Nn / 128, 512, G_SMEM>>>(ub + l * 128, l);
    }

    k_pool<<<Nn * 32 / 256, 256>>>(batch, ntype);
    k_ligcnt<<<Nn / 256, 256>>>(batch, ntype);
    k_readout<<<Bb, 128>>>(rw1, rb1, rw2, rb2, out);
}

// round 8
// speedup vs baseline: 2.3721x; 1.0500x over previous
#include <cuda_runtime.h>
#include <cuda_bf16.h>
#include <math.h>
#include <stdint.h>

#define Nn 65536
#define Ee 1048576
#define Bb 64
#define Hh 128

// ------------------- scratch (static device globals; no allocation) -------------------
__device__ float g_csum[Bb * 4];
__device__ float g_center[Bb * 3];
__device__ float g_posrel[Nn * 3];
__device__ float g_x0[Nn * Hh];           // fp32 node features
__device__ uint32_t g_xhi[Nn * 64];       // bf16x2-packed hi split of x
__device__ uint32_t g_xlo[Nn * 64];       // bf16x2-packed lo split of x
__device__ float g_xa[Nn * Hh];           // x @ W1a + b1  (gathered at col)
__device__ float g_xb[Nn * Hh];           // x @ W1b       (gathered at row)
__device__ float g_msum[Nn * Hh];         // scatter-add of m_ij at row
__device__ float g_dist[Ee];
__device__ int   g_deg[Nn];
__device__ float g_invdeg[Nn];
__device__ float g_gsum[Bb * Hh];
__device__ float g_ligcnt[Bb];
// edge sort (by row) scratch
__device__ int   g_rowstart[Nn];
__device__ int   g_rowcur[Nn];
__device__ int   g_blksum[256];
__device__ int   g_srow[Ee];
__device__ int   g_scol[Ee];
__device__ float g_sdist[Ee];
// prepped transposed weights, bf16 hi/lo, [out][k] row-major
__device__ uint16_t g_w1t_hi[3 * 256 * 128], g_w1t_lo[3 * 256 * 128];
__device__ uint16_t g_w2t_hi[3 * 128 * 128], g_w2t_lo[3 * 128 * 128];
__device__ uint16_t g_ut_hi[3 * 128 * 256], g_ut_lo[3 * 128 * 256];
__device__ uint16_t g_lint_hi[128 * 128], g_lint_lo[128 * 128];

// ------------------- helpers -------------------
__device__ __forceinline__ uint32_t smem_u32(const void* p) {
    uint32_t a;
    asm("{ .reg .u64 t; cvta.to.shared.u64 t, %1; cvt.u32.u64 %0, t; }" : "=r"(a) : "l"(p));
    return a;
}
__device__ __forceinline__ void ldsm_x4(uint32_t* r, uint32_t addr) {
    asm volatile("ldmatrix.sync.aligned.m8n8.x4.shared.b16 {%0,%1,%2,%3}, [%4];"
                 : "=r"(r[0]), "=r"(r[1]), "=r"(r[2]), "=r"(r[3]) : "r"(addr));
}
__device__ __forceinline__ void ldsm_x2(uint32_t* r, uint32_t addr) {
    asm volatile("ldmatrix.sync.aligned.m8n8.x2.shared.b16 {%0,%1}, [%2];"
                 : "=r"(r[0]), "=r"(r[1]) : "r"(addr));
}
__device__ __forceinline__ void mma_bf16(float* d, const uint32_t* a, const uint32_t* b) {
    asm volatile("mma.sync.aligned.m16n8k16.row.col.f32.bf16.bf16.f32 "
                 "{%0,%1,%2,%3}, {%4,%5,%6,%7}, {%8,%9}, {%0,%1,%2,%3};"
                 : "+f"(d[0]), "+f"(d[1]), "+f"(d[2]), "+f"(d[3])
                 : "r"(a[0]), "r"(a[1]), "r"(a[2]), "r"(a[3]), "r"(b[0]), "r"(b[1]));
}
__device__ __forceinline__ void split2(float v0, float v1, uint32_t& hi, uint32_t& lo) {
    __nv_bfloat162 h = __floats2bfloat162_rn(v0, v1);
    uint32_t hu = *(uint32_t*)&h;
    float h0 = __uint_as_float(hu << 16);
    float h1 = __uint_as_float(hu & 0xFFFF0000u);
    __nv_bfloat162 l = __floats2bfloat162_rn(v0 - h0, v1 - h1);
    hi = hu; lo = *(uint32_t*)&l;
}

// 3-term MMA core, 16 warps, warp tile m32 x n32
__device__ __forceinline__ void mma3_128(uint32_t sbase, uint32_t oAhi, uint32_t oAlo,
                                         uint32_t oBhi, uint32_t oBlo,
                                         int lane, int warp_m, int warp_n,
                                         float (&acc)[2][4][4]) {
    uint32_t a_base = sbase + oAhi + (uint32_t)(warp_m * 32 + (lane & 15)) * 272 + (uint32_t)(lane >> 4) * 16;
    uint32_t b_base = sbase + oBhi + (uint32_t)(warp_n * 32 + (lane & 7)) * 272 + (uint32_t)((lane >> 3) & 1) * 16;
    uint32_t dA = oAlo - oAhi, dB = oBlo - oBhi;
    for (int ks = 0; ks < 8; ks++) {
        uint32_t kb = (uint32_t)ks * 32;
        uint32_t a_hi[2][4], a_lo[2][4];
        #pragma unroll
        for (int mt = 0; mt < 2; mt++) {
            uint32_t ad = a_base + (uint32_t)(mt * 16) * 272 + kb;
            ldsm_x4(a_hi[mt], ad);
            ldsm_x4(a_lo[mt], ad + dA);
        }
        uint32_t b_hi[4][2], b_lo[4][2];
        #pragma unroll
        for (int nt = 0; nt < 4; nt++) {
            uint32_t bd = b_base + (uint32_t)(nt * 8) * 272 + kb;
            ldsm_x2(b_hi[nt], bd);
            ldsm_x2(b_lo[nt], bd + dB);
        }
        #pragma unroll
        for (int mt = 0; mt < 2; mt++)
            #pragma unroll
            for (int nt = 0; nt < 4; nt++)
                mma_bf16(acc[mt][nt], a_hi[mt], b_hi[nt]);
        #pragma unroll
        for (int mt = 0; mt < 2; mt++)
            #pragma unroll
            for (int nt = 0; nt < 4; nt++)
                mma_bf16(acc[mt][nt], a_lo[mt], b_hi[nt]);
        #pragma unroll
        for (int mt = 0; mt < 2; mt++)
            #pragma unroll
            for (int nt = 0; nt < 4; nt++)
                mma_bf16(acc[mt][nt], a_hi[mt], b_lo[nt]);
    }
}

__device__ __forceinline__ void stage_acc(char* sm, uint32_t oM, int lane, int warp_m, int warp_n,
                                          float (&acc)[2][4][4]) {
    #pragma unroll
    for (int mt = 0; mt < 2; mt++) {
        int er = warp_m * 32 + mt * 16 + (lane >> 2);
        #pragma unroll
        for (int nt = 0; nt < 4; nt++) {
            int cb = warp_n * 32 + nt * 8 + (lane & 3) * 2;
            *(float2*)(sm + oM + (uint32_t)er * 528 + cb * 4) = make_float2(acc[mt][nt][0], acc[mt][nt][1]);
            *(float2*)(sm + oM + (uint32_t)(er + 8) * 528 + cb * 4) = make_float2(acc[mt][nt][2], acc[mt][nt][3]);
        }
    }
}

// ------------------- small kernels -------------------
__global__ void k_center_sum(const float* __restrict__ pos, const int* __restrict__ batch) {
    int n = blockIdx.x * blockDim.x + threadIdx.x;
    if (n >= Nn) return;
    int lane = threadIdx.x & 31;
    int b = batch[n];
    float px = pos[n * 3 + 0], py = pos[n * 3 + 1], pz = pos[n * 3 + 2], pc = 1.f;
    #pragma unroll
    for (int off = 1; off < 32; off <<= 1) {
        int bs = __shfl_down_sync(0xffffffffu, b, off);
        float tx = __shfl_down_sync(0xffffffffu, px, off);
        float ty = __shfl_down_sync(0xffffffffu, py, off);
        float tz = __shfl_down_sync(0xffffffffu, pz, off);
        float tc = __shfl_down_sync(0xffffffffu, pc, off);
        if (lane + off < 32 && bs == b) { px += tx; py += ty; pz += tz; pc += tc; }
    }
    int bprev = __shfl_up_sync(0xffffffffu, b, 1);
    if (lane == 0 || bprev != b) {
        atomicAdd(&g_csum[b * 4 + 0], px);
        atomicAdd(&g_csum[b * 4 + 1], py);
        atomicAdd(&g_csum[b * 4 + 2], pz);
        atomicAdd(&g_csum[b * 4 + 3], pc);
    }
}

__global__ void k_center_fin() {
    int b = threadIdx.x;
    if (b < Bb) {
        float c = fmaxf(g_csum[b * 4 + 3], 1.f);
        g_center[b * 3 + 0] = g_csum[b * 4 + 0] / c;
        g_center[b * 3 + 1] = g_csum[b * 4 + 1] / c;
        g_center[b * 3 + 2] = g_csum[b * 4 + 2] / c;
    }
}

__global__ void k_dist_deg(const int* __restrict__ eidx) {
    int e = blockIdx.x * blockDim.x + threadIdx.x;
    if (e >= Ee) return;
    int r = eidx[e], c = eidx[Ee + e];
    float dx = g_posrel[c * 3 + 0] - g_posrel[r * 3 + 0];
    float dy = g_posrel[c * 3 + 1] - g_posrel[r * 3 + 1];
    float dz = g_posrel[c * 3 + 2] - g_posrel[r * 3 + 2];
    g_dist[e] = sqrtf(dx * dx + dy * dy + dz * dz);
    atomicAdd(&g_deg[r], 1);
}

__global__ void k_invdeg() {
    int n = blockIdx.x * blockDim.x + threadIdx.x;
    if (n < Nn) g_invdeg[n] = 1.f / fmaxf((float)g_deg[n], 1.f);
}

// ------------------- counting sort of edges by row -------------------
__global__ void k_scan1() {       // 256 blocks x 256 threads over g_deg
    __shared__ int s[256];
    int i = blockIdx.x * 256 + threadIdx.x;
    int v = g_deg[i];
    s[threadIdx.x] = v;
    __syncthreads();
    for (int off = 1; off < 256; off <<= 1) {
        int t = (threadIdx.x >= off) ? s[threadIdx.x - off] : 0;
        __syncthreads();
        s[threadIdx.x] += t;
        __syncthreads();
    }
    g_rowstart[i] = s[threadIdx.x] - v;      // exclusive within block
    if (threadIdx.x == 255) g_blksum[blockIdx.x] = s[255];
}
__global__ void k_scan2() {       // 1 block x 256: exclusive scan of block sums
    __shared__ int s[256];
    int i = threadIdx.x;
    int v = g_blksum[i];
    s[i] = v;
    __syncthreads();
    for (int off = 1; off < 256; off <<= 1) {
        int t = (i >= off) ? s[i - off] : 0;
        __syncthreads();
        s[i] += t;
        __syncthreads();
    }
    g_blksum[i] = s[i] - v;
}
__global__ void k_scan3() {
    int i = blockIdx.x * blockDim.x + threadIdx.x;
    if (i < Nn) {
        int v = g_rowstart[i] + g_blksum[i >> 8];
        g_rowstart[i] = v;
        g_rowcur[i] = v;
    }
}
__global__ void k_scatter(const int* __restrict__ eidx) {
    int e = blockIdx.x * blockDim.x + threadIdx.x;
    if (e >= Ee) return;
    int r = eidx[e];
    int p = atomicAdd(&g_rowcur[r], 1);
    g_srow[p] = r;
    g_scol[p] = eidx[Ee + e];
    g_sdist[p] = g_dist[e];
}

// ------------------- weight prep (transposed, bf16 hi/lo) -------------------
__global__ void k_prep_w1(const float* __restrict__ mw1) {   // 3*256*128
    int idx = blockIdx.x * blockDim.x + threadIdx.x;
    if (idx >= 3 * 256 * 128) return;
    int l = idx >> 15, rem = idx & 32767;
    int n = rem >> 7, k = rem & 127;
    int kin = (n < 128) ? k : 128 + k;
    int j = (n < 128) ? n : n - 128;
    float v = mw1[l * 257 * 128 + kin * 128 + j];
    __nv_bfloat16 h = __float2bfloat16_rn(v);
    __nv_bfloat16 lo = __float2bfloat16_rn(v - __bfloat162float(h));
    g_w1t_hi[idx] = *(uint16_t*)&h;
    g_w1t_lo[idx] = *(uint16_t*)&lo;
}
__global__ void k_prep_w2(const float* __restrict__ mw2) {   // 3*128*128
    int idx = blockIdx.x * blockDim.x + threadIdx.x;
    if (idx >= 3 * 128 * 128) return;
    int l = idx >> 14, rem = idx & 16383;
    int n = rem >> 7, k = rem & 127;
    float v = mw2[l * 16384 + k * 128 + n];
    __nv_bfloat16 h = __float2bfloat16_rn(v);
    __nv_bfloat16 lo = __float2bfloat16_rn(v - __bfloat162float(h));
    g_w2t_hi[idx] = *(uint16_t*)&h;
    g_w2t_lo[idx] = *(uint16_t*)&lo;
}
__global__ void k_prep_u(const float* __restrict__ uw) {     // 3*128*256
    int idx = blockIdx.x * blockDim.x + threadIdx.x;
    if (idx >= 3 * 128 * 256) return;
    int l = idx >> 15, rem = idx & 32767;
    int n = rem >> 8, k = rem & 255;
    float v = uw[l * 32768 + k * 128 + n];
    __nv_bfloat16 h = __float2bfloat16_rn(v);
    __nv_bfloat16 lo = __float2bfloat16_rn(v - __bfloat162float(h));
    g_ut_hi[idx] = *(uint16_t*)&h;
    g_ut_lo[idx] = *(uint16_t*)&lo;
}
__global__ void k_prep_lin(const float* __restrict__ lin_w) {  // 128*128
    int idx = blockIdx.x * blockDim.x + threadIdx.x;
    if (idx >= 128 * 128) return;
    int n = idx >> 7, k = idx & 127;
    float v = lin_w[k * 128 + n];
    __nv_bfloat16 h = __float2bfloat16_rn(v);
    __nv_bfloat16 lo = __float2bfloat16_rn(v - __bfloat162float(h));
    g_lint_hi[idx] = *(uint16_t*)&h;
    g_lint_lo[idx] = *(uint16_t*)&lo;
}

// ------------------- shared smem layout for 128x128 GEMM kernels -------------------
#define GOFF_BIAS 0
#define GOFF_AUX  512
#define GOFF_IDX  2048
#define GOFF_AHI  4096
#define G_ASZ     34816
#define GOFF_ALO  (GOFF_AHI + G_ASZ)
#define GOFF_BHI  (GOFF_ALO + G_ASZ)
#define GOFF_BLO  (GOFF_BHI + G_ASZ)
#define G_SMEM    (GOFF_BLO + G_ASZ)   // 143360

// ------------------- k_input via HMMA -------------------
__global__ void __launch_bounds__(512, 1)
k_input_mma(const float* __restrict__ pos, const int* __restrict__ z,
            const int* __restrict__ batch, const float* __restrict__ emb,
            const float* __restrict__ lin_w, const float* __restrict__ bias) {
    extern __shared__ __align__(16) char sm[];
    uint32_t sbase = smem_u32(sm);
    int tid = threadIdx.x;
    int lane = tid & 31;
    int wid = tid >> 5;
    int n0 = blockIdx.x * 128;
    float* bs  = (float*)(sm + GOFF_BIAS);
    float* tl  = (float*)(sm + GOFF_AUX);
    float* prs = (float*)(sm + GOFF_IDX);
    int*   zs  = (int*)(sm + GOFF_IDX + 1536);

    if (tid < 128) {
        bs[tid] = bias[tid];
        int n = n0 + tid;
        int b = batch[n];
        #pragma unroll
        for (int d = 0; d < 3; d++) {
            float v = pos[n * 3 + d] - g_center[b * 3 + d];
            prs[tid * 3 + d] = v;
            g_posrel[n * 3 + d] = v;
        }
        zs[tid] = z[n];
    } else if (tid >= 128 && tid < 128 + 384) {
        int i = tid - 128;
        tl[i] = lin_w[(128 + (i >> 7)) * 128 + (i & 127)];
    }

    {
        const uint4* bh = (const uint4*)g_lint_hi;
        const uint4* bl = (const uint4*)g_lint_lo;
        #pragma unroll
        for (int it = 0; it < 4; it++) {
            int i = tid + it * 512;
            int r = i >> 4, c = i & 15;
            uint32_t o = (uint32_t)r * 272 + c * 16;
            *(uint4*)(sm + GOFF_BHI + o) = bh[i];
            *(uint4*)(sm + GOFF_BLO + o) = bl[i];
        }
    }
    __syncthreads();

    #pragma unroll
    for (int it = 0; it < 4; it++) {
        int cid = tid + it * 512;
        int r = cid >> 4, kc = cid & 15;
        const float4* ep = (const float4*)(emb + (size_t)zs[r] * 128) + kc * 2;
        float4 e0 = ep[0], e1 = ep[1];
        uint32_t h0, l0, h1, l1, h2, l2, h3, l3;
        split2(e0.x, e0.y, h0, l0);
        split2(e0.z, e0.w, h1, l1);
        split2(e1.x, e1.y, h2, l2);
        split2(e1.z, e1.w, h3, l3);
        uint32_t o = (uint32_t)r * 272 + kc * 16;
        *(uint4*)(sm + GOFF_AHI + o) = make_uint4(h0, h1, h2, h3);
        *(uint4*)(sm + GOFF_ALO + o) = make_uint4(l0, l1, l2, l3);
    }
    __syncthreads();

    float acc[2][4][4];
    #pragma unroll
    for (int mt = 0; mt < 2; mt++)
        #pragma unroll
        for (int nt = 0; nt < 4; nt++)
            #pragma unroll
            for (int q = 0; q < 4; q++) acc[mt][nt][q] = 0.f;
    mma3_128(sbase, GOFF_AHI, GOFF_ALO, GOFF_BHI, GOFF_BLO, lane, wid & 3, wid >> 2, acc);
    __syncthreads();
    stage_acc(sm, GOFF_AHI, lane, wid & 3, wid >> 2, acc);
    __syncthreads();

    #pragma unroll
    for (int it = 0; it < 8; it++) {
        int cid = tid + it * 512;
        int r = cid >> 5, c4 = cid & 31;
        float4 v = *(float4*)(sm + GOFF_AHI + (uint32_t)r * 528 + c4 * 16);
        float p0 = prs[r * 3 + 0], p1 = prs[r * 3 + 1], p2 = prs[r * 3 + 2];
        int c = c4 * 4;
        v.x += bs[c + 0] + p0 * tl[c + 0] + p1 * tl[128 + c + 0] + p2 * tl[256 + c + 0];
        v.y += bs[c + 1] + p0 * tl[c + 1] + p1 * tl[128 + c + 1] + p2 * tl[256 + c + 1];
        v.z += bs[c + 2] + p0 * tl[c + 2] + p1 * tl[128 + c + 2] + p2 * tl[256 + c + 2];
        v.w += bs[c + 3] + p0 * tl[c + 3] + p1 * tl[128 + c + 3] + p2 * tl[256 + c + 3];
        size_t nrow = (size_t)(n0 + r);
        ((float4*)(g_x0 + nrow * 128))[c4] = v;
        uint32_t h01, l01, h23, l23;
        split2(v.x, v.y, h01, l01);
        split2(v.z, v.w, h23, l23);
        ((uint2*)g_xhi)[nrow * 32 + c4] = make_uint2(h01, h23);
        ((uint2*)g_xlo)[nrow * 32 + c4] = make_uint2(l01, l23);
    }
}

// ------------------- k_xab via HMMA -------------------
__global__ void __launch_bounds__(512, 1)
k_xab_mma(const float* __restrict__ b1, int layer) {
    extern __shared__ __align__(16) char sm[];
    uint32_t sbase = smem_u32(sm);
    int tid = threadIdx.x;
    int lane = tid & 31;
    int wid = tid >> 5;
    int n0 = blockIdx.x * 128;
    int half = blockIdx.y;
    float* bs = (float*)(sm + GOFF_BIAS);
    if (tid < 128) bs[tid] = (half == 0) ? b1[tid] : 0.f;

    const uint4* ah = (const uint4*)g_xhi + (size_t)n0 * 16;
    const uint4* al = (const uint4*)g_xlo + (size_t)n0 * 16;
    const uint4* bh = (const uint4*)(g_w1t_hi + layer * 256 * 128) + (size_t)half * 128 * 16;
    const uint4* bl = (const uint4*)(g_w1t_lo + layer * 256 * 128) + (size_t)half * 128 * 16;
    #pragma unroll
    for (int it = 0; it < 4; it++) {
        int cid = tid + it * 512;
        int r = cid >> 4, c = cid & 15;
        uint32_t o = (uint32_t)r * 272 + c * 16;
        *(uint4*)(sm + GOFF_AHI + o) = ah[r * 16 + c];
        *(uint4*)(sm + GOFF_ALO + o) = al[r * 16 + c];
        *(uint4*)(sm + GOFF_BHI + o) = bh[r * 16 + c];
        *(uint4*)(sm + GOFF_BLO + o) = bl[r * 16 + c];
    }
    __syncthreads();

    float acc[2][4][4];
    #pragma unroll
    for (int mt = 0; mt < 2; mt++)
        #pragma unroll
        for (int nt = 0; nt < 4; nt++)
            #pragma unroll
            for (int q = 0; q < 4; q++) acc[mt][nt][q] = 0.f;
    mma3_128(sbase, GOFF_AHI, GOFF_ALO, GOFF_BHI, GOFF_BLO, lane, wid & 3, wid >> 2, acc);
    __syncthreads();
    stage_acc(sm, GOFF_AHI, lane, wid & 3, wid >> 2, acc);
    __syncthreads();

    float* out = half == 0 ? g_xa : g_xb;
    #pragma unroll
    for (int it = 0; it < 8; it++) {
        int cid = tid + it * 512;
        int r = cid >> 5, c4 = cid & 31;
        float4 v = *(float4*)(sm + GOFF_AHI + (uint32_t)r * 528 + c4 * 16);
        v.x += bs[c4 * 4 + 0]; v.y += bs[c4 * 4 + 1];
        v.z += bs[c4 * 4 + 2]; v.w += bs[c4 * 4 + 3];
        ((float4*)(out + (size_t)(n0 + r) * 128))[c4] = v;
    }
}

// ------------------- k_update via HMMA -------------------
__global__ void __launch_bounds__(512, 1)
k_update_mma(const float* __restrict__ bias, int layer) {
    extern __shared__ __align__(16) char sm[];
    uint32_t sbase = smem_u32(sm);
    int tid = threadIdx.x;
    int lane = tid & 31;
    int wid = tid >> 5;
    int n0 = blockIdx.x * 128;
    float* bs = (float*)(sm + GOFF_BIAS);
    float* idg = (float*)(sm + GOFF_AUX);
    if (tid < 128) {
        bs[tid] = bias[tid];
        idg[tid] = g_invdeg[n0 + tid];
    }

    const uint16_t* ut_hi = g_ut_hi + layer * 128 * 256;
    const uint16_t* ut_lo = g_ut_lo + layer * 128 * 256;

    float acc[2][4][4];
    #pragma unroll
    for (int mt = 0; mt < 2; mt++)
        #pragma unroll
        for (int nt = 0; nt < 4; nt++)
            #pragma unroll
            for (int q = 0; q < 4; q++) acc[mt][nt][q] = 0.f;

    {
        const uint4* ah = (const uint4*)g_xhi + (size_t)n0 * 16;
        const uint4* al = (const uint4*)g_xlo + (size_t)n0 * 16;
        const uint4* bh = (const uint4*)ut_hi;
        const uint4* bl = (const uint4*)ut_lo;
        #pragma unroll
        for (int it = 0; it < 4; it++) {
            int cid = tid + it * 512;
            int r = cid >> 4, c = cid & 15;
            uint32_t o = (uint32_t)r * 272 + c * 16;
            *(uint4*)(sm + GOFF_AHI + o) = ah[r * 16 + c];
            *(uint4*)(sm + GOFF_ALO + o) = al[r * 16 + c];
            *(uint4*)(sm + GOFF_BHI + o) = bh[r * 32 + c];
            *(uint4*)(sm + GOFF_BLO + o) = bl[r * 32 + c];
        }
        __syncthreads();
        mma3_128(sbase, GOFF_AHI, GOFF_ALO, GOFF_BHI, GOFF_BLO, lane, wid & 3, wid >> 2, acc);
        __syncthreads();
    }
    {
        const uint4* bh = (const uint4*)ut_hi;
        const uint4* bl = (const uint4*)ut_lo;
        #pragma unroll
        for (int it = 0; it < 4; it++) {
            int cid = tid + it * 512;
            int r = cid >> 4, c = cid & 15;
            uint32_t o = (uint32_t)r * 272 + c * 16;
            const float4* mp = (const float4*)(g_msum + (size_t)(n0 + r) * 128) + c * 2;
            float s = idg[r];
            float4 m0 = mp[0], m1 = mp[1];
            uint32_t h0, l0, h1, l1, h2, l2, h3, l3;
            split2(m0.x * s, m0.y * s, h0, l0);
            split2(m0.z * s, m0.w * s, h1, l1);
            split2(m1.x * s, m1.y * s, h2, l2);
            split2(m1.z * s, m1.w * s, h3, l3);
            *(uint4*)(sm + GOFF_AHI + o) = make_uint4(h0, h1, h2, h3);
            *(uint4*)(sm + GOFF_ALO + o) = make_uint4(l0, l1, l2, l3);
            *(uint4*)(sm + GOFF_BHI + o) = bh[r * 32 + 16 + c];
            *(uint4*)(sm + GOFF_BLO + o) = bl[r * 32 + 16 + c];
        }
        __syncthreads();
        mma3_128(sbase, GOFF_AHI, GOFF_ALO, GOFF_BHI, GOFF_BLO, lane, wid & 3, wid >> 2, acc);
        __syncthreads();
    }

    stage_acc(sm, GOFF_AHI, lane, wid & 3, wid >> 2, acc);
    __syncthreads();

    #pragma unroll
    for (int it = 0; it < 8; it++) {
        int cid = tid + it * 512;
        int r = cid >> 5, c4 = cid & 31;
        float4 v = *(float4*)(sm + GOFF_AHI + (uint32_t)r * 528 + c4 * 16);
        v.x = fmaxf(v.x + bs[c4 * 4 + 0], 0.f);
        v.y = fmaxf(v.y + bs[c4 * 4 + 1], 0.f);
        v.z = fmaxf(v.z + bs[c4 * 4 + 2], 0.f);
        v.w = fmaxf(v.w + bs[c4 * 4 + 3], 0.f);
        size_t nrow = (size_t)(n0 + r);
        ((float4*)(g_x0 + nrow * 128))[c4] = v;
        uint32_t h01, l01, h23, l23;
        split2(v.x, v.y, h01, l01);
        split2(v.z, v.w, h23, l23);
        ((uint2*)g_xhi)[nrow * 32 + c4] = make_uint2(h01, h23);
        ((uint2*)g_xlo)[nrow * 32 + c4] = make_uint2(l01, l23);
    }
}

// ------------------- HMMA edge kernel (sorted edges, segmented epilogue) ---------------
#define EOFF_ROWS 0
#define EOFF_COLS 512
#define EOFF_DIST 1024
#define EOFF_BIAS 1536
#define EOFF_W1C  2048
#define EOFF_SEG  2560          // wcnt[4], woff[4], nseg[1], segstart[130]
#define EOFF_AHI  4096
#define E_ASZ     34816
#define EOFF_ALO  (EOFF_AHI + E_ASZ)
#define EOFF_BHI  (EOFF_ALO + E_ASZ)
#define EOFF_BLO  (EOFF_BHI + E_ASZ)
#define E_SMEM    (EOFF_BLO + E_ASZ)   // 143360

__global__ void __launch_bounds__(512, 1)
k_edge_mma(const float* __restrict__ w1c, const float* __restrict__ b2,
           const uint16_t* __restrict__ w2hi, const uint16_t* __restrict__ w2lo) {
    extern __shared__ __align__(16) char sm[];
    uint32_t sbase = smem_u32(sm);
    int tid = threadIdx.x;
    int lane = tid & 31;
    int wid = tid >> 5;
    int e0 = blockIdx.x * 128;

    int*   rows = (int*)(sm + EOFF_ROWS);
    int*   cols = (int*)(sm + EOFF_COLS);
    float* ds   = (float*)(sm + EOFF_DIST);
    float* bs   = (float*)(sm + EOFF_BIAS);
    float* ws   = (float*)(sm + EOFF_W1C);
    int*   wcnt = (int*)(sm + EOFF_SEG);
    int*   woff = wcnt + 4;
    int*   nsegp = woff + 4;
    int*   segstart = nsegp + 1;   // 130 ints

    if (tid < 128) {
        rows[tid] = g_srow[e0 + tid];
        cols[tid] = g_scol[e0 + tid];
        ds[tid]   = g_sdist[e0 + tid];
        bs[tid]   = b2[tid];
        ws[tid]   = w1c[tid];
    }

    {
        const uint4* bh = (const uint4*)w2hi;
        const uint4* bl = (const uint4*)w2lo;
        #pragma unroll
        for (int it = 0; it < 4; it++) {
            int i = tid + it * 512;
            int r = i >> 4, c = i & 15;
            uint32_t o = (uint32_t)r * 272 + c * 16;
            *(uint4*)(sm + EOFF_BHI + o) = bh[i];
            *(uint4*)(sm + EOFF_BLO + o) = bl[i];
        }
    }
    __syncthreads();

    // A build: h = relu(xa[col] + xb[row] + dist*w1c), split hi/lo
    #pragma unroll
    for (int it = 0; it < 4; it++) {
        int cid = tid + it * 512;
        int e = cid >> 4;
        int kc = cid & 15;
        const float4* pa = (const float4*)(g_xa + (size_t)cols[e] * 128) + kc * 2;
        const float4* pb = (const float4*)(g_xb + (size_t)rows[e] * 128) + kc * 2;
        float d = ds[e];
        float4 a0 = pa[0], a1 = pa[1];
        float4 b0 = pb[0], b1 = pb[1];
        int k0 = kc * 8;
        float v0 = fmaxf(a0.x + b0.x + d * ws[k0 + 0], 0.f);
        float v1 = fmaxf(a0.y + b0.y + d * ws[k0 + 1], 0.f);
        float v2 = fmaxf(a0.z + b0.z + d * ws[k0 + 2], 0.f);
        float v3 = fmaxf(a0.w + b0.w + d * ws[k0 + 3], 0.f);
        float v4 = fmaxf(a1.x + b1.x + d * ws[k0 + 4], 0.f);
        float v5 = fmaxf(a1.y + b1.y + d * ws[k0 + 5], 0.f);
        float v6 = fmaxf(a1.z + b1.z + d * ws[k0 + 6], 0.f);
        float v7 = fmaxf(a1.w + b1.w + d * ws[k0 + 7], 0.f);
        uint32_t h0, l0, h1, l1, h2, l2, h3, l3;
        split2(v0, v1, h0, l0);
        split2(v2, v3, h1, l1);
        split2(v4, v5, h2, l2);
        split2(v6, v7, h3, l3);
        uint32_t o = (uint32_t)e * 272 + kc * 16;
        *(uint4*)(sm + EOFF_AHI + o) = make_uint4(h0, h1, h2, h3);
        *(uint4*)(sm + EOFF_ALO + o) = make_uint4(l0, l1, l2, l3);
    }
    __syncthreads();

    float acc[2][4][4];
    #pragma unroll
    for (int mt = 0; mt < 2; mt++)
        #pragma unroll
        for (int nt = 0; nt < 4; nt++)
            #pragma unroll
            for (int q = 0; q < 4; q++) acc[mt][nt][q] = 0.f;
    mma3_128(sbase, EOFF_AHI, EOFF_ALO, EOFF_BHI, EOFF_BLO, lane, wid & 3, wid >> 2, acc);
    __syncthreads();
    stage_acc(sm, EOFF_AHI, lane, wid & 3, wid >> 2, acc);

    // segment detection on sorted rows (warps 0-3 cover tid 0..127)
    int f = 0, pre = 0;
    if (wid < 4) {
        f = (tid == 0) || (rows[tid] != rows[tid - 1]);
        unsigned m = __ballot_sync(0xffffffffu, f);
        pre = __popc(m & ((1u << lane) - 1u));
        if (lane == 0) wcnt[wid] = __popc(m);
    }
    __syncthreads();
    if (tid == 0) {
        int s = 0;
        #pragma unroll
        for (int w = 0; w < 4; w++) { woff[w] = s; s += wcnt[w]; }
        nsegp[0] = s;
        segstart[s] = 128;
    }
    __syncthreads();
    if (wid < 4 && f) segstart[woff[wid] + pre] = tid;
    __syncthreads();

    // segmented epilogue: bias+relu per element, sum within segment, one red.v4 each
    int nseg = nsegp[0];
    for (int item = tid; item < nseg * 32; item += 512) {
        int s = item >> 5, c4 = item & 31;
        int rbeg = segstart[s], rend = segstart[s + 1];
        float4 bb = *(float4*)(bs + c4 * 4);
        float m0 = 0.f, m1 = 0.f, m2 = 0.f, m3 = 0.f;
        for (int r = rbeg; r < rend; r++) {
            float4 v = *(float4*)(sm + EOFF_AHI + (uint32_t)r * 528 + c4 * 16);
            m0 += fmaxf(v.x + bb.x, 0.f);
            m1 += fmaxf(v.y + bb.y, 0.f);
            m2 += fmaxf(v.z + bb.z, 0.f);
            m3 += fmaxf(v.w + bb.w, 0.f);
        }
        float* p = g_msum + (size_t)rows[rbeg] * 128 + c4 * 4;
        asm volatile("red.global.add.v4.f32 [%0], {%1,%2,%3,%4};"
                     :: "l"(p), "f"(m0), "f"(m1), "f"(m2), "f"(m3) : "memory");
    }
}

// ------------------- readout pooling -------------------
__global__ void k_pool(const int* __restrict__ batch, const int* __restrict__ ntype) {
    int idx = blockIdx.x * blockDim.x + threadIdx.x;
    int n = idx >> 5;
    int q = idx & 31;
    if (n >= Nn) return;
    if (ntype[n] == 1) {
        float4 v = ((const float4*)g_x0)[n * 32 + q];
        float* p = &g_gsum[batch[n] * 128 + q * 4];
        asm volatile("red.global.add.v4.f32 [%0], {%1,%2,%3,%4};"
                     :: "l"(p), "f"(v.x), "f"(v.y), "f"(v.z), "f"(v.w) : "memory");
    }
}

__global__ void k_ligcnt(const int* __restrict__ batch, const int* __restrict__ ntype) {
    int n = blockIdx.x * blockDim.x + threadIdx.x;
    if (n < Nn && ntype[n] == 1) atomicAdd(&g_ligcnt[batch[n]], 1.f);
}

__global__ void __launch_bounds__(128)
k_readout(const float* __restrict__ rw1, const float* __restrict__ rb1,
          const float* __restrict__ rw2, const float* __restrict__ rb2,
          float* __restrict__ out) {
    __shared__ __align__(16) float gs[128];
    __shared__ float red_s[128];
    int b = blockIdx.x;
    int tid = threadIdx.x;
    float cnt = fmaxf(g_ligcnt[b], 1.f);
    gs[tid] = g_gsum[b * 128 + tid] / cnt;
    __syncthreads();

    int j = tid;
    const float* Wj = rw1 + j;
    const float4* gs4 = (const float4*)gs;
    float acc = rb1[j];
    for (int kk = 0; kk < 32; kk++) {
        float w0 = Wj[(kk * 4 + 0) * 128];
        float w1 = Wj[(kk * 4 + 1) * 128];
        float w2 = Wj[(kk * 4 + 2) * 128];
        float w3 = Wj[(kk * 4 + 3) * 128];
        float4 gv = gs4[kk];
        acc += gv.x * w0 + gv.y * w1 + gv.z * w2 + gv.w * w3;
    }
    float hg = fmaxf(acc, 0.f);
    red_s[tid] = hg * rw2[j];
    __syncthreads();
    for (int s = 64; s > 0; s >>= 1) {
        if (tid < s) red_s[tid] += red_s[tid + s];
        __syncthreads();
    }
    if (tid == 0) out[b] = red_s[0] + rb2[0];
}

// ------------------- launch -------------------
extern "C" void kernel_launch(void* const* d_in, const int* in_sizes, int n_in,
                              void* d_out, int out_size) {
    const float* pos   = (const float*)d_in[0];
    const int*   z     = (const int*)d_in[1];
    const int*   batch = (const int*)d_in[2];
    const int*   eidx  = (const int*)d_in[3];
    const int*   ntype = (const int*)d_in[4];
    const float* emb   = (const float*)d_in[5];
    const float* lin_w = (const float*)d_in[6];
    const float* lin_b = (const float*)d_in[7];
    const float* mw1   = (const float*)d_in[8];
    const float* mb1   = (const float*)d_in[9];
    const float* mw2   = (const float*)d_in[10];
    const float* mb2   = (const float*)d_in[11];
    const float* uw    = (const float*)d_in[12];
    const float* ub    = (const float*)d_in[13];
    const float* rw1   = (const float*)d_in[14];
    const float* rb1   = (const float*)d_in[15];
    const float* rw2   = (const float*)d_in[16];
    const float* rb2   = (const float*)d_in[17];
    float* out = (float*)d_out;

    cudaFuncSetAttribute(k_edge_mma, cudaFuncAttributeMaxDynamicSharedMemorySize, E_SMEM);
    cudaFuncSetAttribute(k_xab_mma, cudaFuncAttributeMaxDynamicSharedMemorySize, G_SMEM);
    cudaFuncSetAttribute(k_update_mma, cudaFuncAttributeMaxDynamicSharedMemorySize, G_SMEM);
    cudaFuncSetAttribute(k_input_mma, cudaFuncAttributeMaxDynamicSharedMemorySize, G_SMEM);

    void *p_csum, *p_deg, *p_msum, *p_gsum, *p_lig, *p_w2hi, *p_w2lo;
    cudaGetSymbolAddress(&p_csum, g_csum);
    cudaGetSymbolAddress(&p_deg, g_deg);
    cudaGetSymbolAddress(&p_msum, g_msum);
    cudaGetSymbolAddress(&p_gsum, g_gsum);
    cudaGetSymbolAddress(&p_lig, g_ligcnt);
    cudaGetSymbolAddress(&p_w2hi, g_w2t_hi);
    cudaGetSymbolAddress(&p_w2lo, g_w2t_lo);

    cudaMemsetAsync(p_csum, 0, Bb * 4 * sizeof(float));
    cudaMemsetAsync(p_deg, 0, Nn * sizeof(int));
    cudaMemsetAsync(p_gsum, 0, Bb * Hh * sizeof(float));
    cudaMemsetAsync(p_lig, 0, Bb * sizeof(float));

    // weight preps (all layers at once)
    k_prep_w1<<<(3 * 256 * 128) / 256, 256>>>(mw1);
    k_prep_w2<<<(3 * 128 * 128) / 256, 256>>>(mw2);
    k_prep_u<<<(3 * 128 * 256) / 256, 256>>>(uw);
    k_prep_lin<<<(128 * 128) / 256, 256>>>(lin_w);

    k_center_sum<<<Nn / 256, 256>>>(pos, batch);
    k_center_fin<<<1, 64>>>();
    k_input_mma<<<Nn / 128, 512, G_SMEM>>>(pos, z, batch, emb, lin_w, lin_b);
    k_dist_deg<<<Ee / 256, 256>>>(eidx);
    k_invdeg<<<Nn / 256, 256>>>();

    // counting sort of edges by destination row
    k_scan1<<<256, 256>>>();
    k_scan2<<<1, 256>>>();
    k_scan3<<<Nn / 256, 256>>>();
    k_scatter<<<Ee / 256, 256>>>(eidx);

    for (int l = 0; l < 3; l++) {
        const float* W1 = mw1 + l * 257 * 128;
        k_xab_mma<<<dim3(Nn / 128, 2), 512, G_SMEM>>>(mb1 + l * 128, l);
        cudaMemsetAsync(p_msum, 0, (size_t)Nn * Hh * sizeof(float));
        k_edge_mma<<<Ee / 128, 512, E_SMEM>>>(W1 + 256 * 128, mb2 + l * 128,
                                              (const uint16_t*)p_w2hi + l * 16384,
                                              (const uint16_t*)p_w2lo + l * 16384);
        k_update_mma<<<Nn / 128, 512, G_SMEM>>>(ub + l * 128, l);
    }

    k_pool<<<Nn * 32 / 256, 256>>>(batch, ntype);
    k_ligcnt<<<Nn / 256, 256>>>(batch, ntype);
    k_readout<<<Bb, 128>>>(rw1, rb1, rw2, rb2, out);
}

// round 9
// speedup vs baseline: 3.1641x; 1.3339x over previous
#include <cuda_runtime.h>
#include <cuda_bf16.h>
#include <math.h>
#include <stdint.h>

#define Nn 65536
#define Ee 1048576
#define Bb 64
#define Hh 128

// ------------------- scratch (static device globals; no allocation) -------------------
__device__ float g_csum[Bb * 4];
__device__ float g_center[Bb * 3];
__device__ float g_posrel[Nn * 3];
__device__ float g_x0[Nn * Hh];
__device__ uint32_t g_xhi[Nn * 64];
__device__ uint32_t g_xlo[Nn * 64];
__device__ float g_xa[Nn * Hh];
__device__ float g_xb[Nn * Hh];
__device__ float g_msum[Nn * Hh];
__device__ float g_dist[Ee];
__device__ int   g_deg[Nn];
__device__ float g_invdeg[Nn];
__device__ float g_gsum[Bb * Hh];
__device__ float g_ligcnt[Bb];
// edge sort scratch
__device__ int   g_rowstart[Nn];
__device__ int   g_rowcur[Nn];
__device__ int   g_blksum[256];
__device__ int   g_srow[Ee];
__device__ int   g_scol[Ee];
__device__ float g_sdist[Ee];
// fragment-linear weights (bf16x2 pairs per lane), hi/lo split
// index: ((ks*NT + ntile)*32 + lane) -> uint2 {reg_klow, reg_khigh}
__device__ uint2 g_w1f_hi[3 * 8192], g_w1f_lo[3 * 8192];   // W1^T 256n x 128k, NT=32
__device__ uint2 g_w2f_hi[3 * 4096], g_w2f_lo[3 * 4096];   // W2^T 128n x 128k, NT=16
__device__ uint2 g_uf_hi[3 * 8192],  g_uf_lo[3 * 8192];    // U^T  128n x 256k, NT=16, ks 0..15
__device__ uint2 g_linf_hi[4096],    g_linf_lo[4096];      // lin^T 128n x 128k, NT=16

// ------------------- helpers -------------------
__device__ __forceinline__ uint32_t smem_u32(const void* p) {
    uint32_t a;
    asm("{ .reg .u64 t; cvta.to.shared.u64 t, %1; cvt.u32.u64 %0, t; }" : "=r"(a) : "l"(p));
    return a;
}
__device__ __forceinline__ void ldsm_x4(uint32_t* r, uint32_t addr) {
    asm volatile("ldmatrix.sync.aligned.m8n8.x4.shared.b16 {%0,%1,%2,%3}, [%4];"
                 : "=r"(r[0]), "=r"(r[1]), "=r"(r[2]), "=r"(r[3]) : "r"(addr));
}
__device__ __forceinline__ void mma_bf16(float* d, const uint32_t* a, const uint32_t* b) {
    asm volatile("mma.sync.aligned.m16n8k16.row.col.f32.bf16.bf16.f32 "
                 "{%0,%1,%2,%3}, {%4,%5,%6,%7}, {%8,%9}, {%0,%1,%2,%3};"
                 : "+f"(d[0]), "+f"(d[1]), "+f"(d[2]), "+f"(d[3])
                 : "r"(a[0]), "r"(a[1]), "r"(a[2]), "r"(a[3]), "r"(b[0]), "r"(b[1]));
}
__device__ __forceinline__ void split2(float v0, float v1, uint32_t& hi, uint32_t& lo) {
    __nv_bfloat162 h = __floats2bfloat162_rn(v0, v1);
    uint32_t hu = *(uint32_t*)&h;
    float h0 = __uint_as_float(hu << 16);
    float h1 = __uint_as_float(hu & 0xFFFF0000u);
    __nv_bfloat162 l = __floats2bfloat162_rn(v0 - h0, v1 - h1);
    hi = hu; lo = *(uint32_t*)&l;
}

// 3-term MMA core with B from fragment-linear global arrays.
// A (hi/lo) in smem (128 rows x 256B, stride 272). 16 warps, warp tile m32 x n32.
__device__ __forceinline__ void mma3_gf(uint32_t sbase, uint32_t oAhi, uint32_t oAlo,
                                        const uint2* __restrict__ bfh,
                                        const uint2* __restrict__ bfl,
                                        int NT, int nt_base, int ks_base,
                                        int lane, int warp_m,
                                        float (&acc)[2][4][4]) {
    uint32_t a_base = sbase + oAhi + (uint32_t)(warp_m * 32 + (lane & 15)) * 272 + (uint32_t)(lane >> 4) * 16;
    uint32_t dA = oAlo - oAhi;
    for (int ks = 0; ks < 8; ks++) {
        uint32_t kb = (uint32_t)ks * 32;
        uint32_t a_hi[2][4], a_lo[2][4];
        #pragma unroll
        for (int mt = 0; mt < 2; mt++) {
            uint32_t ad = a_base + (uint32_t)(mt * 16) * 272 + kb;
            ldsm_x4(a_hi[mt], ad);
            ldsm_x4(a_lo[mt], ad + dA);
        }
        int fks = (ks_base + ks) * NT + nt_base;
        #pragma unroll
        for (int nt = 0; nt < 4; nt++) {
            uint2 bh = __ldg(bfh + (size_t)(fks + nt) * 32 + lane);
            uint2 bl = __ldg(bfl + (size_t)(fks + nt) * 32 + lane);
            uint32_t bhv[2] = {bh.x, bh.y};
            uint32_t blv[2] = {bl.x, bl.y};
            mma_bf16(acc[0][nt], a_hi[0], bhv);
            mma_bf16(acc[1][nt], a_hi[1], bhv);
            mma_bf16(acc[0][nt], a_lo[0], bhv);
            mma_bf16(acc[1][nt], a_lo[1], bhv);
            mma_bf16(acc[0][nt], a_hi[0], blv);
            mma_bf16(acc[1][nt], a_hi[1], blv);
        }
    }
}

__device__ __forceinline__ void stage_acc(char* sm, uint32_t oM, int lane, int warp_m, int warp_n,
                                          float (&acc)[2][4][4]) {
    #pragma unroll
    for (int mt = 0; mt < 2; mt++) {
        int er = warp_m * 32 + mt * 16 + (lane >> 2);
        #pragma unroll
        for (int nt = 0; nt < 4; nt++) {
            int cb = warp_n * 32 + nt * 8 + (lane & 3) * 2;
            *(float2*)(sm + oM + (uint32_t)er * 528 + cb * 4) = make_float2(acc[mt][nt][0], acc[mt][nt][1]);
            *(float2*)(sm + oM + (uint32_t)(er + 8) * 528 + cb * 4) = make_float2(acc[mt][nt][2], acc[mt][nt][3]);
        }
    }
}

// ------------------- small kernels -------------------
__global__ void k_center_sum(const float* __restrict__ pos, const int* __restrict__ batch) {
    int n = blockIdx.x * blockDim.x + threadIdx.x;
    if (n >= Nn) return;
    int lane = threadIdx.x & 31;
    int b = batch[n];
    float px = pos[n * 3 + 0], py = pos[n * 3 + 1], pz = pos[n * 3 + 2], pc = 1.f;
    #pragma unroll
    for (int off = 1; off < 32; off <<= 1) {
        int bs = __shfl_down_sync(0xffffffffu, b, off);
        float tx = __shfl_down_sync(0xffffffffu, px, off);
        float ty = __shfl_down_sync(0xffffffffu, py, off);
        float tz = __shfl_down_sync(0xffffffffu, pz, off);
        float tc = __shfl_down_sync(0xffffffffu, pc, off);
        if (lane + off < 32 && bs == b) { px += tx; py += ty; pz += tz; pc += tc; }
    }
    int bprev = __shfl_up_sync(0xffffffffu, b, 1);
    if (lane == 0 || bprev != b) {
        atomicAdd(&g_csum[b * 4 + 0], px);
        atomicAdd(&g_csum[b * 4 + 1], py);
        atomicAdd(&g_csum[b * 4 + 2], pz);
        atomicAdd(&g_csum[b * 4 + 3], pc);
    }
}

__global__ void k_center_fin() {
    int b = threadIdx.x;
    if (b < Bb) {
        float c = fmaxf(g_csum[b * 4 + 3], 1.f);
        g_center[b * 3 + 0] = g_csum[b * 4 + 0] / c;
        g_center[b * 3 + 1] = g_csum[b * 4 + 1] / c;
        g_center[b * 3 + 2] = g_csum[b * 4 + 2] / c;
    }
}

__global__ void k_dist_deg(const int* __restrict__ eidx) {
    int e = blockIdx.x * blockDim.x + threadIdx.x;
    if (e >= Ee) return;
    int r = eidx[e], c = eidx[Ee + e];
    float dx = g_posrel[c * 3 + 0] - g_posrel[r * 3 + 0];
    float dy = g_posrel[c * 3 + 1] - g_posrel[r * 3 + 1];
    float dz = g_posrel[c * 3 + 2] - g_posrel[r * 3 + 2];
    g_dist[e] = sqrtf(dx * dx + dy * dy + dz * dz);
    atomicAdd(&g_deg[r], 1);
}

__global__ void k_invdeg() {
    int n = blockIdx.x * blockDim.x + threadIdx.x;
    if (n < Nn) g_invdeg[n] = 1.f / fmaxf((float)g_deg[n], 1.f);
}

// ------------------- counting sort of edges by row -------------------
__global__ void k_scan1() {
    __shared__ int s[256];
    int i = blockIdx.x * 256 + threadIdx.x;
    int v = g_deg[i];
    s[threadIdx.x] = v;
    __syncthreads();
    for (int off = 1; off < 256; off <<= 1) {
        int t = (threadIdx.x >= off) ? s[threadIdx.x - off] : 0;
        __syncthreads();
        s[threadIdx.x] += t;
        __syncthreads();
    }
    g_rowstart[i] = s[threadIdx.x] - v;
    if (threadIdx.x == 255) g_blksum[blockIdx.x] = s[255];
}
__global__ void k_scan2() {
    __shared__ int s[256];
    int i = threadIdx.x;
    int v = g_blksum[i];
    s[i] = v;
    __syncthreads();
    for (int off = 1; off < 256; off <<= 1) {
        int t = (i >= off) ? s[i - off] : 0;
        __syncthreads();
        s[i] += t;
        __syncthreads();
    }
    g_blksum[i] = s[i] - v;
}
__global__ void k_scan3() {
    int i = blockIdx.x * blockDim.x + threadIdx.x;
    if (i < Nn) {
        int v = g_rowstart[i] + g_blksum[i >> 8];
        g_rowstart[i] = v;
        g_rowcur[i] = v;
    }
}
__global__ void k_scatter(const int* __restrict__ eidx) {
    int e = blockIdx.x * blockDim.x + threadIdx.x;
    if (e >= Ee) return;
    int r = eidx[e];
    int p = atomicAdd(&g_rowcur[r], 1);
    g_srow[p] = r;
    g_scol[p] = eidx[Ee + e];
    g_sdist[p] = g_dist[e];
}

// ------------------- weight prep into fragment-linear layout -------------------
// frag element (ks, ntile, lane): n = ntile*8 + lane/4, k0 = ks*16 + (lane%4)*2
// reg0 = pack(W[n][k0], W[n][k0+1]); reg1 = pack(W[n][k0+8], W[n][k0+9])
__global__ void k_prep_w1(const float* __restrict__ mw1) {    // 3 * 8192 frags (NT=32)
    int idx = blockIdx.x * blockDim.x + threadIdx.x;
    if (idx >= 3 * 8192) return;
    int l = idx / 8192, r = idx % 8192;
    int ks = r >> 10, ntile = (r >> 5) & 31, lane = r & 31;
    int n = ntile * 8 + (lane >> 2);
    int k0 = ks * 16 + (lane & 3) * 2;
    const float* W = mw1 + l * 257 * 128;
    float v[4];
    #pragma unroll
    for (int q = 0; q < 4; q++) {
        int k = k0 + (q >> 1) * 8 + (q & 1);
        v[q] = (n < 128) ? W[k * 128 + n] : W[(128 + k) * 128 + (n - 128)];
    }
    uint32_t h0, l0, h1, l1;
    split2(v[0], v[1], h0, l0);
    split2(v[2], v[3], h1, l1);
    g_w1f_hi[idx] = make_uint2(h0, h1);
    g_w1f_lo[idx] = make_uint2(l0, l1);
}
__global__ void k_prep_w2(const float* __restrict__ mw2) {    // 3 * 4096 frags (NT=16)
    int idx = blockIdx.x * blockDim.x + threadIdx.x;
    if (idx >= 3 * 4096) return;
    int l = idx / 4096, r = idx % 4096;
    int ks = r >> 9, ntile = (r >> 5) & 15, lane = r & 31;
    int n = ntile * 8 + (lane >> 2);
    int k0 = ks * 16 + (lane & 3) * 2;
    const float* W = mw2 + l * 16384;
    float v[4];
    #pragma unroll
    for (int q = 0; q < 4; q++) {
        int k = k0 + (q >> 1) * 8 + (q & 1);
        v[q] = W[k * 128 + n];
    }
    uint32_t h0, l0, h1, l1;
    split2(v[0], v[1], h0, l0);
    split2(v[2], v[3], h1, l1);
    g_w2f_hi[idx] = make_uint2(h0, h1);
    g_w2f_lo[idx] = make_uint2(l0, l1);
}
__global__ void k_prep_u(const float* __restrict__ uw) {      // 3 * 8192 frags (NT=16, ks 0..15)
    int idx = blockIdx.x * blockDim.x + threadIdx.x;
    if (idx >= 3 * 8192) return;
    int l = idx / 8192, r = idx % 8192;
    int ks = r >> 9, ntile = (r >> 5) & 15, lane = r & 31;
    int n = ntile * 8 + (lane >> 2);
    int k0 = ks * 16 + (lane & 3) * 2;
    const float* W = uw + l * 32768;
    float v[4];
    #pragma unroll
    for (int q = 0; q < 4; q++) {
        int k = k0 + (q >> 1) * 8 + (q & 1);
        v[q] = W[k * 128 + n];
    }
    uint32_t h0, l0, h1, l1;
    split2(v[0], v[1], h0, l0);
    split2(v[2], v[3], h1, l1);
    g_uf_hi[idx] = make_uint2(h0, h1);
    g_uf_lo[idx] = make_uint2(l0, l1);
}
__global__ void k_prep_lin(const float* __restrict__ lin_w) { // 4096 frags (NT=16)
    int idx = blockIdx.x * blockDim.x + threadIdx.x;
    if (idx >= 4096) return;
    int ks = idx >> 9, ntile = (idx >> 5) & 15, lane = idx & 31;
    int n = ntile * 8 + (lane >> 2);
    int k0 = ks * 16 + (lane & 3) * 2;
    float v[4];
    #pragma unroll
    for (int q = 0; q < 4; q++) {
        int k = k0 + (q >> 1) * 8 + (q & 1);
        v[q] = lin_w[k * 128 + n];
    }
    uint32_t h0, l0, h1, l1;
    split2(v[0], v[1], h0, l0);
    split2(v[2], v[3], h1, l1);
    g_linf_hi[idx] = make_uint2(h0, h1);
    g_linf_lo[idx] = make_uint2(l0, l1);
}

// ------------------- smem layout: header + A hi/lo only -------------------
#define GOFF_BIAS 0
#define GOFF_AUX  512
#define GOFF_IDX  2048
#define GOFF_AHI  4096
#define G_ASZ     34816
#define GOFF_ALO  (GOFF_AHI + G_ASZ)
#define G_SMEM    (GOFF_ALO + G_ASZ)   // 73728 -> occupancy 2

// ------------------- k_input via HMMA -------------------
__global__ void __launch_bounds__(512, 2)
k_input_mma(const float* __restrict__ pos, const int* __restrict__ z,
            const int* __restrict__ batch, const float* __restrict__ emb,
            const float* __restrict__ lin_w, const float* __restrict__ bias) {
    extern __shared__ __align__(16) char sm[];
    uint32_t sbase = smem_u32(sm);
    int tid = threadIdx.x;
    int lane = tid & 31;
    int wid = tid >> 5;
    int n0 = blockIdx.x * 128;
    float* bs  = (float*)(sm + GOFF_BIAS);
    float* tl  = (float*)(sm + GOFF_AUX);
    float* prs = (float*)(sm + GOFF_IDX);
    int*   zs  = (int*)(sm + GOFF_IDX + 1536);

    if (tid < 128) {
        bs[tid] = bias[tid];
        int n = n0 + tid;
        int b = batch[n];
        #pragma unroll
        for (int d = 0; d < 3; d++) {
            float v = pos[n * 3 + d] - g_center[b * 3 + d];
            prs[tid * 3 + d] = v;
            g_posrel[n * 3 + d] = v;
        }
        zs[tid] = z[n];
    } else if (tid >= 128 && tid < 128 + 384) {
        int i = tid - 128;
        tl[i] = lin_w[(128 + (i >> 7)) * 128 + (i & 127)];
    }
    __syncthreads();

    #pragma unroll
    for (int it = 0; it < 4; it++) {
        int cid = tid + it * 512;
        int r = cid >> 4, kc = cid & 15;
        const float4* ep = (const float4*)(emb + (size_t)zs[r] * 128) + kc * 2;
        float4 e0 = ep[0], e1 = ep[1];
        uint32_t h0, l0, h1, l1, h2, l2, h3, l3;
        split2(e0.x, e0.y, h0, l0);
        split2(e0.z, e0.w, h1, l1);
        split2(e1.x, e1.y, h2, l2);
        split2(e1.z, e1.w, h3, l3);
        uint32_t o = (uint32_t)r * 272 + kc * 16;
        *(uint4*)(sm + GOFF_AHI + o) = make_uint4(h0, h1, h2, h3);
        *(uint4*)(sm + GOFF_ALO + o) = make_uint4(l0, l1, l2, l3);
    }
    __syncthreads();

    float acc[2][4][4];
    #pragma unroll
    for (int mt = 0; mt < 2; mt++)
        #pragma unroll
        for (int nt = 0; nt < 4; nt++)
            #pragma unroll
            for (int q = 0; q < 4; q++) acc[mt][nt][q] = 0.f;
    mma3_gf(sbase, GOFF_AHI, GOFF_ALO, g_linf_hi, g_linf_lo, 16, (wid >> 2) * 4, 0,
            lane, wid & 3, acc);
    __syncthreads();
    stage_acc(sm, GOFF_AHI, lane, wid & 3, wid >> 2, acc);
    __syncthreads();

    #pragma unroll
    for (int it = 0; it < 8; it++) {
        int cid = tid + it * 512;
        int r = cid >> 5, c4 = cid & 31;
        float4 v = *(float4*)(sm + GOFF_AHI + (uint32_t)r * 528 + c4 * 16);
        float p0 = prs[r * 3 + 0], p1 = prs[r * 3 + 1], p2 = prs[r * 3 + 2];
        int c = c4 * 4;
        v.x += bs[c + 0] + p0 * tl[c + 0] + p1 * tl[128 + c + 0] + p2 * tl[256 + c + 0];
        v.y += bs[c + 1] + p0 * tl[c + 1] + p1 * tl[128 + c + 1] + p2 * tl[256 + c + 1];
        v.z += bs[c + 2] + p0 * tl[c + 2] + p1 * tl[128 + c + 2] + p2 * tl[256 + c + 2];
        v.w += bs[c + 3] + p0 * tl[c + 3] + p1 * tl[128 + c + 3] + p2 * tl[256 + c + 3];
        size_t nrow = (size_t)(n0 + r);
        ((float4*)(g_x0 + nrow * 128))[c4] = v;
        uint32_t h01, l01, h23, l23;
        split2(v.x, v.y, h01, l01);
        split2(v.z, v.w, h23, l23);
        ((uint2*)g_xhi)[nrow * 32 + c4] = make_uint2(h01, h23);
        ((uint2*)g_xlo)[nrow * 32 + c4] = make_uint2(l01, l23);
    }
}

// ------------------- k_xab via HMMA -------------------
__global__ void __launch_bounds__(512, 2)
k_xab_mma(const float* __restrict__ b1, int layer) {
    extern __shared__ __align__(16) char sm[];
    uint32_t sbase = smem_u32(sm);
    int tid = threadIdx.x;
    int lane = tid & 31;
    int wid = tid >> 5;
    int n0 = blockIdx.x * 128;
    int half = blockIdx.y;
    float* bs = (float*)(sm + GOFF_BIAS);
    if (tid < 128) bs[tid] = (half == 0) ? b1[tid] : 0.f;

    const uint4* ah = (const uint4*)g_xhi + (size_t)n0 * 16;
    const uint4* al = (const uint4*)g_xlo + (size_t)n0 * 16;
    #pragma unroll
    for (int it = 0; it < 4; it++) {
        int cid = tid + it * 512;
        int r = cid >> 4, c = cid & 15;
        uint32_t o = (uint32_t)r * 272 + c * 16;
        *(uint4*)(sm + GOFF_AHI + o) = ah[r * 16 + c];
        *(uint4*)(sm + GOFF_ALO + o) = al[r * 16 + c];
    }
    __syncthreads();

    float acc[2][4][4];
    #pragma unroll
    for (int mt = 0; mt < 2; mt++)
        #pragma unroll
        for (int nt = 0; nt < 4; nt++)
            #pragma unroll
            for (int q = 0; q < 4; q++) acc[mt][nt][q] = 0.f;
    mma3_gf(sbase, GOFF_AHI, GOFF_ALO, g_w1f_hi + layer * 8192, g_w1f_lo + layer * 8192,
            32, half * 16 + (wid >> 2) * 4, 0, lane, wid & 3, acc);
    __syncthreads();
    stage_acc(sm, GOFF_AHI, lane, wid & 3, wid >> 2, acc);
    __syncthreads();

    float* out = half == 0 ? g_xa : g_xb;
    #pragma unroll
    for (int it = 0; it < 8; it++) {
        int cid = tid + it * 512;
        int r = cid >> 5, c4 = cid & 31;
        float4 v = *(float4*)(sm + GOFF_AHI + (uint32_t)r * 528 + c4 * 16);
        v.x += bs[c4 * 4 + 0]; v.y += bs[c4 * 4 + 1];
        v.z += bs[c4 * 4 + 2]; v.w += bs[c4 * 4 + 3];
        ((float4*)(out + (size_t)(n0 + r) * 128))[c4] = v;
    }
}

// ------------------- k_update via HMMA -------------------
__global__ void __launch_bounds__(512, 2)
k_update_mma(const float* __restrict__ bias, int layer) {
    extern __shared__ __align__(16) char sm[];
    uint32_t sbase = smem_u32(sm);
    int tid = threadIdx.x;
    int lane = tid & 31;
    int wid = tid >> 5;
    int n0 = blockIdx.x * 128;
    float* bs = (float*)(sm + GOFF_BIAS);
    float* idg = (float*)(sm + GOFF_AUX);
    if (tid < 128) {
        bs[tid] = bias[tid];
        idg[tid] = g_invdeg[n0 + tid];
    }

    const uint2* uf_hi = g_uf_hi + layer * 8192;
    const uint2* uf_lo = g_uf_lo + layer * 8192;

    float acc[2][4][4];
    #pragma unroll
    for (int mt = 0; mt < 2; mt++)
        #pragma unroll
        for (int nt = 0; nt < 4; nt++)
            #pragma unroll
            for (int q = 0; q < 4; q++) acc[mt][nt][q] = 0.f;

    // pass 0: A = x hi/lo, B = U^T ks 0..7
    {
        const uint4* ah = (const uint4*)g_xhi + (size_t)n0 * 16;
        const uint4* al = (const uint4*)g_xlo + (size_t)n0 * 16;
        #pragma unroll
        for (int it = 0; it < 4; it++) {
            int cid = tid + it * 512;
            int r = cid >> 4, c = cid & 15;
            uint32_t o = (uint32_t)r * 272 + c * 16;
            *(uint4*)(sm + GOFF_AHI + o) = ah[r * 16 + c];
            *(uint4*)(sm + GOFF_ALO + o) = al[r * 16 + c];
        }
        __syncthreads();
        mma3_gf(sbase, GOFF_AHI, GOFF_ALO, uf_hi, uf_lo, 16, (wid >> 2) * 4, 0,
                lane, wid & 3, acc);
        __syncthreads();
    }
    // pass 1: A = msum*invdeg, B = U^T ks 8..15
    {
        #pragma unroll
        for (int it = 0; it < 4; it++) {
            int cid = tid + it * 512;
            int r = cid >> 4, c = cid & 15;
            uint32_t o = (uint32_t)r * 272 + c * 16;
            const float4* mp = (const float4*)(g_msum + (size_t)(n0 + r) * 128) + c * 2;
            float s = idg[r];
            float4 m0 = mp[0], m1 = mp[1];
            uint32_t h0, l0, h1, l1, h2, l2, h3, l3;
            split2(m0.x * s, m0.y * s, h0, l0);
            split2(m0.z * s, m0.w * s, h1, l1);
            split2(m1.x * s, m1.y * s, h2, l2);
            split2(m1.z * s, m1.w * s, h3, l3);
            *(uint4*)(sm + GOFF_AHI + o) = make_uint4(h0, h1, h2, h3);
            *(uint4*)(sm + GOFF_ALO + o) = make_uint4(l0, l1, l2, l3);
        }
        __syncthreads();
        mma3_gf(sbase, GOFF_AHI, GOFF_ALO, uf_hi, uf_lo, 16, (wid >> 2) * 4, 8,
                lane, wid & 3, acc);
        __syncthreads();
    }

    stage_acc(sm, GOFF_AHI, lane, wid & 3, wid >> 2, acc);
    __syncthreads();

    #pragma unroll
    for (int it = 0; it < 8; it++) {
        int cid = tid + it * 512;
        int r = cid >> 5, c4 = cid & 31;
        float4 v = *(float4*)(sm + GOFF_AHI + (uint32_t)r * 528 + c4 * 16);
        v.x = fmaxf(v.x + bs[c4 * 4 + 0], 0.f);
        v.y = fmaxf(v.y + bs[c4 * 4 + 1], 0.f);
        v.z = fmaxf(v.z + bs[c4 * 4 + 2], 0.f);
        v.w = fmaxf(v.w + bs[c4 * 4 + 3], 0.f);
        size_t nrow = (size_t)(n0 + r);
        ((float4*)(g_x0 + nrow * 128))[c4] = v;
        uint32_t h01, l01, h23, l23;
        split2(v.x, v.y, h01, l01);
        split2(v.z, v.w, h23, l23);
        ((uint2*)g_xhi)[nrow * 32 + c4] = make_uint2(h01, h23);
        ((uint2*)g_xlo)[nrow * 32 + c4] = make_uint2(l01, l23);
    }
}

// ------------------- HMMA edge kernel (sorted edges, segmented epilogue) ---------------
#define EOFF_ROWS 0
#define EOFF_COLS 512
#define EOFF_DIST 1024
#define EOFF_BIAS 1536
#define EOFF_W1C  2048
#define EOFF_SEG  2560
#define EOFF_AHI  4096
#define E_ASZ     34816
#define EOFF_ALO  (EOFF_AHI + E_ASZ)
#define E_SMEM    (EOFF_ALO + E_ASZ)   // 73728 -> occupancy 2

__global__ void __launch_bounds__(512, 2)
k_edge_mma(const float* __restrict__ w1c, const float* __restrict__ b2, int layer) {
    extern __shared__ __align__(16) char sm[];
    uint32_t sbase = smem_u32(sm);
    int tid = threadIdx.x;
    int lane = tid & 31;
    int wid = tid >> 5;
    int e0 = blockIdx.x * 128;

    int*   rows = (int*)(sm + EOFF_ROWS);
    int*   cols = (int*)(sm + EOFF_COLS);
    float* ds   = (float*)(sm + EOFF_DIST);
    float* bs   = (float*)(sm + EOFF_BIAS);
    float* ws   = (float*)(sm + EOFF_W1C);
    int*   wcnt = (int*)(sm + EOFF_SEG);
    int*   woff = wcnt + 4;
    int*   nsegp = woff + 4;
    int*   segstart = nsegp + 1;

    if (tid < 128) {
        rows[tid] = g_srow[e0 + tid];
        cols[tid] = g_scol[e0 + tid];
        ds[tid]   = g_sdist[e0 + tid];
        bs[tid]   = b2[tid];
        ws[tid]   = w1c[tid];
    }
    __syncthreads();

    // A build: h = relu(xa[col] + xb[row] + dist*w1c), split hi/lo
    #pragma unroll
    for (int it = 0; it < 4; it++) {
        int cid = tid + it * 512;
        int e = cid >> 4;
        int kc = cid & 15;
        const float4* pa = (const float4*)(g_xa + (size_t)cols[e] * 128) + kc * 2;
        const float4* pb = (const float4*)(g_xb + (size_t)rows[e] * 128) + kc * 2;
        float d = ds[e];
        float4 a0 = pa[0], a1 = pa[1];
        float4 b0 = pb[0], b1 = pb[1];
        int k0 = kc * 8;
        float v0 = fmaxf(a0.x + b0.x + d * ws[k0 + 0], 0.f);
        float v1 = fmaxf(a0.y + b0.y + d * ws[k0 + 1], 0.f);
        float v2 = fmaxf(a0.z + b0.z + d * ws[k0 + 2], 0.f);
        float v3 = fmaxf(a0.w + b0.w + d * ws[k0 + 3], 0.f);
        float v4 = fmaxf(a1.x + b1.x + d * ws[k0 + 4], 0.f);
        float v5 = fmaxf(a1.y + b1.y + d * ws[k0 + 5], 0.f);
        float v6 = fmaxf(a1.z + b1.z + d * ws[k0 + 6], 0.f);
        float v7 = fmaxf(a1.w + b1.w + d * ws[k0 + 7], 0.f);
        uint32_t h0, l0, h1, l1, h2, l2, h3, l3;
        split2(v0, v1, h0, l0);
        split2(v2, v3, h1, l1);
        split2(v4, v5, h2, l2);
        split2(v6, v7, h3, l3);
        uint32_t o = (uint32_t)e * 272 + kc * 16;
        *(uint4*)(sm + EOFF_AHI + o) = make_uint4(h0, h1, h2, h3);
        *(uint4*)(sm + EOFF_ALO + o) = make_uint4(l0, l1, l2, l3);
    }
    __syncthreads();

    float acc[2][4][4];
    #pragma unroll
    for (int mt = 0; mt < 2; mt++)
        #pragma unroll
        for (int nt = 0; nt < 4; nt++)
            #pragma unroll
            for (int q = 0; q < 4; q++) acc[mt][nt][q] = 0.f;
    mma3_gf(sbase, EOFF_AHI, EOFF_ALO, g_w2f_hi + layer * 4096, g_w2f_lo + layer * 4096,
            16, (wid >> 2) * 4, 0, lane, wid & 3, acc);
    __syncthreads();
    stage_acc(sm, EOFF_AHI, lane, wid & 3, wid >> 2, acc);

    // segment detection on sorted rows (warps 0-3)
    int f = 0, pre = 0;
    if (wid < 4) {
        f = (tid == 0) || (rows[tid] != rows[tid - 1]);
        unsigned m = __ballot_sync(0xffffffffu, f);
        pre = __popc(m & ((1u << lane) - 1u));
        if (lane == 0) wcnt[wid] = __popc(m);
    }
    __syncthreads();
    if (tid == 0) {
        int s = 0;
        #pragma unroll
        for (int w = 0; w < 4; w++) { woff[w] = s; s += wcnt[w]; }
        nsegp[0] = s;
        segstart[s] = 128;
    }
    __syncthreads();
    if (wid < 4 && f) segstart[woff[wid] + pre] = tid;
    __syncthreads();

    int nseg = nsegp[0];
    for (int item = tid; item < nseg * 32; item += 512) {
        int s = item >> 5, c4 = item & 31;
        int rbeg = segstart[s], rend = segstart[s + 1];
        float4 bb = *(float4*)(bs + c4 * 4);
        float m0 = 0.f, m1 = 0.f, m2 = 0.f, m3 = 0.f;
        for (int r = rbeg; r < rend; r++) {
            float4 v = *(float4*)(sm + EOFF_AHI + (uint32_t)r * 528 + c4 * 16);
            m0 += fmaxf(v.x + bb.x, 0.f);
            m1 += fmaxf(v.y + bb.y, 0.f);
            m2 += fmaxf(v.z + bb.z, 0.f);
            m3 += fmaxf(v.w + bb.w, 0.f);
        }
        float* p = g_msum + (size_t)rows[rbeg] * 128 + c4 * 4;
        asm volatile("red.global.add.v4.f32 [%0], {%1,%2,%3,%4};"
                     :: "l"(p), "f"(m0), "f"(m1), "f"(m2), "f"(m3) : "memory");
    }
}

// ------------------- readout pooling -------------------
__global__ void k_pool(const int* __restrict__ batch, const int* __restrict__ ntype) {
    int idx = blockIdx.x * blockDim.x + threadIdx.x;
    int n = idx >> 5;
    int q = idx & 31;
    if (n >= Nn) return;
    if (ntype[n] == 1) {
        float4 v = ((const float4*)g_x0)[n * 32 + q];
        float* p = &g_gsum[batch[n] * 128 + q * 4];
        asm volatile("red.global.add.v4.f32 [%0], {%1,%2,%3,%4};"
                     :: "l"(p), "f"(v.x), "f"(v.y), "f"(v.z), "f"(v.w) : "memory");
    }
}

__global__ void k_ligcnt(const int* __restrict__ batch, const int* __restrict__ ntype) {
    int n = blockIdx.x * blockDim.x + threadIdx.x;
    if (n < Nn && ntype[n] == 1) atomicAdd(&g_ligcnt[batch[n]], 1.f);
}

__global__ void __launch_bounds__(128)
k_readout(const float* __restrict__ rw1, const float* __restrict__ rb1,
          const float* __restrict__ rw2, const float* __restrict__ rb2,
          float* __restrict__ out) {
    __shared__ __align__(16) float gs[128];
    __shared__ float red_s[128];
    int b = blockIdx.x;
    int tid = threadIdx.x;
    float cnt = fmaxf(g_ligcnt[b], 1.f);
    gs[tid] = g_gsum[b * 128 + tid] / cnt;
    __syncthreads();

    int j = tid;
    const float* Wj = rw1 + j;
    const float4* gs4 = (const float4*)gs;
    float acc = rb1[j];
    for (int kk = 0; kk < 32; kk++) {
        float w0 = Wj[(kk * 4 + 0) * 128];
        float w1 = Wj[(kk * 4 + 1) * 128];
        float w2 = Wj[(kk * 4 + 2) * 128];
        float w3 = Wj[(kk * 4 + 3) * 128];
        float4 gv = gs4[kk];
        acc += gv.x * w0 + gv.y * w1 + gv.z * w2 + gv.w * w3;
    }
    float hg = fmaxf(acc, 0.f);
    red_s[tid] = hg * rw2[j];
    __syncthreads();
    for (int s = 64; s > 0; s >>= 1) {
        if (tid < s) red_s[tid] += red_s[tid + s];
        __syncthreads();
    }
    if (tid == 0) out[b] = red_s[0] + rb2[0];
}

// ------------------- launch -------------------
extern "C" void kernel_launch(void* const* d_in, const int* in_sizes, int n_in,
                              void* d_out, int out_size) {
    const float* pos   = (const float*)d_in[0];
    const int*   z     = (const int*)d_in[1];
    const int*   batch = (const int*)d_in[2];
    const int*   eidx  = (const int*)d_in[3];
    const int*   ntype = (const int*)d_in[4];
    const float* emb   = (const float*)d_in[5];
    const float* lin_w = (const float*)d_in[6];
    const float* lin_b = (const float*)d_in[7];
    const float* mw1   = (const float*)d_in[8];
    const float* mb1   = (const float*)d_in[9];
    const float* mw2   = (const float*)d_in[10];
    const float* mb2   = (const float*)d_in[11];
    const float* uw    = (const float*)d_in[12];
    const float* ub    = (const float*)d_in[13];
    const float* rw1   = (const float*)d_in[14];
    const float* rb1   = (const float*)d_in[15];
    const float* rw2   = (const float*)d_in[16];
    const float* rb2   = (const float*)d_in[17];
    float* out = (float*)d_out;

    cudaFuncSetAttribute(k_edge_mma, cudaFuncAttributeMaxDynamicSharedMemorySize, E_SMEM);
    cudaFuncSetAttribute(k_xab_mma, cudaFuncAttributeMaxDynamicSharedMemorySize, G_SMEM);
    cudaFuncSetAttribute(k_update_mma, cudaFuncAttributeMaxDynamicSharedMemorySize, G_SMEM);
    cudaFuncSetAttribute(k_input_mma, cudaFuncAttributeMaxDynamicSharedMemorySize, G_SMEM);

    void *p_csum, *p_deg, *p_msum, *p_gsum, *p_lig;
    cudaGetSymbolAddress(&p_csum, g_csum);
    cudaGetSymbolAddress(&p_deg, g_deg);
    cudaGetSymbolAddress(&p_msum, g_msum);
    cudaGetSymbolAddress(&p_gsum, g_gsum);
    cudaGetSymbolAddress(&p_lig, g_ligcnt);

    cudaMemsetAsync(p_csum, 0, Bb * 4 * sizeof(float));
    cudaMemsetAsync(p_deg, 0, Nn * sizeof(int));
    cudaMemsetAsync(p_gsum, 0, Bb * Hh * sizeof(float));
    cudaMemsetAsync(p_lig, 0, Bb * sizeof(float));

    // weight preps (all layers, fragment-linear)
    k_prep_w1<<<(3 * 8192) / 256, 256>>>(mw1);
    k_prep_w2<<<(3 * 4096) / 256, 256>>>(mw2);
    k_prep_u<<<(3 * 8192) / 256, 256>>>(uw);
    k_prep_lin<<<4096 / 256, 256>>>(lin_w);

    k_center_sum<<<Nn / 256, 256>>>(pos, batch);
    k_center_fin<<<1, 64>>>();
    k_input_mma<<<Nn / 128, 512, G_SMEM>>>(pos, z, batch, emb, lin_w, lin_b);
    k_dist_deg<<<Ee / 256, 256>>>(eidx);
    k_invdeg<<<Nn / 256, 256>>>();

    // counting sort of edges by destination row
    k_scan1<<<256, 256>>>();
    k_scan2<<<1, 256>>>();
    k_scan3<<<Nn / 256, 256>>>();
    k_scatter<<<Ee / 256, 256>>>(eidx);

    for (int l = 0; l < 3; l++) {
        const float* W1 = mw1 + l * 257 * 128;
        k_xab_mma<<<dim3(Nn / 128, 2), 512, G_SMEM>>>(mb1 + l * 128, l);
        cudaMemsetAsync(p_msum, 0, (size_t)Nn * Hh * sizeof(float));
        k_edge_mma<<<Ee / 128, 512, E_SMEM>>>(W1 + 256 * 128, mb2 + l * 128, l);
        k_update_mma<<<Nn / 128, 512, G_SMEM>>>(ub + l * 128, l);
    }

    k_pool<<<Nn * 32 / 256, 256>>>(batch, ntype);
    k_ligcnt<<<Nn / 256, 256>>>(batch, ntype);
    k_readout<<<Bb, 128>>>(rw1, rb1, rw2, rb2, out);
}

// round 10
// speedup vs baseline: 3.2518x; 1.0277x over previous
#include <cuda_runtime.h>
#include <cuda_bf16.h>
#include <math.h>
#include <stdint.h>

#define Nn 65536
#define Ee 1048576
#define Bb 64
#define Hh 128

// ------------------- scratch (static device globals; no allocation) -------------------
__device__ float g_csum[Bb * 4];
__device__ float g_center[Bb * 3];
__device__ float g_posrel[Nn * 3];
__device__ float g_x0[Nn * Hh];
__device__ uint32_t g_xhi[Nn * 64];
__device__ uint32_t g_xlo[Nn * 64];
__device__ float g_xa[Nn * Hh];
__device__ float g_xb[Nn * Hh];
__device__ float g_msum[Nn * Hh];
__device__ int   g_deg[Nn];
__device__ float g_invdeg[Nn];
__device__ float g_gsum[Bb * Hh];
__device__ float g_ligcnt[Bb];
// edge sort scratch
__device__ int   g_rowstart[Nn];
__device__ int   g_rowcur[Nn];
__device__ int   g_blksum[256];
__device__ int   g_srow[Ee];
__device__ int   g_scol[Ee];
__device__ float g_sdist[Ee];
// fragment-linear weights (bf16x2 pairs per lane), hi/lo split
__device__ uint2 g_w1f_hi[3 * 8192], g_w1f_lo[3 * 8192];   // W1^T 256n x 128k, NT=32
__device__ uint2 g_w2f_hi[3 * 4096], g_w2f_lo[3 * 4096];   // W2^T 128n x 128k, NT=16
__device__ uint2 g_uf_hi[3 * 8192],  g_uf_lo[3 * 8192];    // U^T  128n x 256k, NT=16
__device__ uint2 g_linf_hi[4096],    g_linf_lo[4096];      // lin^T 128n x 128k, NT=16

// ------------------- helpers -------------------
__device__ __forceinline__ uint32_t smem_u32(const void* p) {
    uint32_t a;
    asm("{ .reg .u64 t; cvta.to.shared.u64 t, %1; cvt.u32.u64 %0, t; }" : "=r"(a) : "l"(p));
    return a;
}
__device__ __forceinline__ void ldsm_x4(uint32_t* r, uint32_t addr) {
    asm volatile("ldmatrix.sync.aligned.m8n8.x4.shared.b16 {%0,%1,%2,%3}, [%4];"
                 : "=r"(r[0]), "=r"(r[1]), "=r"(r[2]), "=r"(r[3]) : "r"(addr));
}
__device__ __forceinline__ void mma_bf16(float* d, const uint32_t* a, const uint32_t* b) {
    asm volatile("mma.sync.aligned.m16n8k16.row.col.f32.bf16.bf16.f32 "
                 "{%0,%1,%2,%3}, {%4,%5,%6,%7}, {%8,%9}, {%0,%1,%2,%3};"
                 : "+f"(d[0]), "+f"(d[1]), "+f"(d[2]), "+f"(d[3])
                 : "r"(a[0]), "r"(a[1]), "r"(a[2]), "r"(a[3]), "r"(b[0]), "r"(b[1]));
}
__device__ __forceinline__ void split2(float v0, float v1, uint32_t& hi, uint32_t& lo) {
    __nv_bfloat162 h = __floats2bfloat162_rn(v0, v1);
    uint32_t hu = *(uint32_t*)&h;
    float h0 = __uint_as_float(hu << 16);
    float h1 = __uint_as_float(hu & 0xFFFF0000u);
    __nv_bfloat162 l = __floats2bfloat162_rn(v0 - h0, v1 - h1);
    hi = hu; lo = *(uint32_t*)&l;
}

// 3-term MMA core with B from fragment-linear global arrays.
__device__ __forceinline__ void mma3_gf(uint32_t sbase, uint32_t oAhi, uint32_t oAlo,
                                        const uint2* __restrict__ bfh,
                                        const uint2* __restrict__ bfl,
                                        int NT, int nt_base, int ks_base,
                                        int lane, int warp_m,
                                        float (&acc)[2][4][4]) {
    uint32_t a_base = sbase + oAhi + (uint32_t)(warp_m * 32 + (lane & 15)) * 272 + (uint32_t)(lane >> 4) * 16;
    uint32_t dA = oAlo - oAhi;
    for (int ks = 0; ks < 8; ks++) {
        uint32_t kb = (uint32_t)ks * 32;
        uint32_t a_hi[2][4], a_lo[2][4];
        #pragma unroll
        for (int mt = 0; mt < 2; mt++) {
            uint32_t ad = a_base + (uint32_t)(mt * 16) * 272 + kb;
            ldsm_x4(a_hi[mt], ad);
            ldsm_x4(a_lo[mt], ad + dA);
        }
        int fks = (ks_base + ks) * NT + nt_base;
        #pragma unroll
        for (int nt = 0; nt < 4; nt++) {
            uint2 bh = __ldg(bfh + (size_t)(fks + nt) * 32 + lane);
            uint2 bl = __ldg(bfl + (size_t)(fks + nt) * 32 + lane);
            uint32_t bhv[2] = {bh.x, bh.y};
            uint32_t blv[2] = {bl.x, bl.y};
            mma_bf16(acc[0][nt], a_hi[0], bhv);
            mma_bf16(acc[1][nt], a_hi[1], bhv);
            mma_bf16(acc[0][nt], a_lo[0], bhv);
            mma_bf16(acc[1][nt], a_lo[1], bhv);
            mma_bf16(acc[0][nt], a_hi[0], blv);
            mma_bf16(acc[1][nt], a_hi[1], blv);
        }
    }
}

__device__ __forceinline__ void stage_acc(char* sm, uint32_t oM, int lane, int warp_m, int warp_n,
                                          float (&acc)[2][4][4]) {
    #pragma unroll
    for (int mt = 0; mt < 2; mt++) {
        int er = warp_m * 32 + mt * 16 + (lane >> 2);
        #pragma unroll
        for (int nt = 0; nt < 4; nt++) {
            int cb = warp_n * 32 + nt * 8 + (lane & 3) * 2;
            *(float2*)(sm + oM + (uint32_t)er * 528 + cb * 4) = make_float2(acc[mt][nt][0], acc[mt][nt][1]);
            *(float2*)(sm + oM + (uint32_t)(er + 8) * 528 + cb * 4) = make_float2(acc[mt][nt][2], acc[mt][nt][3]);
        }
    }
}

// write xa/xb directly from fragments (bias optional)
__device__ __forceinline__ void write_frag_out(float* out, int n0, int lane, int warp_m, int warp_n,
                                               const float* bsm, float (&acc)[2][4][4]) {
    #pragma unroll
    for (int mt = 0; mt < 2; mt++) {
        int er = n0 + warp_m * 32 + mt * 16 + (lane >> 2);
        #pragma unroll
        for (int nt = 0; nt < 4; nt++) {
            int cb = warp_n * 32 + nt * 8 + (lane & 3) * 2;
            float b0 = bsm ? bsm[cb] : 0.f;
            float b1 = bsm ? bsm[cb + 1] : 0.f;
            *(float2*)(out + (size_t)er * 128 + cb) = make_float2(acc[mt][nt][0] + b0, acc[mt][nt][1] + b1);
            *(float2*)(out + (size_t)(er + 8) * 128 + cb) = make_float2(acc[mt][nt][2] + b0, acc[mt][nt][3] + b1);
        }
    }
}

// ------------------- small kernels -------------------
__global__ void k_center_sum(const float* __restrict__ pos, const int* __restrict__ batch) {
    int n = blockIdx.x * blockDim.x + threadIdx.x;
    if (n >= Nn) return;
    int lane = threadIdx.x & 31;
    int b = batch[n];
    float px = pos[n * 3 + 0], py = pos[n * 3 + 1], pz = pos[n * 3 + 2], pc = 1.f;
    #pragma unroll
    for (int off = 1; off < 32; off <<= 1) {
        int bs = __shfl_down_sync(0xffffffffu, b, off);
        float tx = __shfl_down_sync(0xffffffffu, px, off);
        float ty = __shfl_down_sync(0xffffffffu, py, off);
        float tz = __shfl_down_sync(0xffffffffu, pz, off);
        float tc = __shfl_down_sync(0xffffffffu, pc, off);
        if (lane + off < 32 && bs == b) { px += tx; py += ty; pz += tz; pc += tc; }
    }
    int bprev = __shfl_up_sync(0xffffffffu, b, 1);
    if (lane == 0 || bprev != b) {
        atomicAdd(&g_csum[b * 4 + 0], px);
        atomicAdd(&g_csum[b * 4 + 1], py);
        atomicAdd(&g_csum[b * 4 + 2], pz);
        atomicAdd(&g_csum[b * 4 + 3], pc);
    }
}

__global__ void k_center_fin() {
    int b = threadIdx.x;
    if (b < Bb) {
        float c = fmaxf(g_csum[b * 4 + 3], 1.f);
        g_center[b * 3 + 0] = g_csum[b * 4 + 0] / c;
        g_center[b * 3 + 1] = g_csum[b * 4 + 1] / c;
        g_center[b * 3 + 2] = g_csum[b * 4 + 2] / c;
    }
}

__global__ void k_deg(const int* __restrict__ eidx) {
    int e = blockIdx.x * blockDim.x + threadIdx.x;
    if (e < Ee) atomicAdd(&g_deg[eidx[e]], 1);
}

// ------------------- counting sort (scan + scatter; scatter computes dist) ------------
__global__ void k_scan1() {
    __shared__ int s[256];
    int i = blockIdx.x * 256 + threadIdx.x;
    int v = g_deg[i];
    s[threadIdx.x] = v;
    __syncthreads();
    for (int off = 1; off < 256; off <<= 1) {
        int t = (threadIdx.x >= off) ? s[threadIdx.x - off] : 0;
        __syncthreads();
        s[threadIdx.x] += t;
        __syncthreads();
    }
    g_rowstart[i] = s[threadIdx.x] - v;
    if (threadIdx.x == 255) g_blksum[blockIdx.x] = s[255];
}
__global__ void k_scan2() {
    __shared__ int s[256];
    int i = threadIdx.x;
    int v = g_blksum[i];
    s[i] = v;
    __syncthreads();
    for (int off = 1; off < 256; off <<= 1) {
        int t = (i >= off) ? s[i - off] : 0;
        __syncthreads();
        s[i] += t;
        __syncthreads();
    }
    g_blksum[i] = s[i] - v;
}
__global__ void k_scan3() {
    int i = blockIdx.x * blockDim.x + threadIdx.x;
    if (i < Nn) {
        int v = g_rowstart[i] + g_blksum[i >> 8];
        g_rowstart[i] = v;
        g_rowcur[i] = v;
        g_invdeg[i] = 1.f / fmaxf((float)g_deg[i], 1.f);
    }
}
__global__ void k_scatter(const int* __restrict__ eidx) {
    int e = blockIdx.x * blockDim.x + threadIdx.x;
    if (e >= Ee) return;
    int r = eidx[e], c = eidx[Ee + e];
    int p = atomicAdd(&g_rowcur[r], 1);
    float dx = g_posrel[c * 3 + 0] - g_posrel[r * 3 + 0];
    float dy = g_posrel[c * 3 + 1] - g_posrel[r * 3 + 1];
    float dz = g_posrel[c * 3 + 2] - g_posrel[r * 3 + 2];
    g_srow[p] = r;
    g_scol[p] = c;
    g_sdist[p] = sqrtf(dx * dx + dy * dy + dz * dz);
}

// ------------------- weight prep into fragment-linear layout -------------------
__global__ void k_prep_w1(const float* __restrict__ mw1) {
    int idx = blockIdx.x * blockDim.x + threadIdx.x;
    if (idx >= 3 * 8192) return;
    int l = idx / 8192, r = idx % 8192;
    int ks = r >> 10, ntile = (r >> 5) & 31, lane = r & 31;
    int n = ntile * 8 + (lane >> 2);
    int k0 = ks * 16 + (lane & 3) * 2;
    const float* W = mw1 + l * 257 * 128;
    float v[4];
    #pragma unroll
    for (int q = 0; q < 4; q++) {
        int k = k0 + (q >> 1) * 8 + (q & 1);
        v[q] = (n < 128) ? W[k * 128 + n] : W[(128 + k) * 128 + (n - 128)];
    }
    uint32_t h0, l0, h1, l1;
    split2(v[0], v[1], h0, l0);
    split2(v[2], v[3], h1, l1);
    g_w1f_hi[idx] = make_uint2(h0, h1);
    g_w1f_lo[idx] = make_uint2(l0, l1);
}
__global__ void k_prep_w2(const float* __restrict__ mw2) {
    int idx = blockIdx.x * blockDim.x + threadIdx.x;
    if (idx >= 3 * 4096) return;
    int l = idx / 4096, r = idx % 4096;
    int ks = r >> 9, ntile = (r >> 5) & 15, lane = r & 31;
    int n = ntile * 8 + (lane >> 2);
    int k0 = ks * 16 + (lane & 3) * 2;
    const float* W = mw2 + l * 16384;
    float v[4];
    #pragma unroll
    for (int q = 0; q < 4; q++) {
        int k = k0 + (q >> 1) * 8 + (q & 1);
        v[q] = W[k * 128 + n];
    }
    uint32_t h0, l0, h1, l1;
    split2(v[0], v[1], h0, l0);
    split2(v[2], v[3], h1, l1);
    g_w2f_hi[idx] = make_uint2(h0, h1);
    g_w2f_lo[idx] = make_uint2(l0, l1);
}
__global__ void k_prep_u(const float* __restrict__ uw) {
    int idx = blockIdx.x * blockDim.x + threadIdx.x;
    if (idx >= 3 * 8192) return;
    int l = idx / 8192, r = idx % 8192;
    int ks = r >> 9, ntile = (r >> 5) & 15, lane = r & 31;
    int n = ntile * 8 + (lane >> 2);
    int k0 = ks * 16 + (lane & 3) * 2;
    const float* W = uw + l * 32768;
    float v[4];
    #pragma unroll
    for (int q = 0; q < 4; q++) {
        int k = k0 + (q >> 1) * 8 + (q & 1);
        v[q] = W[k * 128 + n];
    }
    uint32_t h0, l0, h1, l1;
    split2(v[0], v[1], h0, l0);
    split2(v[2], v[3], h1, l1);
    g_uf_hi[idx] = make_uint2(h0, h1);
    g_uf_lo[idx] = make_uint2(l0, l1);
}
__global__ void k_prep_lin(const float* __restrict__ lin_w) {
    int idx = blockIdx.x * blockDim.x + threadIdx.x;
    if (idx >= 4096) return;
    int ks = idx >> 9, ntile = (idx >> 5) & 15, lane = idx & 31;
    int n = ntile * 8 + (lane >> 2);
    int k0 = ks * 16 + (lane & 3) * 2;
    float v[4];
    #pragma unroll
    for (int q = 0; q < 4; q++) {
        int k = k0 + (q >> 1) * 8 + (q & 1);
        v[q] = lin_w[k * 128 + n];
    }
    uint32_t h0, l0, h1, l1;
    split2(v[0], v[1], h0, l0);
    split2(v[2], v[3], h1, l1);
    g_linf_hi[idx] = make_uint2(h0, h1);
    g_linf_lo[idx] = make_uint2(l0, l1);
}

// ------------------- node-kernel smem layout -------------------
#define GOFF_BIAS 0        // 512B
#define GOFF_AUX  512      // 1536B (idg / tail weights)
#define GOFF_IDX  2048     // 2048B (prs + zs)
#define GOFF_B1   4096     // 512B (next-layer b1)
#define GOFF_AHI  4608
#define G_ASZ     34816
#define GOFF_ALO  (GOFF_AHI + G_ASZ)
#define G_SMEM    (GOFF_ALO + G_ASZ)   // 74240 -> occupancy 2

// ------------------- k_input_xab: lin_in GEMM + fused W1(0) GEMM -------------------
__global__ void __launch_bounds__(512, 2)
k_input_xab(const float* __restrict__ pos, const int* __restrict__ z,
            const int* __restrict__ batch, const float* __restrict__ emb,
            const float* __restrict__ lin_w, const float* __restrict__ bias,
            const float* __restrict__ b1n) {
    extern __shared__ __align__(16) char sm[];
    uint32_t sbase = smem_u32(sm);
    int tid = threadIdx.x;
    int lane = tid & 31;
    int wid = tid >> 5;
    int n0 = blockIdx.x * 128;
    float* bs  = (float*)(sm + GOFF_BIAS);
    float* tl  = (float*)(sm + GOFF_AUX);
    float* prs = (float*)(sm + GOFF_IDX);
    int*   zs  = (int*)(sm + GOFF_IDX + 1536);
    float* b1s = (float*)(sm + GOFF_B1);

    if (tid < 128) {
        bs[tid] = bias[tid];
        b1s[tid] = b1n[tid];
        int n = n0 + tid;
        int b = batch[n];
        #pragma unroll
        for (int d = 0; d < 3; d++) {
            float v = pos[n * 3 + d] - g_center[b * 3 + d];
            prs[tid * 3 + d] = v;
            g_posrel[n * 3 + d] = v;
        }
        zs[tid] = z[n];
    } else if (tid >= 128 && tid < 128 + 384) {
        int i = tid - 128;
        tl[i] = lin_w[(128 + (i >> 7)) * 128 + (i & 127)];
    }
    __syncthreads();

    // A build: emb gather + split
    #pragma unroll
    for (int it = 0; it < 4; it++) {
        int cid = tid + it * 512;
        int r = cid >> 4, kc = cid & 15;
        const float4* ep = (const float4*)(emb + (size_t)zs[r] * 128) + kc * 2;
        float4 e0 = ep[0], e1 = ep[1];
        uint32_t h0, l0, h1, l1, h2, l2, h3, l3;
        split2(e0.x, e0.y, h0, l0);
        split2(e0.z, e0.w, h1, l1);
        split2(e1.x, e1.y, h2, l2);
        split2(e1.z, e1.w, h3, l3);
        uint32_t o = (uint32_t)r * 272 + kc * 16;
        *(uint4*)(sm + GOFF_AHI + o) = make_uint4(h0, h1, h2, h3);
        *(uint4*)(sm + GOFF_ALO + o) = make_uint4(l0, l1, l2, l3);
    }
    __syncthreads();

    float acc[2][4][4];
    #pragma unroll
    for (int mt = 0; mt < 2; mt++)
        #pragma unroll
        for (int nt = 0; nt < 4; nt++)
            #pragma unroll
            for (int q = 0; q < 4; q++) acc[mt][nt][q] = 0.f;
    mma3_gf(sbase, GOFF_AHI, GOFF_ALO, g_linf_hi, g_linf_lo, 16, (wid >> 2) * 4, 0,
            lane, wid & 3, acc);
    __syncthreads();
    stage_acc(sm, GOFF_AHI, lane, wid & 3, wid >> 2, acc);
    __syncthreads();

    // epilogue with register carry: x0 = stage + bias + tail; write xhi/xlo; rebuild A
    uint4 chi[4], clo[4];
    #pragma unroll
    for (int it = 0; it < 4; it++) {
        int cid = tid + it * 512;
        int r = cid >> 4, kc = cid & 15;
        float4 v0 = *(float4*)(sm + GOFF_AHI + (uint32_t)r * 528 + kc * 32);
        float4 v1 = *(float4*)(sm + GOFF_AHI + (uint32_t)r * 528 + kc * 32 + 16);
        float p0 = prs[r * 3 + 0], p1 = prs[r * 3 + 1], p2 = prs[r * 3 + 2];
        int c = kc * 8;
        v0.x += bs[c + 0] + p0 * tl[c + 0] + p1 * tl[128 + c + 0] + p2 * tl[256 + c + 0];
        v0.y += bs[c + 1] + p0 * tl[c + 1] + p1 * tl[128 + c + 1] + p2 * tl[256 + c + 1];
        v0.z += bs[c + 2] + p0 * tl[c + 2] + p1 * tl[128 + c + 2] + p2 * tl[256 + c + 2];
        v0.w += bs[c + 3] + p0 * tl[c + 3] + p1 * tl[128 + c + 3] + p2 * tl[256 + c + 3];
        v1.x += bs[c + 4] + p0 * tl[c + 4] + p1 * tl[128 + c + 4] + p2 * tl[256 + c + 4];
        v1.y += bs[c + 5] + p0 * tl[c + 5] + p1 * tl[128 + c + 5] + p2 * tl[256 + c + 5];
        v1.z += bs[c + 6] + p0 * tl[c + 6] + p1 * tl[128 + c + 6] + p2 * tl[256 + c + 6];
        v1.w += bs[c + 7] + p0 * tl[c + 7] + p1 * tl[128 + c + 7] + p2 * tl[256 + c + 7];
        uint32_t h0, l0, h1, l1, h2, l2, h3, l3;
        split2(v0.x, v0.y, h0, l0);
        split2(v0.z, v0.w, h1, l1);
        split2(v1.x, v1.y, h2, l2);
        split2(v1.z, v1.w, h3, l3);
        chi[it] = make_uint4(h0, h1, h2, h3);
        clo[it] = make_uint4(l0, l1, l2, l3);
        size_t nrow = (size_t)(n0 + r);
        ((uint4*)g_xhi)[nrow * 16 + kc] = chi[it];
        ((uint4*)g_xlo)[nrow * 16 + kc] = clo[it];
    }
    __syncthreads();
    #pragma unroll
    for (int it = 0; it < 4; it++) {
        int cid = tid + it * 512;
        int r = cid >> 4, kc = cid & 15;
        uint32_t o = (uint32_t)r * 272 + kc * 16;
        *(uint4*)(sm + GOFF_AHI + o) = chi[it];
        *(uint4*)(sm + GOFF_ALO + o) = clo[it];
    }
    __syncthreads();

    // fused xab(0): both halves off the same A tile, direct fragment stores
    #pragma unroll
    for (int half = 0; half < 2; half++) {
        #pragma unroll
        for (int mt = 0; mt < 2; mt++)
            #pragma unroll
            for (int nt = 0; nt < 4; nt++)
                #pragma unroll
                for (int q = 0; q < 4; q++) acc[mt][nt][q] = 0.f;
        mma3_gf(sbase, GOFF_AHI, GOFF_ALO, g_w1f_hi, g_w1f_lo,
                32, half * 16 + (wid >> 2) * 4, 0, lane, wid & 3, acc);
        write_frag_out(half == 0 ? g_xa : g_xb, n0, lane, wid & 3, wid >> 2,
                       half == 0 ? b1s : (const float*)nullptr, acc);
    }
}

// ------------------- k_update_xab: update GEMM + fused W1(l+1) GEMM -------------------
__global__ void __launch_bounds__(512, 2)
k_update_xab(const float* __restrict__ bias, int layer,
             const float* __restrict__ b1n, int do_next) {
    extern __shared__ __align__(16) char sm[];
    uint32_t sbase = smem_u32(sm);
    int tid = threadIdx.x;
    int lane = tid & 31;
    int wid = tid >> 5;
    int n0 = blockIdx.x * 128;
    float* bs = (float*)(sm + GOFF_BIAS);
    float* idg = (float*)(sm + GOFF_AUX);
    float* b1s = (float*)(sm + GOFF_B1);
    if (tid < 128) {
        bs[tid] = bias[tid];
        idg[tid] = g_invdeg[n0 + tid];
        b1s[tid] = do_next ? b1n[tid] : 0.f;
    }

    const uint2* uf_hi = g_uf_hi + layer * 8192;
    const uint2* uf_lo = g_uf_lo + layer * 8192;

    float acc[2][4][4];
    #pragma unroll
    for (int mt = 0; mt < 2; mt++)
        #pragma unroll
        for (int nt = 0; nt < 4; nt++)
            #pragma unroll
            for (int q = 0; q < 4; q++) acc[mt][nt][q] = 0.f;

    // pass 0: A = x hi/lo, B = U^T ks 0..7
    {
        const uint4* ah = (const uint4*)g_xhi + (size_t)n0 * 16;
        const uint4* al = (const uint4*)g_xlo + (size_t)n0 * 16;
        #pragma unroll
        for (int it = 0; it < 4; it++) {
            int cid = tid + it * 512;
            int r = cid >> 4, c = cid & 15;
            uint32_t o = (uint32_t)r * 272 + c * 16;
            *(uint4*)(sm + GOFF_AHI + o) = ah[r * 16 + c];
            *(uint4*)(sm + GOFF_ALO + o) = al[r * 16 + c];
        }
        __syncthreads();
        mma3_gf(sbase, GOFF_AHI, GOFF_ALO, uf_hi, uf_lo, 16, (wid >> 2) * 4, 0,
                lane, wid & 3, acc);
        __syncthreads();
    }
    // pass 1: A = msum*invdeg, B = U^T ks 8..15
    {
        #pragma unroll
        for (int it = 0; it < 4; it++) {
            int cid = tid + it * 512;
            int r = cid >> 4, c = cid & 15;
            uint32_t o = (uint32_t)r * 272 + c * 16;
            const float4* mp = (const float4*)(g_msum + (size_t)(n0 + r) * 128) + c * 2;
            float s = idg[r];
            float4 m0 = mp[0], m1 = mp[1];
            uint32_t h0, l0, h1, l1, h2, l2, h3, l3;
            split2(m0.x * s, m0.y * s, h0, l0);
            split2(m0.z * s, m0.w * s, h1, l1);
            split2(m1.x * s, m1.y * s, h2, l2);
            split2(m1.z * s, m1.w * s, h3, l3);
            *(uint4*)(sm + GOFF_AHI + o) = make_uint4(h0, h1, h2, h3);
            *(uint4*)(sm + GOFF_ALO + o) = make_uint4(l0, l1, l2, l3);
        }
        __syncthreads();
        mma3_gf(sbase, GOFF_AHI, GOFF_ALO, uf_hi, uf_lo, 16, (wid >> 2) * 4, 8,
                lane, wid & 3, acc);
        __syncthreads();
    }

    stage_acc(sm, GOFF_AHI, lane, wid & 3, wid >> 2, acc);
    __syncthreads();

    // epilogue with register carry: x' = relu(stage + bias); write globals; rebuild A
    uint4 chi[4], clo[4];
    #pragma unroll
    for (int it = 0; it < 4; it++) {
        int cid = tid + it * 512;
        int r = cid >> 4, kc = cid & 15;
        float4 v0 = *(float4*)(sm + GOFF_AHI + (uint32_t)r * 528 + kc * 32);
        float4 v1 = *(float4*)(sm + GOFF_AHI + (uint32_t)r * 528 + kc * 32 + 16);
        int c = kc * 8;
        v0.x = fmaxf(v0.x + bs[c + 0], 0.f);
        v0.y = fmaxf(v0.y + bs[c + 1], 0.f);
        v0.z = fmaxf(v0.z + bs[c + 2], 0.f);
        v0.w = fmaxf(v0.w + bs[c + 3], 0.f);
        v1.x = fmaxf(v1.x + bs[c + 4], 0.f);
        v1.y = fmaxf(v1.y + bs[c + 5], 0.f);
        v1.z = fmaxf(v1.z + bs[c + 6], 0.f);
        v1.w = fmaxf(v1.w + bs[c + 7], 0.f);
        size_t nrow = (size_t)(n0 + r);
        if (do_next) {
            uint32_t h0, l0, h1, l1, h2, l2, h3, l3;
            split2(v0.x, v0.y, h0, l0);
            split2(v0.z, v0.w, h1, l1);
            split2(v1.x, v1.y, h2, l2);
            split2(v1.z, v1.w, h3, l3);
            chi[it] = make_uint4(h0, h1, h2, h3);
            clo[it] = make_uint4(l0, l1, l2, l3);
            ((uint4*)g_xhi)[nrow * 16 + kc] = chi[it];
            ((uint4*)g_xlo)[nrow * 16 + kc] = clo[it];
        } else {
            ((float4*)(g_x0 + nrow * 128))[kc * 2] = v0;
            ((float4*)(g_x0 + nrow * 128))[kc * 2 + 1] = v1;
        }
    }
    if (!do_next) return;
    __syncthreads();
    #pragma unroll
    for (int it = 0; it < 4; it++) {
        int cid = tid + it * 512;
        int r = cid >> 4, kc = cid & 15;
        uint32_t o = (uint32_t)r * 272 + kc * 16;
        *(uint4*)(sm + GOFF_AHI + o) = chi[it];
        *(uint4*)(sm + GOFF_ALO + o) = clo[it];
    }
    __syncthreads();

    // fused xab(layer+1)
    const uint2* w1h = g_w1f_hi + (layer + 1) * 8192;
    const uint2* w1l = g_w1f_lo + (layer + 1) * 8192;
    #pragma unroll
    for (int half = 0; half < 2; half++) {
        #pragma unroll
        for (int mt = 0; mt < 2; mt++)
            #pragma unroll
            for (int nt = 0; nt < 4; nt++)
                #pragma unroll
                for (int q = 0; q < 4; q++) acc[mt][nt][q] = 0.f;
        mma3_gf(sbase, GOFF_AHI, GOFF_ALO, w1h, w1l,
                32, half * 16 + (wid >> 2) * 4, 0, lane, wid & 3, acc);
        write_frag_out(half == 0 ? g_xa : g_xb, n0, lane, wid & 3, wid >> 2,
                       half == 0 ? b1s : (const float*)nullptr, acc);
    }
}

// ------------------- HMMA edge kernel (sorted edges, segmented epilogue) ---------------
#define EOFF_ROWS 0
#define EOFF_COLS 512
#define EOFF_DIST 1024
#define EOFF_BIAS 1536
#define EOFF_W1C  2048
#define EOFF_SEG  2560
#define EOFF_AHI  4096
#define E_ASZ     34816
#define EOFF_ALO  (EOFF_AHI + E_ASZ)
#define E_SMEM    (EOFF_ALO + E_ASZ)   // 73728 -> occupancy 2

__global__ void __launch_bounds__(512, 2)
k_edge_mma(const float* __restrict__ w1c, const float* __restrict__ b2, int layer) {
    extern __shared__ __align__(16) char sm[];
    uint32_t sbase = smem_u32(sm);
    int tid = threadIdx.x;
    int lane = tid & 31;
    int wid = tid >> 5;
    int e0 = blockIdx.x * 128;

    int*   rows = (int*)(sm + EOFF_ROWS);
    int*   cols = (int*)(sm + EOFF_COLS);
    float* ds   = (float*)(sm + EOFF_DIST);
    float* bs   = (float*)(sm + EOFF_BIAS);
    float* ws   = (float*)(sm + EOFF_W1C);
    int*   wcnt = (int*)(sm + EOFF_SEG);
    int*   woff = wcnt + 4;
    int*   nsegp = woff + 4;
    int*   segstart = nsegp + 1;

    if (tid < 128) {
        rows[tid] = g_srow[e0 + tid];
        cols[tid] = g_scol[e0 + tid];
        ds[tid]   = g_sdist[e0 + tid];
        bs[tid]   = b2[tid];
        ws[tid]   = w1c[tid];
    }
    __syncthreads();

    #pragma unroll
    for (int it = 0; it < 4; it++) {
        int cid = tid + it * 512;
        int e = cid >> 4;
        int kc = cid & 15;
        const float4* pa = (const float4*)(g_xa + (size_t)cols[e] * 128) + kc * 2;
        const float4* pb = (const float4*)(g_xb + (size_t)rows[e] * 128) + kc * 2;
        float d = ds[e];
        float4 a0 = pa[0], a1 = pa[1];
        float4 b0 = pb[0], b1 = pb[1];
        int k0 = kc * 8;
        float v0 = fmaxf(a0.x + b0.x + d * ws[k0 + 0], 0.f);
        float v1 = fmaxf(a0.y + b0.y + d * ws[k0 + 1], 0.f);
        float v2 = fmaxf(a0.z + b0.z + d * ws[k0 + 2], 0.f);
        float v3 = fmaxf(a0.w + b0.w + d * ws[k0 + 3], 0.f);
        float v4 = fmaxf(a1.x + b1.x + d * ws[k0 + 4], 0.f);
        float v5 = fmaxf(a1.y + b1.y + d * ws[k0 + 5], 0.f);
        float v6 = fmaxf(a1.z + b1.z + d * ws[k0 + 6], 0.f);
        float v7 = fmaxf(a1.w + b1.w + d * ws[k0 + 7], 0.f);
        uint32_t h0, l0, h1, l1, h2, l2, h3, l3;
        split2(v0, v1, h0, l0);
        split2(v2, v3, h1, l1);
        split2(v4, v5, h2, l2);
        split2(v6, v7, h3, l3);
        uint32_t o = (uint32_t)e * 272 + kc * 16;
        *(uint4*)(sm + EOFF_AHI + o) = make_uint4(h0, h1, h2, h3);
        *(uint4*)(sm + EOFF_ALO + o) = make_uint4(l0, l1, l2, l3);
    }
    __syncthreads();

    float acc[2][4][4];
    #pragma unroll
    for (int mt = 0; mt < 2; mt++)
        #pragma unroll
        for (int nt = 0; nt < 4; nt++)
            #pragma unroll
            for (int q = 0; q < 4; q++) acc[mt][nt][q] = 0.f;
    mma3_gf(sbase, EOFF_AHI, EOFF_ALO, g_w2f_hi + layer * 4096, g_w2f_lo + layer * 4096,
            16, (wid >> 2) * 4, 0, lane, wid & 3, acc);
    __syncthreads();
    stage_acc(sm, EOFF_AHI, lane, wid & 3, wid >> 2, acc);

    int f = 0, pre = 0;
    if (wid < 4) {
        f = (tid == 0) || (rows[tid] != rows[tid - 1]);
        unsigned m = __ballot_sync(0xffffffffu, f);
        pre = __popc(m & ((1u << lane) - 1u));
        if (lane == 0) wcnt[wid] = __popc(m);
    }
    __syncthreads();
    if (tid == 0) {
        int s = 0;
        #pragma unroll
        for (int w = 0; w < 4; w++) { woff[w] = s; s += wcnt[w]; }
        nsegp[0] = s;
        segstart[s] = 128;
    }
    __syncthreads();
    if (wid < 4 && f) segstart[woff[wid] + pre] = tid;
    __syncthreads();

    int nseg = nsegp[0];
    for (int item = tid; item < nseg * 32; item += 512) {
        int s = item >> 5, c4 = item & 31;
        int rbeg = segstart[s], rend = segstart[s + 1];
        float4 bb = *(float4*)(bs + c4 * 4);
        float m0 = 0.f, m1 = 0.f, m2 = 0.f, m3 = 0.f;
        for (int r = rbeg; r < rend; r++) {
            float4 v = *(float4*)(sm + EOFF_AHI + (uint32_t)r * 528 + c4 * 16);
            m0 += fmaxf(v.x + bb.x, 0.f);
            m1 += fmaxf(v.y + bb.y, 0.f);
            m2 += fmaxf(v.z + bb.z, 0.f);
            m3 += fmaxf(v.w + bb.w, 0.f);
        }
        float* p = g_msum + (size_t)rows[rbeg] * 128 + c4 * 4;
        asm volatile("red.global.add.v4.f32 [%0], {%1,%2,%3,%4};"
                     :: "l"(p), "f"(m0), "f"(m1), "f"(m2), "f"(m3) : "memory");
    }
}

// ------------------- readout pooling (fused ligcnt) -------------------
__global__ void k_pool(const int* __restrict__ batch, const int* __restrict__ ntype) {
    int idx = blockIdx.x * blockDim.x + threadIdx.x;
    int n = idx >> 5;
    int q = idx & 31;
    if (n >= Nn) return;
    if (ntype[n] == 1) {
        int b = batch[n];
        float4 v = ((const float4*)g_x0)[n * 32 + q];
        float* p = &g_gsum[b * 128 + q * 4];
        asm volatile("red.global.add.v4.f32 [%0], {%1,%2,%3,%4};"
                     :: "l"(p), "f"(v.x), "f"(v.y), "f"(v.z), "f"(v.w) : "memory");
        if (q == 0) atomicAdd(&g_ligcnt[b], 1.f);
    }
}

__global__ void __launch_bounds__(128)
k_readout(const float* __restrict__ rw1, const float* __restrict__ rb1,
          const float* __restrict__ rw2, const float* __restrict__ rb2,
          float* __restrict__ out) {
    __shared__ __align__(16) float gs[128];
    __shared__ float red_s[128];
    int b = blockIdx.x;
    int tid = threadIdx.x;
    float cnt = fmaxf(g_ligcnt[b], 1.f);
    gs[tid] = g_gsum[b * 128 + tid] / cnt;
    __syncthreads();

    int j = tid;
    const float* Wj = rw1 + j;
    const float4* gs4 = (const float4*)gs;
    float acc = rb1[j];
    for (int kk = 0; kk < 32; kk++) {
        float w0 = Wj[(kk * 4 + 0) * 128];
        float w1 = Wj[(kk * 4 + 1) * 128];
        float w2 = Wj[(kk * 4 + 2) * 128];
        float w3 = Wj[(kk * 4 + 3) * 128];
        float4 gv = gs4[kk];
        acc += gv.x * w0 + gv.y * w1 + gv.z * w2 + gv.w * w3;
    }
    float hg = fmaxf(acc, 0.f);
    red_s[tid] = hg * rw2[j];
    __syncthreads();
    for (int s = 64; s > 0; s >>= 1) {
        if (tid < s) red_s[tid] += red_s[tid + s];
        __syncthreads();
    }
    if (tid == 0) out[b] = red_s[0] + rb2[0];
}

// ------------------- launch -------------------
extern "C" void kernel_launch(void* const* d_in, const int* in_sizes, int n_in,
                              void* d_out, int out_size) {
    const float* pos   = (const float*)d_in[0];
    const int*   z     = (const int*)d_in[1];
    const int*   batch = (const int*)d_in[2];
    const int*   eidx  = (const int*)d_in[3];
    const int*   ntype = (const int*)d_in[4];
    const float* emb   = (const float*)d_in[5];
    const float* lin_w = (const float*)d_in[6];
    const float* lin_b = (const float*)d_in[7];
    const float* mw1   = (const float*)d_in[8];
    const float* mb1   = (const float*)d_in[9];
    const float* mw2   = (const float*)d_in[10];
    const float* mb2   = (const float*)d_in[11];
    const float* uw    = (const float*)d_in[12];
    const float* ub    = (const float*)d_in[13];
    const float* rw1   = (const float*)d_in[14];
    const float* rb1   = (const float*)d_in[15];
    const float* rw2   = (const float*)d_in[16];
    const float* rb2   = (const float*)d_in[17];
    float* out = (float*)d_out;

    cudaFuncSetAttribute(k_edge_mma, cudaFuncAttributeMaxDynamicSharedMemorySize, E_SMEM);
    cudaFuncSetAttribute(k_input_xab, cudaFuncAttributeMaxDynamicSharedMemorySize, G_SMEM);
    cudaFuncSetAttribute(k_update_xab, cudaFuncAttributeMaxDynamicSharedMemorySize, G_SMEM);

    void *p_csum, *p_deg, *p_msum, *p_gsum, *p_lig;
    cudaGetSymbolAddress(&p_csum, g_csum);
    cudaGetSymbolAddress(&p_deg, g_deg);
    cudaGetSymbolAddress(&p_msum, g_msum);
    cudaGetSymbolAddress(&p_gsum, g_gsum);
    cudaGetSymbolAddress(&p_lig, g_ligcnt);

    cudaMemsetAsync(p_csum, 0, Bb * 4 * sizeof(float));
    cudaMemsetAsync(p_deg, 0, Nn * sizeof(int));
    cudaMemsetAsync(p_gsum, 0, Bb * Hh * sizeof(float));
    cudaMemsetAsync(p_lig, 0, Bb * sizeof(float));

    k_prep_w1<<<(3 * 8192) / 256, 256>>>(mw1);
    k_prep_w2<<<(3 * 4096) / 256, 256>>>(mw2);
    k_prep_u<<<(3 * 8192) / 256, 256>>>(uw);
    k_prep_lin<<<4096 / 256, 256>>>(lin_w);

    k_center_sum<<<Nn / 256, 256>>>(pos, batch);
    k_center_fin<<<1, 64>>>();
    k_input_xab<<<Nn / 128, 512, G_SMEM>>>(pos, z, batch, emb, lin_w, lin_b, mb1);
    k_deg<<<Ee / 256, 256>>>(eidx);
    k_scan1<<<256, 256>>>();
    k_scan2<<<1, 256>>>();
    k_scan3<<<Nn / 256, 256>>>();
    k_scatter<<<Ee / 256, 256>>>(eidx);

    for (int l = 0; l < 3; l++) {
        const float* W1 = mw1 + l * 257 * 128;
        cudaMemsetAsync(p_msum, 0, (size_t)Nn * Hh * sizeof(float));
        k_edge_mma<<<Ee / 128, 512, E_SMEM>>>(W1 + 256 * 128, mb2 + l * 128, l);
        k_update_xab<<<Nn / 128, 512, G_SMEM>>>(ub + l * 128, l,
                                                l < 2 ? (mb1 + (l + 1) * 128) : mb1,
                                                l < 2 ? 1 : 0);
    }

    k_pool<<<Nn * 32 / 256, 256>>>(batch, ntype);
    k_readout<<<Bb, 128>>>(rw1, rb1, rw2, rb2, out);
}

// round 11
// speedup vs baseline: 3.8511x; 1.1843x over previous
#include <cuda_runtime.h>
#include <cuda_fp16.h>
#include <math.h>
#include <stdint.h>

#define Nn 65536
#define Ee 1048576
#define Bb 64
#define Hh 128

// ------------------- scratch (static device globals; no allocation) -------------------
__device__ float g_csum[Bb * 4];
__device__ float g_center[Bb * 3];
__device__ float g_posrel[Nn * 3];
__device__ float g_x0[Nn * Hh];
__device__ uint32_t g_xhi[Nn * 64];       // fp16x2-packed hi split of x
__device__ uint32_t g_xlo[Nn * 64];       // fp16x2-packed lo split (residual)
__device__ float g_xa[Nn * Hh];
__device__ float g_xb[Nn * Hh];
__device__ float g_msum[Nn * Hh];
__device__ int   g_deg[Nn];
__device__ float g_invdeg[Nn];
__device__ float g_gsum[Bb * Hh];
__device__ float g_ligcnt[Bb];
// edge sort scratch
__device__ int   g_rowstart[Nn];
__device__ int   g_rowcur[Nn];
__device__ int   g_blksum[256];
__device__ int   g_srow[Ee];
__device__ int   g_scol[Ee];
__device__ float g_sdist[Ee];
// fragment-linear weights (fp16x2 pairs per lane), hi only (2-term scheme)
__device__ uint2 g_w1f[3 * 8192];   // W1^T 256n x 128k, NT=32
__device__ uint2 g_w2f[3 * 4096];   // W2^T 128n x 128k, NT=16
__device__ uint2 g_uf[3 * 8192];    // U^T  128n x 256k, NT=16
__device__ uint2 g_linf[4096];      // lin^T 128n x 128k, NT=16

// ------------------- helpers -------------------
__device__ __forceinline__ uint32_t smem_u32(const void* p) {
    uint32_t a;
    asm("{ .reg .u64 t; cvta.to.shared.u64 t, %1; cvt.u32.u64 %0, t; }" : "=r"(a) : "l"(p));
    return a;
}
__device__ __forceinline__ void ldsm_x4(uint32_t* r, uint32_t addr) {
    asm volatile("ldmatrix.sync.aligned.m8n8.x4.shared.b16 {%0,%1,%2,%3}, [%4];"
                 : "=r"(r[0]), "=r"(r[1]), "=r"(r[2]), "=r"(r[3]) : "r"(addr));
}
__device__ __forceinline__ void mma_f16(float* d, const uint32_t* a, const uint32_t* b) {
    asm volatile("mma.sync.aligned.m16n8k16.row.col.f32.f16.f16.f32 "
                 "{%0,%1,%2,%3}, {%4,%5,%6,%7}, {%8,%9}, {%0,%1,%2,%3};"
                 : "+f"(d[0]), "+f"(d[1]), "+f"(d[2]), "+f"(d[3])
                 : "r"(a[0]), "r"(a[1]), "r"(a[2]), "r"(a[3]), "r"(b[0]), "r"(b[1]));
}
// split two fp32 into fp16x2 hi + fp16x2 lo (residual); A is exact to ~2^-22
__device__ __forceinline__ void split2(float v0, float v1, uint32_t& hi, uint32_t& lo) {
    __half2 h = __floats2half2_rn(v0, v1);
    float h0 = __half2float(__low2half(h));
    float h1 = __half2float(__high2half(h));
    __half2 l = __floats2half2_rn(v0 - h0, v1 - h1);
    hi = *(uint32_t*)&h;
    lo = *(uint32_t*)&l;
}
__device__ __forceinline__ uint32_t pack_h2(float v0, float v1) {
    __half2 h = __floats2half2_rn(v0, v1);
    return *(uint32_t*)&h;
}

// 2-term MMA core: D += (Ahi + Alo) * Bhi.  B from fragment-linear global arrays.
// A (hi/lo) in smem (128 rows x 256B, stride 272). 16 warps, warp tile m32 x n32.
__device__ __forceinline__ void mma2_gf(uint32_t sbase, uint32_t oAhi, uint32_t oAlo,
                                        const uint2* __restrict__ bf,
                                        int NT, int nt_base, int ks_base,
                                        int lane, int warp_m,
                                        float (&acc)[2][4][4]) {
    uint32_t a_base = sbase + oAhi + (uint32_t)(warp_m * 32 + (lane & 15)) * 272 + (uint32_t)(lane >> 4) * 16;
    uint32_t dA = oAlo - oAhi;
    for (int ks = 0; ks < 8; ks++) {
        uint32_t kb = (uint32_t)ks * 32;
        uint32_t a_hi[2][4], a_lo[2][4];
        #pragma unroll
        for (int mt = 0; mt < 2; mt++) {
            uint32_t ad = a_base + (uint32_t)(mt * 16) * 272 + kb;
            ldsm_x4(a_hi[mt], ad);
            ldsm_x4(a_lo[mt], ad + dA);
        }
        int fks = (ks_base + ks) * NT + nt_base;
        #pragma unroll
        for (int nt = 0; nt < 4; nt++) {
            uint2 bh = __ldg(bf + (size_t)(fks + nt) * 32 + lane);
            uint32_t bhv[2] = {bh.x, bh.y};
            mma_f16(acc[0][nt], a_hi[0], bhv);
            mma_f16(acc[1][nt], a_hi[1], bhv);
            mma_f16(acc[0][nt], a_lo[0], bhv);
            mma_f16(acc[1][nt], a_lo[1], bhv);
        }
    }
}

__device__ __forceinline__ void stage_acc(char* sm, uint32_t oM, int lane, int warp_m, int warp_n,
                                          float (&acc)[2][4][4]) {
    #pragma unroll
    for (int mt = 0; mt < 2; mt++) {
        int er = warp_m * 32 + mt * 16 + (lane >> 2);
        #pragma unroll
        for (int nt = 0; nt < 4; nt++) {
            int cb = warp_n * 32 + nt * 8 + (lane & 3) * 2;
            *(float2*)(sm + oM + (uint32_t)er * 528 + cb * 4) = make_float2(acc[mt][nt][0], acc[mt][nt][1]);
            *(float2*)(sm + oM + (uint32_t)(er + 8) * 528 + cb * 4) = make_float2(acc[mt][nt][2], acc[mt][nt][3]);
        }
    }
}

__device__ __forceinline__ void write_frag_out(float* out, int n0, int lane, int warp_m, int warp_n,
                                               const float* bsm, float (&acc)[2][4][4]) {
    #pragma unroll
    for (int mt = 0; mt < 2; mt++) {
        int er = n0 + warp_m * 32 + mt * 16 + (lane >> 2);
        #pragma unroll
        for (int nt = 0; nt < 4; nt++) {
            int cb = warp_n * 32 + nt * 8 + (lane & 3) * 2;
            float b0 = bsm ? bsm[cb] : 0.f;
            float b1 = bsm ? bsm[cb + 1] : 0.f;
            *(float2*)(out + (size_t)er * 128 + cb) = make_float2(acc[mt][nt][0] + b0, acc[mt][nt][1] + b1);
            *(float2*)(out + (size_t)(er + 8) * 128 + cb) = make_float2(acc[mt][nt][2] + b0, acc[mt][nt][3] + b1);
        }
    }
}

// ------------------- small kernels -------------------
__global__ void k_center_sum(const float* __restrict__ pos, const int* __restrict__ batch) {
    int n = blockIdx.x * blockDim.x + threadIdx.x;
    if (n >= Nn) return;
    int lane = threadIdx.x & 31;
    int b = batch[n];
    float px = pos[n * 3 + 0], py = pos[n * 3 + 1], pz = pos[n * 3 + 2], pc = 1.f;
    #pragma unroll
    for (int off = 1; off < 32; off <<= 1) {
        int bs = __shfl_down_sync(0xffffffffu, b, off);
        float tx = __shfl_down_sync(0xffffffffu, px, off);
        float ty = __shfl_down_sync(0xffffffffu, py, off);
        float tz = __shfl_down_sync(0xffffffffu, pz, off);
        float tc = __shfl_down_sync(0xffffffffu, pc, off);
        if (lane + off < 32 && bs == b) { px += tx; py += ty; pz += tz; pc += tc; }
    }
    int bprev = __shfl_up_sync(0xffffffffu, b, 1);
    if (lane == 0 || bprev != b) {
        atomicAdd(&g_csum[b * 4 + 0], px);
        atomicAdd(&g_csum[b * 4 + 1], py);
        atomicAdd(&g_csum[b * 4 + 2], pz);
        atomicAdd(&g_csum[b * 4 + 3], pc);
    }
}

__global__ void k_center_fin() {
    int b = threadIdx.x;
    if (b < Bb) {
        float c = fmaxf(g_csum[b * 4 + 3], 1.f);
        g_center[b * 3 + 0] = g_csum[b * 4 + 0] / c;
        g_center[b * 3 + 1] = g_csum[b * 4 + 1] / c;
        g_center[b * 3 + 2] = g_csum[b * 4 + 2] / c;
    }
}

__global__ void k_deg(const int* __restrict__ eidx) {
    int e = blockIdx.x * blockDim.x + threadIdx.x;
    if (e < Ee) atomicAdd(&g_deg[eidx[e]], 1);
}

// ------------------- counting sort -------------------
__global__ void k_scan1() {
    __shared__ int s[256];
    int i = blockIdx.x * 256 + threadIdx.x;
    int v = g_deg[i];
    s[threadIdx.x] = v;
    __syncthreads();
    for (int off = 1; off < 256; off <<= 1) {
        int t = (threadIdx.x >= off) ? s[threadIdx.x - off] : 0;
        __syncthreads();
        s[threadIdx.x] += t;
        __syncthreads();
    }
    g_rowstart[i] = s[threadIdx.x] - v;
    if (threadIdx.x == 255) g_blksum[blockIdx.x] = s[255];
}
__global__ void k_scan2() {
    __shared__ int s[256];
    int i = threadIdx.x;
    int v = g_blksum[i];
    s[i] = v;
    __syncthreads();
    for (int off = 1; off < 256; off <<= 1) {
        int t = (i >= off) ? s[i - off] : 0;
        __syncthreads();
        s[i] += t;
        __syncthreads();
    }
    g_blksum[i] = s[i] - v;
}
__global__ void k_scan3() {
    int i = blockIdx.x * blockDim.x + threadIdx.x;
    if (i < Nn) {
        int v = g_rowstart[i] + g_blksum[i >> 8];
        g_rowstart[i] = v;
        g_rowcur[i] = v;
        g_invdeg[i] = 1.f / fmaxf((float)g_deg[i], 1.f);
    }
}
__global__ void k_scatter(const int* __restrict__ eidx) {
    int e = blockIdx.x * blockDim.x + threadIdx.x;
    if (e >= Ee) return;
    int r = eidx[e], c = eidx[Ee + e];
    int p = atomicAdd(&g_rowcur[r], 1);
    float dx = g_posrel[c * 3 + 0] - g_posrel[r * 3 + 0];
    float dy = g_posrel[c * 3 + 1] - g_posrel[r * 3 + 1];
    float dz = g_posrel[c * 3 + 2] - g_posrel[r * 3 + 2];
    g_srow[p] = r;
    g_scol[p] = c;
    g_sdist[p] = sqrtf(dx * dx + dy * dy + dz * dz);
}

// ------------------- weight prep into fragment-linear fp16 layout -------------------
__global__ void k_prep_w1(const float* __restrict__ mw1) {
    int idx = blockIdx.x * blockDim.x + threadIdx.x;
    if (idx >= 3 * 8192) return;
    int l = idx / 8192, r = idx % 8192;
    int ks = r >> 10, ntile = (r >> 5) & 31, lane = r & 31;
    int n = ntile * 8 + (lane >> 2);
    int k0 = ks * 16 + (lane & 3) * 2;
    const float* W = mw1 + l * 257 * 128;
    float v[4];
    #pragma unroll
    for (int q = 0; q < 4; q++) {
        int k = k0 + (q >> 1) * 8 + (q & 1);
        v[q] = (n < 128) ? W[k * 128 + n] : W[(128 + k) * 128 + (n - 128)];
    }
    g_w1f[idx] = make_uint2(pack_h2(v[0], v[1]), pack_h2(v[2], v[3]));
}
__global__ void k_prep_w2(const float* __restrict__ mw2) {
    int idx = blockIdx.x * blockDim.x + threadIdx.x;
    if (idx >= 3 * 4096) return;
    int l = idx / 4096, r = idx % 4096;
    int ks = r >> 9, ntile = (r >> 5) & 15, lane = r & 31;
    int n = ntile * 8 + (lane >> 2);
    int k0 = ks * 16 + (lane & 3) * 2;
    const float* W = mw2 + l * 16384;
    float v[4];
    #pragma unroll
    for (int q = 0; q < 4; q++) {
        int k = k0 + (q >> 1) * 8 + (q & 1);
        v[q] = W[k * 128 + n];
    }
    g_w2f[idx] = make_uint2(pack_h2(v[0], v[1]), pack_h2(v[2], v[3]));
}
__global__ void k_prep_u(const float* __restrict__ uw) {
    int idx = blockIdx.x * blockDim.x + threadIdx.x;
    if (idx >= 3 * 8192) return;
    int l = idx / 8192, r = idx % 8192;
    int ks = r >> 9, ntile = (r >> 5) & 15, lane = r & 31;
    int n = ntile * 8 + (lane >> 2);
    int k0 = ks * 16 + (lane & 3) * 2;
    const float* W = uw + l * 32768;
    float v[4];
    #pragma unroll
    for (int q = 0; q < 4; q++) {
        int k = k0 + (q >> 1) * 8 + (q & 1);
        v[q] = W[k * 128 + n];
    }
    g_uf[idx] = make_uint2(pack_h2(v[0], v[1]), pack_h2(v[2], v[3]));
}
__global__ void k_prep_lin(const float* __restrict__ lin_w) {
    int idx = blockIdx.x * blockDim.x + threadIdx.x;
    if (idx >= 4096) return;
    int ks = idx >> 9, ntile = (idx >> 5) & 15, lane = idx & 31;
    int n = ntile * 8 + (lane >> 2);
    int k0 = ks * 16 + (lane & 3) * 2;
    float v[4];
    #pragma unroll
    for (int q = 0; q < 4; q++) {
        int k = k0 + (q >> 1) * 8 + (q & 1);
        v[q] = lin_w[k * 128 + n];
    }
    g_linf[idx] = make_uint2(pack_h2(v[0], v[1]), pack_h2(v[2], v[3]));
}

// ------------------- node-kernel smem layout -------------------
#define GOFF_BIAS 0
#define GOFF_AUX  512
#define GOFF_IDX  2048
#define GOFF_B1   4096
#define GOFF_AHI  4608
#define G_ASZ     34816
#define GOFF_ALO  (GOFF_AHI + G_ASZ)
#define G_SMEM    (GOFF_ALO + G_ASZ)   // 74240 -> occupancy 2

// ------------------- k_input_xab -------------------
__global__ void __launch_bounds__(512, 2)
k_input_xab(const float* __restrict__ pos, const int* __restrict__ z,
            const int* __restrict__ batch, const float* __restrict__ emb,
            const float* __restrict__ lin_w, const float* __restrict__ bias,
            const float* __restrict__ b1n) {
    extern __shared__ __align__(16) char sm[];
    uint32_t sbase = smem_u32(sm);
    int tid = threadIdx.x;
    int lane = tid & 31;
    int wid = tid >> 5;
    int n0 = blockIdx.x * 128;
    float* bs  = (float*)(sm + GOFF_BIAS);
    float* tl  = (float*)(sm + GOFF_AUX);
    float* prs = (float*)(sm + GOFF_IDX);
    int*   zs  = (int*)(sm + GOFF_IDX + 1536);
    float* b1s = (float*)(sm + GOFF_B1);

    if (tid < 128) {
        bs[tid] = bias[tid];
        b1s[tid] = b1n[tid];
        int n = n0 + tid;
        int b = batch[n];
        #pragma unroll
        for (int d = 0; d < 3; d++) {
            float v = pos[n * 3 + d] - g_center[b * 3 + d];
            prs[tid * 3 + d] = v;
            g_posrel[n * 3 + d] = v;
        }
        zs[tid] = z[n];
    } else if (tid >= 128 && tid < 128 + 384) {
        int i = tid - 128;
        tl[i] = lin_w[(128 + (i >> 7)) * 128 + (i & 127)];
    }
    __syncthreads();

    #pragma unroll
    for (int it = 0; it < 4; it++) {
        int cid = tid + it * 512;
        int r = cid >> 4, kc = cid & 15;
        const float4* ep = (const float4*)(emb + (size_t)zs[r] * 128) + kc * 2;
        float4 e0 = ep[0], e1 = ep[1];
        uint32_t h0, l0, h1, l1, h2, l2, h3, l3;
        split2(e0.x, e0.y, h0, l0);
        split2(e0.z, e0.w, h1, l1);
        split2(e1.x, e1.y, h2, l2);
        split2(e1.z, e1.w, h3, l3);
        uint32_t o = (uint32_t)r * 272 + kc * 16;
        *(uint4*)(sm + GOFF_AHI + o) = make_uint4(h0, h1, h2, h3);
        *(uint4*)(sm + GOFF_ALO + o) = make_uint4(l0, l1, l2, l3);
    }
    __syncthreads();

    float acc[2][4][4];
    #pragma unroll
    for (int mt = 0; mt < 2; mt++)
        #pragma unroll
        for (int nt = 0; nt < 4; nt++)
            #pragma unroll
            for (int q = 0; q < 4; q++) acc[mt][nt][q] = 0.f;
    mma2_gf(sbase, GOFF_AHI, GOFF_ALO, g_linf, 16, (wid >> 2) * 4, 0, lane, wid & 3, acc);
    __syncthreads();
    stage_acc(sm, GOFF_AHI, lane, wid & 3, wid >> 2, acc);
    __syncthreads();

    uint4 chi[4], clo[4];
    #pragma unroll
    for (int it = 0; it < 4; it++) {
        int cid = tid + it * 512;
        int r = cid >> 4, kc = cid & 15;
        float4 v0 = *(float4*)(sm + GOFF_AHI + (uint32_t)r * 528 + kc * 32);
        float4 v1 = *(float4*)(sm + GOFF_AHI + (uint32_t)r * 528 + kc * 32 + 16);
        float p0 = prs[r * 3 + 0], p1 = prs[r * 3 + 1], p2 = prs[r * 3 + 2];
        int c = kc * 8;
        v0.x += bs[c + 0] + p0 * tl[c + 0] + p1 * tl[128 + c + 0] + p2 * tl[256 + c + 0];
        v0.y += bs[c + 1] + p0 * tl[c + 1] + p1 * tl[128 + c + 1] + p2 * tl[256 + c + 1];
        v0.z += bs[c + 2] + p0 * tl[c + 2] + p1 * tl[128 + c + 2] + p2 * tl[256 + c + 2];
        v0.w += bs[c + 3] + p0 * tl[c + 3] + p1 * tl[128 + c + 3] + p2 * tl[256 + c + 3];
        v1.x += bs[c + 4] + p0 * tl[c + 4] + p1 * tl[128 + c + 4] + p2 * tl[256 + c + 4];
        v1.y += bs[c + 5] + p0 * tl[c + 5] + p1 * tl[128 + c + 5] + p2 * tl[256 + c + 5];
        v1.z += bs[c + 6] + p0 * tl[c + 6] + p1 * tl[128 + c + 6] + p2 * tl[256 + c + 6];
        v1.w += bs[c + 7] + p0 * tl[c + 7] + p1 * tl[128 + c + 7] + p2 * tl[256 + c + 7];
        uint32_t h0, l0, h1, l1, h2, l2, h3, l3;
        split2(v0.x, v0.y, h0, l0);
        split2(v0.z, v0.w, h1, l1);
        split2(v1.x, v1.y, h2, l2);
        split2(v1.z, v1.w, h3, l3);
        chi[it] = make_uint4(h0, h1, h2, h3);
        clo[it] = make_uint4(l0, l1, l2, l3);
        size_t nrow = (size_t)(n0 + r);
        ((uint4*)g_xhi)[nrow * 16 + kc] = chi[it];
        ((uint4*)g_xlo)[nrow * 16 + kc] = clo[it];
    }
    __syncthreads();
    #pragma unroll
    for (int it = 0; it < 4; it++) {
        int cid = tid + it * 512;
        int r = cid >> 4, kc = cid & 15;
        uint32_t o = (uint32_t)r * 272 + kc * 16;
        *(uint4*)(sm + GOFF_AHI + o) = chi[it];
        *(uint4*)(sm + GOFF_ALO + o) = clo[it];
    }
    __syncthreads();

    #pragma unroll
    for (int half = 0; half < 2; half++) {
        #pragma unroll
        for (int mt = 0; mt < 2; mt++)
            #pragma unroll
            for (int nt = 0; nt < 4; nt++)
                #pragma unroll
                for (int q = 0; q < 4; q++) acc[mt][nt][q] = 0.f;
        mma2_gf(sbase, GOFF_AHI, GOFF_ALO, g_w1f,
                32, half * 16 + (wid >> 2) * 4, 0, lane, wid & 3, acc);
        write_frag_out(half == 0 ? g_xa : g_xb, n0, lane, wid & 3, wid >> 2,
                       half == 0 ? b1s : (const float*)nullptr, acc);
    }
}

// ------------------- k_update_xab -------------------
__global__ void __launch_bounds__(512, 2)
k_update_xab(const float* __restrict__ bias, int layer,
             const float* __restrict__ b1n, int do_next) {
    extern __shared__ __align__(16) char sm[];
    uint32_t sbase = smem_u32(sm);
    int tid = threadIdx.x;
    int lane = tid & 31;
    int wid = tid >> 5;
    int n0 = blockIdx.x * 128;
    float* bs = (float*)(sm + GOFF_BIAS);
    float* idg = (float*)(sm + GOFF_AUX);
    float* b1s = (float*)(sm + GOFF_B1);
    if (tid < 128) {
        bs[tid] = bias[tid];
        idg[tid] = g_invdeg[n0 + tid];
        b1s[tid] = do_next ? b1n[tid] : 0.f;
    }

    const uint2* uf = g_uf + layer * 8192;

    float acc[2][4][4];
    #pragma unroll
    for (int mt = 0; mt < 2; mt++)
        #pragma unroll
        for (int nt = 0; nt < 4; nt++)
            #pragma unroll
            for (int q = 0; q < 4; q++) acc[mt][nt][q] = 0.f;

    {
        const uint4* ah = (const uint4*)g_xhi + (size_t)n0 * 16;
        const uint4* al = (const uint4*)g_xlo + (size_t)n0 * 16;
        #pragma unroll
        for (int it = 0; it < 4; it++) {
            int cid = tid + it * 512;
            int r = cid >> 4, c = cid & 15;
            uint32_t o = (uint32_t)r * 272 + c * 16;
            *(uint4*)(sm + GOFF_AHI + o) = ah[r * 16 + c];
            *(uint4*)(sm + GOFF_ALO + o) = al[r * 16 + c];
        }
        __syncthreads();
        mma2_gf(sbase, GOFF_AHI, GOFF_ALO, uf, 16, (wid >> 2) * 4, 0, lane, wid & 3, acc);
        __syncthreads();
    }
    {
        #pragma unroll
        for (int it = 0; it < 4; it++) {
            int cid = tid + it * 512;
            int r = cid >> 4, c = cid & 15;
            uint32_t o = (uint32_t)r * 272 + c * 16;
            const float4* mp = (const float4*)(g_msum + (size_t)(n0 + r) * 128) + c * 2;
            float s = idg[r];
            float4 m0 = mp[0], m1 = mp[1];
            uint32_t h0, l0, h1, l1, h2, l2, h3, l3;
            split2(m0.x * s, m0.y * s, h0, l0);
            split2(m0.z * s, m0.w * s, h1, l1);
            split2(m1.x * s, m1.y * s, h2, l2);
            split2(m1.z * s, m1.w * s, h3, l3);
            *(uint4*)(sm + GOFF_AHI + o) = make_uint4(h0, h1, h2, h3);
            *(uint4*)(sm + GOFF_ALO + o) = make_uint4(l0, l1, l2, l3);
        }
        __syncthreads();
        mma2_gf(sbase, GOFF_AHI, GOFF_ALO, uf, 16, (wid >> 2) * 4, 8, lane, wid & 3, acc);
        __syncthreads();
    }

    stage_acc(sm, GOFF_AHI, lane, wid & 3, wid >> 2, acc);
    __syncthreads();

    uint4 chi[4], clo[4];
    #pragma unroll
    for (int it = 0; it < 4; it++) {
        int cid = tid + it * 512;
        int r = cid >> 4, kc = cid & 15;
        float4 v0 = *(float4*)(sm + GOFF_AHI + (uint32_t)r * 528 + kc * 32);
        float4 v1 = *(float4*)(sm + GOFF_AHI + (uint32_t)r * 528 + kc * 32 + 16);
        int c = kc * 8;
        v0.x = fmaxf(v0.x + bs[c + 0], 0.f);
        v0.y = fmaxf(v0.y + bs[c + 1], 0.f);
        v0.z = fmaxf(v0.z + bs[c + 2], 0.f);
        v0.w = fmaxf(v0.w + bs[c + 3], 0.f);
        v1.x = fmaxf(v1.x + bs[c + 4], 0.f);
        v1.y = fmaxf(v1.y + bs[c + 5], 0.f);
        v1.z = fmaxf(v1.z + bs[c + 6], 0.f);
        v1.w = fmaxf(v1.w + bs[c + 7], 0.f);
        size_t nrow = (size_t)(n0 + r);
        if (do_next) {
            uint32_t h0, l0, h1, l1, h2, l2, h3, l3;
            split2(v0.x, v0.y, h0, l0);
            split2(v0.z, v0.w, h1, l1);
            split2(v1.x, v1.y, h2, l2);
            split2(v1.z, v1.w, h3, l3);
            chi[it] = make_uint4(h0, h1, h2, h3);
            clo[it] = make_uint4(l0, l1, l2, l3);
            ((uint4*)g_xhi)[nrow * 16 + kc] = chi[it];
            ((uint4*)g_xlo)[nrow * 16 + kc] = clo[it];
        } else {
            ((float4*)(g_x0 + nrow * 128))[kc * 2] = v0;
            ((float4*)(g_x0 + nrow * 128))[kc * 2 + 1] = v1;
        }
    }
    if (!do_next) return;
    __syncthreads();
    #pragma unroll
    for (int it = 0; it < 4; it++) {
        int cid = tid + it * 512;
        int r = cid >> 4, kc = cid & 15;
        uint32_t o = (uint32_t)r * 272 + kc * 16;
        *(uint4*)(sm + GOFF_AHI + o) = chi[it];
        *(uint4*)(sm + GOFF_ALO + o) = clo[it];
    }
    __syncthreads();

    const uint2* w1 = g_w1f + (layer + 1) * 8192;
    #pragma unroll
    for (int half = 0; half < 2; half++) {
        #pragma unroll
        for (int mt = 0; mt < 2; mt++)
            #pragma unroll
            for (int nt = 0; nt < 4; nt++)
                #pragma unroll
                for (int q = 0; q < 4; q++) acc[mt][nt][q] = 0.f;
        mma2_gf(sbase, GOFF_AHI, GOFF_ALO, w1,
                32, half * 16 + (wid >> 2) * 4, 0, lane, wid & 3, acc);
        write_frag_out(half == 0 ? g_xa : g_xb, n0, lane, wid & 3, wid >> 2,
                       half == 0 ? b1s : (const float*)nullptr, acc);
    }
}

// ------------------- HMMA edge kernel -------------------
#define EOFF_ROWS 0
#define EOFF_COLS 512
#define EOFF_DIST 1024
#define EOFF_BIAS 1536
#define EOFF_W1C  2048
#define EOFF_SEG  2560
#define EOFF_AHI  4096
#define E_ASZ     34816
#define EOFF_ALO  (EOFF_AHI + E_ASZ)
#define E_SMEM    (EOFF_ALO + E_ASZ)   // 73728 -> occupancy 2

__global__ void __launch_bounds__(512, 2)
k_edge_mma(const float* __restrict__ w1c, const float* __restrict__ b2, int layer) {
    extern __shared__ __align__(16) char sm[];
    uint32_t sbase = smem_u32(sm);
    int tid = threadIdx.x;
    int lane = tid & 31;
    int wid = tid >> 5;
    int e0 = blockIdx.x * 128;

    int*   rows = (int*)(sm + EOFF_ROWS);
    int*   cols = (int*)(sm + EOFF_COLS);
    float* ds   = (float*)(sm + EOFF_DIST);
    float* bs   = (float*)(sm + EOFF_BIAS);
    float* ws   = (float*)(sm + EOFF_W1C);
    int*   wcnt = (int*)(sm + EOFF_SEG);
    int*   woff = wcnt + 4;
    int*   nsegp = woff + 4;
    int*   segstart = nsegp + 1;

    if (tid < 128) {
        rows[tid] = g_srow[e0 + tid];
        cols[tid] = g_scol[e0 + tid];
        ds[tid]   = g_sdist[e0 + tid];
        bs[tid]   = b2[tid];
        ws[tid]   = w1c[tid];
    }
    __syncthreads();

    #pragma unroll
    for (int it = 0; it < 4; it++) {
        int cid = tid + it * 512;
        int e = cid >> 4;
        int kc = cid & 15;
        const float4* pa = (const float4*)(g_xa + (size_t)cols[e] * 128) + kc * 2;
        const float4* pb = (const float4*)(g_xb + (size_t)rows[e] * 128) + kc * 2;
        float d = ds[e];
        float4 a0 = pa[0], a1 = pa[1];
        float4 b0 = pb[0], b1 = pb[1];
        int k0 = kc * 8;
        float v0 = fmaxf(a0.x + b0.x + d * ws[k0 + 0], 0.f);
        float v1 = fmaxf(a0.y + b0.y + d * ws[k0 + 1], 0.f);
        float v2 = fmaxf(a0.z + b0.z + d * ws[k0 + 2], 0.f);
        float v3 = fmaxf(a0.w + b0.w + d * ws[k0 + 3], 0.f);
        float v4 = fmaxf(a1.x + b1.x + d * ws[k0 + 4], 0.f);
        float v5 = fmaxf(a1.y + b1.y + d * ws[k0 + 5], 0.f);
        float v6 = fmaxf(a1.z + b1.z + d * ws[k0 + 6], 0.f);
        float v7 = fmaxf(a1.w + b1.w + d * ws[k0 + 7], 0.f);
        uint32_t h0, l0, h1, l1, h2, l2, h3, l3;
        split2(v0, v1, h0, l0);
        split2(v2, v3, h1, l1);
        split2(v4, v5, h2, l2);
        split2(v6, v7, h3, l3);
        uint32_t o = (uint32_t)e * 272 + kc * 16;
        *(uint4*)(sm + EOFF_AHI + o) = make_uint4(h0, h1, h2, h3);
        *(uint4*)(sm + EOFF_ALO + o) = make_uint4(l0, l1, l2, l3);
    }
    __syncthreads();

    float acc[2][4][4];
    #pragma unroll
    for (int mt = 0; mt < 2; mt++)
        #pragma unroll
        for (int nt = 0; nt < 4; nt++)
            #pragma unroll
            for (int q = 0; q < 4; q++) acc[mt][nt][q] = 0.f;
    mma2_gf(sbase, EOFF_AHI, EOFF_ALO, g_w2f + layer * 4096,
            16, (wid >> 2) * 4, 0, lane, wid & 3, acc);
    __syncthreads();
    stage_acc(sm, EOFF_AHI, lane, wid & 3, wid >> 2, acc);

    int f = 0, pre = 0;
    if (wid < 4) {
        f = (tid == 0) || (rows[tid] != rows[tid - 1]);
        unsigned m = __ballot_sync(0xffffffffu, f);
        pre = __popc(m & ((1u << lane) - 1u));
        if (lane == 0) wcnt[wid] = __popc(m);
    }
    __syncthreads();
    if (tid == 0) {
        int s = 0;
        #pragma unroll
        for (int w = 0; w < 4; w++) { woff[w] = s; s += wcnt[w]; }
        nsegp[0] = s;
        segstart[s] = 128;
    }
    __syncthreads();
    if (wid < 4 && f) segstart[woff[wid] + pre] = tid;
    __syncthreads();

    int nseg = nsegp[0];
    for (int item = tid; item < nseg * 32; item += 512) {
        int s = item >> 5, c4 = item & 31;
        int rbeg = segstart[s], rend = segstart[s + 1];
        float4 bb = *(float4*)(bs + c4 * 4);
        float m0 = 0.f, m1 = 0.f, m2 = 0.f, m3 = 0.f;
        for (int r = rbeg; r < rend; r++) {
            float4 v = *(float4*)(sm + EOFF_AHI + (uint32_t)r * 528 + c4 * 16);
            m0 += fmaxf(v.x + bb.x, 0.f);
            m1 += fmaxf(v.y + bb.y, 0.f);
            m2 += fmaxf(v.z + bb.z, 0.f);
            m3 += fmaxf(v.w + bb.w, 0.f);
        }
        float* p = g_msum + (size_t)rows[rbeg] * 128 + c4 * 4;
        asm volatile("red.global.add.v4.f32 [%0], {%1,%2,%3,%4};"
                     :: "l"(p), "f"(m0), "f"(m1), "f"(m2), "f"(m3) : "memory");
    }
}

// ------------------- readout pooling (fused ligcnt) -------------------
__global__ void k_pool(const int* __restrict__ batch, const int* __restrict__ ntype) {
    int idx = blockIdx.x * blockDim.x + threadIdx.x;
    int n = idx >> 5;
    int q = idx & 31;
    if (n >= Nn) return;
    if (ntype[n] == 1) {
        int b = batch[n];
        float4 v = ((const float4*)g_x0)[n * 32 + q];
        float* p = &g_gsum[b * 128 + q * 4];
        asm volatile("red.global.add.v4.f32 [%0], {%1,%2,%3,%4};"
                     :: "l"(p), "f"(v.x), "f"(v.y), "f"(v.z), "f"(v.w) : "memory");
        if (q == 0) atomicAdd(&g_ligcnt[b], 1.f);
    }
}

__global__ void __launch_bounds__(128)
k_readout(const float* __restrict__ rw1, const float* __restrict__ rb1,
          const float* __restrict__ rw2, const float* __restrict__ rb2,
          float* __restrict__ out) {
    __shared__ __align__(16) float gs[128];
    __shared__ float red_s[128];
    int b = blockIdx.x;
    int tid = threadIdx.x;
    float cnt = fmaxf(g_ligcnt[b], 1.f);
    gs[tid] = g_gsum[b * 128 + tid] / cnt;
    __syncthreads();

    int j = tid;
    const float* Wj = rw1 + j;
    const float4* gs4 = (const float4*)gs;
    float acc = rb1[j];
    for (int kk = 0; kk < 32; kk++) {
        float w0 = Wj[(kk * 4 + 0) * 128];
        float w1 = Wj[(kk * 4 + 1) * 128];
        float w2 = Wj[(kk * 4 + 2) * 128];
        float w3 = Wj[(kk * 4 + 3) * 128];
        float4 gv = gs4[kk];
        acc += gv.x * w0 + gv.y * w1 + gv.z * w2 + gv.w * w3;
    }
    float hg = fmaxf(acc, 0.f);
    red_s[tid] = hg * rw2[j];
    __syncthreads();
    for (int s = 64; s > 0; s >>= 1) {
        if (tid < s) red_s[tid] += red_s[tid + s];
        __syncthreads();
    }
    if (tid == 0) out[b] = red_s[0] + rb2[0];
}

// ------------------- launch -------------------
extern "C" void kernel_launch(void* const* d_in, const int* in_sizes, int n_in,
                              void* d_out, int out_size) {
    const float* pos   = (const float*)d_in[0];
    const int*   z     = (const int*)d_in[1];
    const int*   batch = (const int*)d_in[2];
    const int*   eidx  = (const int*)d_in[3];
    const int*   ntype = (const int*)d_in[4];
    const float* emb   = (const float*)d_in[5];
    const float* lin_w = (const float*)d_in[6];
    const float* lin_b = (const float*)d_in[7];
    const float* mw1   = (const float*)d_in[8];
    const float* mb1   = (const float*)d_in[9];
    const float* mw2   = (const float*)d_in[10];
    const float* mb2   = (const float*)d_in[11];
    const float* uw    = (const float*)d_in[12];
    const float* ub    = (const float*)d_in[13];
    const float* rw1   = (const float*)d_in[14];
    const float* rb1   = (const float*)d_in[15];
    const float* rw2   = (const float*)d_in[16];
    const float* rb2   = (const float*)d_in[17];
    float* out = (float*)d_out;

    cudaFuncSetAttribute(k_edge_mma, cudaFuncAttributeMaxDynamicSharedMemorySize, E_SMEM);
    cudaFuncSetAttribute(k_input_xab, cudaFuncAttributeMaxDynamicSharedMemorySize, G_SMEM);
    cudaFuncSetAttribute(k_update_xab, cudaFuncAttributeMaxDynamicSharedMemorySize, G_SMEM);

    void *p_csum, *p_deg, *p_msum, *p_gsum, *p_lig;
    cudaGetSymbolAddress(&p_csum, g_csum);
    cudaGetSymbolAddress(&p_deg, g_deg);
    cudaGetSymbolAddress(&p_msum, g_msum);
    cudaGetSymbolAddress(&p_gsum, g_gsum);
    cudaGetSymbolAddress(&p_lig, g_ligcnt);

    cudaMemsetAsync(p_csum, 0, Bb * 4 * sizeof(float));
    cudaMemsetAsync(p_deg, 0, Nn * sizeof(int));
    cudaMemsetAsync(p_gsum, 0, Bb * Hh * sizeof(float));
    cudaMemsetAsync(p_lig, 0, Bb * sizeof(float));

    k_prep_w1<<<(3 * 8192) / 256, 256>>>(mw1);
    k_prep_w2<<<(3 * 4096) / 256, 256>>>(mw2);
    k_prep_u<<<(3 * 8192) / 256, 256>>>(uw);
    k_prep_lin<<<4096 / 256, 256>>>(lin_w);

    k_center_sum<<<Nn / 256, 256>>>(pos, batch);
    k_center_fin<<<1, 64>>>();
    k_input_xab<<<Nn / 128, 512, G_SMEM>>>(pos, z, batch, emb, lin_w, lin_b, mb1);
    k_deg<<<Ee / 256, 256>>>(eidx);
    k_scan1<<<256, 256>>>();
    k_scan2<<<1, 256>>>();
    k_scan3<<<Nn / 256, 256>>>();
    k_scatter<<<Ee / 256, 256>>>(eidx);

    for (int l = 0; l < 3; l++) {
        const float* W1 = mw1 + l * 257 * 128;
        cudaMemsetAsync(p_msum, 0, (size_t)Nn * Hh * sizeof(float));
        k_edge_mma<<<Ee / 128, 512, E_SMEM>>>(W1 + 256 * 128, mb2 + l * 128, l);
        k_update_xab<<<Nn / 128, 512, G_SMEM>>>(ub + l * 128, l,
                                                l < 2 ? (mb1 + (l + 1) * 128) : mb1,
                                                l < 2 ? 1 : 0);
    }

    k_pool<<<Nn * 32 / 256, 256>>>(batch, ntype);
    k_readout<<<Bb, 128>>>(rw1, rb1, rw2, rb2, out);
}